// round 10
// baseline (speedup 1.0000x reference)
#include <cuda_runtime.h>
#include <cstdint>
#include <cstddef>

// Problem: V=35, E=256, H=512, K=128, VS=128, N=64, T=2000, L=300, START=33
#define NBLK 128
#define NTHR 512

#define N_B   64
#define T_T   2000
#define TS    2048        // padded t stride for transposed KV
#define T4S   512         // TS/4
#define L_L   300
#define E_E   256
#define H_H   512
#define KD    128
#define V_V   35
#define K2    640
#define START_TOK 33
#define MAXCH 1024        // 64 * ceil(2000/128)

// ---------------- device scratch (static: no allocation) ----------------
__device__ __align__(16) float g_keyT[(size_t)N_B * KD * TS];    // [n][d][t] padded
__device__ __align__(16) float g_valT[(size_t)N_B * KD * TS];
__device__ __align__(16) float g_W1c[128 * H_H * 4];             // ctx part [(k*512+j)*4+g]
__device__ __align__(16) float g_W1h[512 * H_H * 4];             // h1 part
__device__ __align__(16) float g_W2q[K2 * KD * 4];
__device__ __align__(16) float g_embW1[V_V * H_H * 4];
__device__ __align__(16) float g_b2[KD * 4];
__device__ __align__(16) float g_pre1a[H_H * 4 * N_B];           // W_h1[0:256]  @ h1
__device__ __align__(16) float g_pre1b[H_H * 4 * N_B];           // W_h1[256:512]@ h1
__device__ __align__(16) float g_x1[2][128 * N_B];               // ctx [buf][k][n]
__device__ __align__(16) float g_h1[H_H * N_B];
__device__ __align__(16) float g_x2[2][K2 * N_B];                // k<512 h1, k>=512 h2
__device__ __align__(16) float g_c1[H_H * N_B];
__device__ __align__(16) float g_c2[KD * N_B];

// chunk schedule + flash partials
__device__ int   g_sched[MAXCH];      // (n<<16) | chunk_idx
__device__ int   g_coff[N_B + 1];
__device__ int   g_nchunks;
__device__ float g_cm[MAXCH];
__device__ float g_cs[MAXCH];
__device__ __align__(16) float g_cctx[MAXCH * 128];

__device__ unsigned g_arrive[NBLK * 32];
__device__ unsigned g_release;

__device__ __forceinline__ float sigf(float x) { return 1.0f / (1.0f + __expf(-x)); }

__device__ __forceinline__ unsigned long long packf2(float a, float b) {
    float2 f = make_float2(a, b);
    return *reinterpret_cast<unsigned long long*>(&f);
}
__device__ __forceinline__ unsigned long long f2fma(unsigned long long a,
                                                    unsigned long long b,
                                                    unsigned long long c) {
    unsigned long long d;
    asm("fma.rn.f32x2 %0, %1, %2, %3;" : "=l"(d) : "l"(a), "l"(b), "l"(c));
    return d;
}

#define HBAR(id) asm volatile("bar.sync %0, %1;" :: "r"(id), "r"(256) : "memory")

// ---------------- replay-safe fence-free grid barrier ----------------
struct Bar { unsigned gen, s0, r0, sb0, sb1, sb2, sb3; };

__device__ __forceinline__ unsigned ld_rlx(const unsigned* p) {
    unsigned v; asm volatile("ld.relaxed.gpu.u32 %0, [%1];" : "=r"(v) : "l"(p)); return v;
}
__device__ __forceinline__ unsigned ld_acq(const unsigned* p) {
    unsigned v; asm volatile("ld.acquire.gpu.u32 %0, [%1];" : "=r"(v) : "l"(p) : "memory"); return v;
}
__device__ __forceinline__ void st_rel(unsigned* p, unsigned v) {
    asm volatile("st.release.gpu.u32 [%0], %1;" :: "l"(p), "r"(v) : "memory");
}

__device__ __forceinline__ void gridbar(Bar& bs) {
    bs.gen++;
    __syncthreads();
    if (threadIdx.x == 0) st_rel(&g_arrive[blockIdx.x * 32], bs.s0 + bs.gen);
    if (blockIdx.x == 0) {
        if (threadIdx.x < 32) {
            unsigned base[4] = {bs.sb0, bs.sb1, bs.sb2, bs.sb3};
#pragma unroll
            for (int i = 0; i < 4; i++) {
                const unsigned tgt = base[i] + bs.gen;
                while (ld_acq(&g_arrive[(threadIdx.x + 32 * i) * 32]) != tgt) {}
            }
            __syncwarp();
            if (threadIdx.x == 0) st_rel(&g_release, bs.r0 + bs.gen);
        }
    } else {
        if (threadIdx.x == 0) {
            const unsigned tgt = bs.r0 + bs.gen;
            while (ld_acq(&g_release) != tgt) {}
        }
    }
    __syncthreads();
}

__global__ __launch_bounds__(NTHR, 1) void mega(
    const float* __restrict__ key, const float* __restrict__ values,
    const int* __restrict__ lens, const int* __restrict__ text,
    const float* __restrict__ emb,
    const float* __restrict__ Wih1, const float* __restrict__ Whh1,
    const float* __restrict__ bih1, const float* __restrict__ bhh1,
    const float* __restrict__ Wih2, const float* __restrict__ Whh2,
    const float* __restrict__ bih2, const float* __restrict__ bhh2,
    const float* __restrict__ bout, float* __restrict__ out)
{
    __shared__ __align__(16) float cb[8192];       // 32 KB multi-purpose
    __shared__ __align__(16) float gsum[8 * 64];
    __shared__ __align__(16) float h2s[128];
    __shared__ __align__(16) float ctxs[128];
    __shared__ float red[32];
    __shared__ float wgt[16];
    __shared__ float dinv;

    const int tid = threadIdx.x;
    const int b = blockIdx.x;
    const int wid = tid >> 5, lane = tid & 31;

    Bar bs; bs.gen = 0; bs.s0 = 0; bs.r0 = 0; bs.sb0 = bs.sb1 = bs.sb2 = bs.sb3 = 0;
    if (tid == 0) { bs.s0 = ld_rlx(&g_arrive[b * 32]); bs.r0 = ld_rlx(&g_release); }
    if (b == 0 && tid < 32) {
        bs.sb0 = ld_rlx(&g_arrive[(tid +  0) * 32]);
        bs.sb1 = ld_rlx(&g_arrive[(tid + 32) * 32]);
        bs.sb2 = ld_rlx(&g_arrive[(tid + 64) * 32]);
        bs.sb3 = ld_rlx(&g_arrive[(tid + 96) * 32]);
    }

    // ======================= PREP =======================
    for (int i = b * NTHR + tid; i < 2 * 128 * N_B; i += NBLK * NTHR) ((float*)g_x1)[i] = 0.0f;
    for (int i = b * NTHR + tid; i < H_H * N_B; i += NBLK * NTHR) g_h1[i] = 0.0f;
    for (int i = b * NTHR + tid; i < 2 * K2 * N_B; i += NBLK * NTHR) ((float*)g_x2)[i] = 0.0f;
    for (int i = b * NTHR + tid; i < H_H * N_B; i += NBLK * NTHR) g_c1[i] = 0.0f;
    for (int i = b * NTHR + tid; i < KD * N_B; i += NBLK * NTHR) g_c2[i] = 0.0f;
    for (int i = b * NTHR + tid; i < H_H * 4 * N_B; i += NBLK * NTHR) {
        g_pre1a[i] = 0.0f; g_pre1b[i] = 0.0f;
    }

    if (b == 0 && tid == 0) {       // chunk schedule (deterministic each launch)
        int idx = 0;
        for (int n = 0; n < N_B; n++) {
            g_coff[n] = idx;
            const int c = (lens[n] + 127) >> 7;
            for (int i = 0; i < c; i++) g_sched[idx++] = (n << 16) | i;
        }
        g_coff[N_B] = idx;
        g_nchunks = idx;
    }

    for (int idx = b * NTHR + tid; idx < 128 * H_H; idx += NBLK * NTHR) {
        int k = idx / H_H, j = idx % H_H;
        float4 w; float* wp = reinterpret_cast<float*>(&w);
#pragma unroll
        for (int g = 0; g < 4; g++) wp[g] = Wih1[(size_t)(g * H_H + j) * 384 + 256 + k];
        *reinterpret_cast<float4*>(&g_W1c[(size_t)idx * 4]) = w;
    }
    for (int idx = b * NTHR + tid; idx < 512 * H_H; idx += NBLK * NTHR) {
        int k = idx / H_H, j = idx % H_H;
        float4 w; float* wp = reinterpret_cast<float*>(&w);
#pragma unroll
        for (int g = 0; g < 4; g++) wp[g] = Whh1[(size_t)(g * H_H + j) * 512 + k];
        *reinterpret_cast<float4*>(&g_W1h[(size_t)idx * 4]) = w;
    }
    for (int idx = b * NTHR + tid; idx < K2 * KD; idx += NBLK * NTHR) {
        int k = idx / KD, j = idx % KD;
        float4 w; float* wp = reinterpret_cast<float*>(&w);
#pragma unroll
        for (int g = 0; g < 4; g++) {
            int row = g * KD + j;
            wp[g] = (k < 512) ? Wih2[(size_t)row * 512 + k]
                              : Whh2[(size_t)row * 128 + (k - 512)];
        }
        *reinterpret_cast<float4*>(&g_W2q[(size_t)idx * 4]) = w;
    }
    for (int j = b * NTHR + tid; j < KD; j += NBLK * NTHR) {
        float4 w;
        w.x = bih2[j] + bhh2[j];
        w.y = bih2[j + 128] + bhh2[j + 128];
        w.z = bih2[j + 256] + bhh2[j + 256];
        w.w = bih2[j + 384] + bhh2[j + 384];
        *reinterpret_cast<float4*>(&g_b2[j * 4]) = w;
    }
    for (int it = b * 16 + wid; it < V_V * H_H; it += NBLK * 16) {
        int tok = it / H_H, j = it % H_H;
        const float4* e4 = reinterpret_cast<const float4*>(emb + (size_t)tok * E_E);
        float4 ea = e4[lane], eb = e4[lane + 32];
        float a[4];
#pragma unroll
        for (int g = 0; g < 4; g++) {
            const float4* w4 = reinterpret_cast<const float4*>(Wih1 + (size_t)(g * H_H + j) * 384);
            float4 wa = w4[lane], wb = w4[lane + 32];
            a[g] = ea.x * wa.x + ea.y * wa.y + ea.z * wa.z + ea.w * wa.w
                 + eb.x * wb.x + eb.y * wb.y + eb.z * wb.z + eb.w * wb.w;
        }
#pragma unroll
        for (int s = 16; s > 0; s >>= 1) {
#pragma unroll
            for (int g = 0; g < 4; g++) a[g] += __shfl_xor_sync(0xffffffffu, a[g], s);
        }
        if (lane == 0) {
            float4 r;
            r.x = a[0] + bih1[j] + bhh1[j];
            r.y = a[1] + bih1[j + 512] + bhh1[j + 512];
            r.z = a[2] + bih1[j + 1024] + bhh1[j + 1024];
            r.w = a[3] + bih1[j + 1536] + bhh1[j + 1536];
            *reinterpret_cast<float4*>(&g_embW1[(size_t)it * 4]) = r;
        }
    }
    // transpose key/values -> [n][d][t(2048 padded)]: 64 t-tiles x 4 d-tiles per n
    {
        const int tx = tid & 31, ty = tid >> 5;
        for (int tileid = b; tileid < 2 * N_B * 64 * 4; tileid += NBLK) {
            int rem = tileid;
            const float* src = key;
            float* dst = g_keyT;
            if (rem >= N_B * 64 * 4) { rem -= N_B * 64 * 4; src = values; dst = g_valT; }
            int n = rem / (64 * 4);
            int r2 = rem % (64 * 4);
            int t0 = (r2 / 4) * 32, d0 = (r2 % 4) * 32;
            __syncthreads();
#pragma unroll
            for (int r = 0; r < 32; r += 16) {
                int t = t0 + r + ty;
                cb[(r + ty) * 33 + tx] =
                    (t < T_T) ? src[((size_t)n * T_T + t) * KD + d0 + tx] : 0.0f;
            }
            __syncthreads();
#pragma unroll
            for (int r = 0; r < 32; r += 16) {
                dst[((size_t)n * KD + d0 + r + ty) * TS + t0 + tx] = cb[tx * 33 + (r + ty)];
            }
        }
        __syncthreads();
    }

    gridbar(bs);
    const int nch = g_nchunks;   // stable after prep

    // ======================= MAIN LOOP =======================
    for (int step = 0; step < L_L; step++) {
        const int cur = step & 1, nxt = cur ^ 1;

        // ---- Phase A: gates1 = embW1 + W1c@ctx (K=128) + pre1a + pre1b; cell1 ----
        {
            const int ks = tid >> 6;        // 0..7
            const int jl = (tid >> 4) & 3;
            const int nq = tid & 15;
            const int j = b * 4 + jl;
            const float4* __restrict__ x4 = reinterpret_cast<const float4*>(g_x1[cur]);
            unsigned long long acc[8];
#pragma unroll
            for (int i = 0; i < 8; i++) acc[i] = 0ull;
#pragma unroll
            for (int kc = 0; kc < 16; kc += 8) {
                float4 xv[8];
#pragma unroll
                for (int i = 0; i < 8; i++)
                    xv[i] = __ldcg(&x4[(ks * 16 + kc + i) * 16 + nq]);
#pragma unroll
                for (int i = 0; i < 8; i++) {
                    const int k = ks * 16 + kc + i;
                    const float4 w4 = *reinterpret_cast<const float4*>(&g_W1c[((size_t)k * 512 + j) * 4]);
                    const unsigned long long xlo = packf2(xv[i].x, xv[i].y);
                    const unsigned long long xhi = packf2(xv[i].z, xv[i].w);
                    acc[0] = f2fma(packf2(w4.x, w4.x), xlo, acc[0]);
                    acc[1] = f2fma(packf2(w4.x, w4.x), xhi, acc[1]);
                    acc[2] = f2fma(packf2(w4.y, w4.y), xlo, acc[2]);
                    acc[3] = f2fma(packf2(w4.y, w4.y), xhi, acc[3]);
                    acc[4] = f2fma(packf2(w4.z, w4.z), xlo, acc[4]);
                    acc[5] = f2fma(packf2(w4.z, w4.z), xhi, acc[5]);
                    acc[6] = f2fma(packf2(w4.w, w4.w), xlo, acc[6]);
                    acc[7] = f2fma(packf2(w4.w, w4.w), xhi, acc[7]);
                }
            }
#pragma unroll
            for (int g = 0; g < 4; g++) {
                float2 lo = *reinterpret_cast<float2*>(&acc[g * 2]);
                float2 hi = *reinterpret_cast<float2*>(&acc[g * 2 + 1]);
                *reinterpret_cast<float4*>(&cb[((ks * 4 + jl) * 4 + g) * 64 + nq * 4]) =
                    make_float4(lo.x, lo.y, hi.x, hi.y);
            }
            __syncthreads();
            if (tid < 256) {
                const int jl2 = tid >> 6, n = tid & 63;
                const int j2 = b * 4 + jl2;
                const int tok = (step == 0) ? START_TOK : text[n * L_L + step - 1];
                const float4 g0 = *reinterpret_cast<const float4*>(&g_embW1[((size_t)tok * 512 + j2) * 4]);
                float gi = g0.x + __ldcg(&g_pre1a[(j2 * 4 + 0) * 64 + n]) + __ldcg(&g_pre1b[(j2 * 4 + 0) * 64 + n]);
                float gf = g0.y + __ldcg(&g_pre1a[(j2 * 4 + 1) * 64 + n]) + __ldcg(&g_pre1b[(j2 * 4 + 1) * 64 + n]);
                float gg = g0.z + __ldcg(&g_pre1a[(j2 * 4 + 2) * 64 + n]) + __ldcg(&g_pre1b[(j2 * 4 + 2) * 64 + n]);
                float go = g0.w + __ldcg(&g_pre1a[(j2 * 4 + 3) * 64 + n]) + __ldcg(&g_pre1b[(j2 * 4 + 3) * 64 + n]);
#pragma unroll
                for (int s = 0; s < 8; s++) {
                    gi += cb[((s * 4 + jl2) * 4 + 0) * 64 + n];
                    gf += cb[((s * 4 + jl2) * 4 + 1) * 64 + n];
                    gg += cb[((s * 4 + jl2) * 4 + 2) * 64 + n];
                    go += cb[((s * 4 + jl2) * 4 + 3) * 64 + n];
                }
                float c = g_c1[j2 * 64 + n];
                c = sigf(gf) * c + sigf(gi) * tanhf(gg);
                float h = sigf(go) * tanhf(c);
                g_c1[j2 * 64 + n] = c;
                __stcg(&g_h1[j2 * 64 + n], h);
                __stcg(&g_x2[cur][j2 * 64 + n], h);
            }
        }
        gridbar(bs);

        // ---- Phase B: blocks 0-63 gates2+cell2 (2 j); blocks 64-127 pre1a (k 0..255) ----
        if (b < 64) {
            const int ks = tid >> 5;        // 0..15 (40 k each)
            const int jl = (tid >> 4) & 1;
            const int nq = tid & 15;
            const int j = b * 2 + jl;
            const float4* __restrict__ x4 = reinterpret_cast<const float4*>(g_x2[cur]);
            unsigned long long acc[8];
#pragma unroll
            for (int i = 0; i < 8; i++) acc[i] = 0ull;
            for (int kc = 0; kc < 40; kc += 8) {
                float4 xv[8];
#pragma unroll
                for (int i = 0; i < 8; i++)
                    xv[i] = __ldcg(&x4[(ks * 40 + kc + i) * 16 + nq]);
#pragma unroll
                for (int i = 0; i < 8; i++) {
                    const int k = ks * 40 + kc + i;
                    const float4 w4 = *reinterpret_cast<const float4*>(&g_W2q[((size_t)k * 128 + j) * 4]);
                    const unsigned long long xlo = packf2(xv[i].x, xv[i].y);
                    const unsigned long long xhi = packf2(xv[i].z, xv[i].w);
                    acc[0] = f2fma(packf2(w4.x, w4.x), xlo, acc[0]);
                    acc[1] = f2fma(packf2(w4.x, w4.x), xhi, acc[1]);
                    acc[2] = f2fma(packf2(w4.y, w4.y), xlo, acc[2]);
                    acc[3] = f2fma(packf2(w4.y, w4.y), xhi, acc[3]);
                    acc[4] = f2fma(packf2(w4.z, w4.z), xlo, acc[4]);
                    acc[5] = f2fma(packf2(w4.z, w4.z), xhi, acc[5]);
                    acc[6] = f2fma(packf2(w4.w, w4.w), xlo, acc[6]);
                    acc[7] = f2fma(packf2(w4.w, w4.w), xhi, acc[7]);
                }
            }
#pragma unroll
            for (int g = 0; g < 4; g++) {
                float2 lo = *reinterpret_cast<float2*>(&acc[g * 2]);
                float2 hi = *reinterpret_cast<float2*>(&acc[g * 2 + 1]);
                *reinterpret_cast<float4*>(&cb[((ks * 2 + jl) * 4 + g) * 64 + nq * 4]) =
                    make_float4(lo.x, lo.y, hi.x, hi.y);
            }
            __syncthreads();
            {   // 512 threads: each owns (jl,g,n)
                const int jl2 = tid >> 8, g2 = (tid >> 6) & 3, n2 = tid & 63;
                float s = 0.0f;
#pragma unroll
                for (int ks2 = 0; ks2 < 16; ks2++) s += cb[((ks2 * 2 + jl2) * 4 + g2) * 64 + n2];
                gsum[(jl2 * 4 + g2) * 64 + n2] = s;
            }
            __syncthreads();
            if (tid < 128) {
                const int jj = tid >> 6, n = tid & 63;
                const int j2 = b * 2 + jj;
                const float4 bb = *reinterpret_cast<const float4*>(&g_b2[j2 * 4]);
                float gi = bb.x + gsum[(jj * 4 + 0) * 64 + n];
                float gf = bb.y + gsum[(jj * 4 + 1) * 64 + n];
                float gg = bb.z + gsum[(jj * 4 + 2) * 64 + n];
                float go = bb.w + gsum[(jj * 4 + 3) * 64 + n];
                float c = g_c2[j2 * 64 + n];
                c = sigf(gf) * c + sigf(gi) * tanhf(gg);
                float h = sigf(go) * tanhf(c);
                g_c2[j2 * 64 + n] = c;
                __stcg(&g_x2[nxt][(512 + j2) * 64 + n], h);
            }
        } else {
            // pre1a: k in [0,256)
            const int j0 = (b - 64) * 8;
            const int ks = tid >> 7, jl = (tid >> 4) & 7, nq = tid & 15;
            const int j = j0 + jl;
            const float4* __restrict__ h14 = reinterpret_cast<const float4*>(g_h1);
            unsigned long long acc[8];
#pragma unroll
            for (int i = 0; i < 8; i++) acc[i] = 0ull;
            for (int kc = 0; kc < 64; kc += 8) {
                float4 xv[8];
#pragma unroll
                for (int i = 0; i < 8; i++)
                    xv[i] = __ldcg(&h14[(ks * 64 + kc + i) * 16 + nq]);
#pragma unroll
                for (int i = 0; i < 8; i++) {
                    const int k = ks * 64 + kc + i;
                    const float4 w4 = *reinterpret_cast<const float4*>(&g_W1h[((size_t)k * 512 + j) * 4]);
                    const unsigned long long xlo = packf2(xv[i].x, xv[i].y);
                    const unsigned long long xhi = packf2(xv[i].z, xv[i].w);
                    acc[0] = f2fma(packf2(w4.x, w4.x), xlo, acc[0]);
                    acc[1] = f2fma(packf2(w4.x, w4.x), xhi, acc[1]);
                    acc[2] = f2fma(packf2(w4.y, w4.y), xlo, acc[2]);
                    acc[3] = f2fma(packf2(w4.y, w4.y), xhi, acc[3]);
                    acc[4] = f2fma(packf2(w4.z, w4.z), xlo, acc[4]);
                    acc[5] = f2fma(packf2(w4.z, w4.z), xhi, acc[5]);
                    acc[6] = f2fma(packf2(w4.w, w4.w), xlo, acc[6]);
                    acc[7] = f2fma(packf2(w4.w, w4.w), xhi, acc[7]);
                }
            }
#pragma unroll
            for (int g = 0; g < 4; g++) {
                float2 lo = *reinterpret_cast<float2*>(&acc[g * 2]);
                float2 hi = *reinterpret_cast<float2*>(&acc[g * 2 + 1]);
                *reinterpret_cast<float4*>(&cb[((ks * 8 + jl) * 4 + g) * 64 + nq * 4]) =
                    make_float4(lo.x, lo.y, hi.x, hi.y);
            }
            __syncthreads();
            {
                const int jl2 = tid >> 6, n = tid & 63;
                const int j2 = j0 + jl2;
#pragma unroll
                for (int g = 0; g < 4; g++) {
                    float s = cb[((0 * 8 + jl2) * 4 + g) * 64 + n]
                            + cb[((1 * 8 + jl2) * 4 + g) * 64 + n]
                            + cb[((2 * 8 + jl2) * 4 + g) * 64 + n]
                            + cb[((3 * 8 + jl2) * 4 + g) * 64 + n];
                    __stcg(&g_pre1a[(j2 * 4 + g) * 64 + n], s);
                }
            }
        }
        gridbar(bs);

        // ---- Phase C: chunked attention, all 128 blocks, 2 halves of 256 threads ----
        {
            const int half = tid >> 8;
            const int htid = tid & 255;
            const int barid = half + 1;
            float* part = cb + half * 1024;          // [8 dg][32 tq] float4
            float* esw  = cb + 2048 + half * 128;    // 32 float4 weights
            float* ctmp = cb + 2304 + half * 256;
            float* h2h  = cb + 2816 + half * 128;

            for (int ci = b * 2 + half; ci < nch; ci += 2 * NBLK) {
                const int sc = g_sched[ci];
                const int n = sc >> 16;
                const int q0 = (sc & 0xffff) * 32;   // quad offset in padded t
                const int len = lens[n];

                if (htid < 128) h2h[htid] = __ldcg(&g_x2[nxt][(512 + htid) * 64 + n]);
                HBAR(barid);

                // energy partials: tq 0..31, dg 0..7 (16 d each)
                {
                    const int tq = htid & 31, dg = htid >> 5;
                    const float4* kT = reinterpret_cast<const float4*>(g_keyT + (size_t)n * KD * TS);
                    float4 a = make_float4(0.f, 0.f, 0.f, 0.f);
#pragma unroll
                    for (int w2 = 0; w2 < 2; w2++) {
                        float4 kv[8];
#pragma unroll
                        for (int i = 0; i < 8; i++)
                            kv[i] = __ldcg(&kT[(size_t)(dg * 16 + w2 * 8 + i) * T4S + q0 + tq]);
#pragma unroll
                        for (int i = 0; i < 8; i++) {
                            const float hv = h2h[dg * 16 + w2 * 8 + i];
                            a.x = fmaf(hv, kv[i].x, a.x);
                            a.y = fmaf(hv, kv[i].y, a.y);
                            a.z = fmaf(hv, kv[i].z, a.z);
                            a.w = fmaf(hv, kv[i].w, a.w);
                        }
                    }
                    reinterpret_cast<float4*>(part)[dg * 32 + tq] = a;
                }
                HBAR(barid);

                if (htid < 32) {
                    float4 e = make_float4(0.f, 0.f, 0.f, 0.f);
#pragma unroll
                    for (int dgi = 0; dgi < 8; dgi++) {
                        float4 p = reinterpret_cast<float4*>(part)[dgi * 32 + htid];
                        e.x += p.x; e.y += p.y; e.z += p.z; e.w += p.w;
                    }
                    const int tb = q0 * 4 + htid * 4;
                    const bool v0 = tb < len, v1 = tb + 1 < len, v2 = tb + 2 < len, v3 = tb + 3 < len;
                    float m = v0 ? e.x : -3e38f;
                    if (v1) m = fmaxf(m, e.y);
                    if (v2) m = fmaxf(m, e.z);
                    if (v3) m = fmaxf(m, e.w);
#pragma unroll
                    for (int s = 16; s > 0; s >>= 1) m = fmaxf(m, __shfl_xor_sync(0xffffffffu, m, s));
                    float4 w;
                    w.x = v0 ? __expf(e.x - m) : 0.0f;
                    w.y = v1 ? __expf(e.y - m) : 0.0f;
                    w.z = v2 ? __expf(e.z - m) : 0.0f;
                    w.w = v3 ? __expf(e.w - m) : 0.0f;
                    reinterpret_cast<float4*>(esw)[htid] = w;
                    float s = w.x + w.y + w.z + w.w;
#pragma unroll
                    for (int t = 16; t > 0; t >>= 1) s += __shfl_xor_sync(0xffffffffu, s, t);
                    if (htid == 0) { __stcg(&g_cm[ci], m); __stcg(&g_cs[ci], s); }
                }
                HBAR(barid);

                // ctx partials: d = htid>>1, t-half = htid&1 (16 quads each)
                {
                    const int d = htid >> 1, tp = htid & 1;
                    const float4* vT = reinterpret_cast<const float4*>(g_valT + (size_t)n * KD * TS);
                    const float4* wq = reinterpret_cast<const float4*>(esw) + tp * 16;
                    float4 a = make_float4(0.f, 0.f, 0.f, 0.f);
#pragma unroll
                    for (int w2 = 0; w2 < 2; w2++) {
                        float4 vv[8];
#pragma unroll
                        for (int i = 0; i < 8; i++)
                            vv[i] = __ldcg(&vT[(size_t)d * T4S + q0 + tp * 16 + w2 * 8 + i]);
#pragma unroll
                        for (int i = 0; i < 8; i++) {
                            const float4 ww = wq[w2 * 8 + i];
                            a.x = fmaf(ww.x, vv[i].x, a.x);
                            a.y = fmaf(ww.y, vv[i].y, a.y);
                            a.z = fmaf(ww.z, vv[i].z, a.z);
                            a.w = fmaf(ww.w, vv[i].w, a.w);
                        }
                    }
                    ctmp[htid] = a.x + a.y + a.z + a.w;
                }
                HBAR(barid);
                if (htid < 128)
                    __stcg(&g_cctx[(size_t)ci * 128 + htid], ctmp[htid * 2] + ctmp[htid * 2 + 1]);
                HBAR(barid);
            }
        }
        gridbar(bs);

        // ---- Phase D: blocks 0-63 merge+logits; blocks 64-127 pre1b (k 256..511) ----
        if (b < 64) {
            const int n = b;
            const int off = g_coff[n];
            const int cn = g_coff[n + 1] - off;
            if (tid < 32) {
                float mi = (tid < cn) ? __ldcg(&g_cm[off + tid]) : -3e38f;
                float si = (tid < cn) ? __ldcg(&g_cs[off + tid]) : 0.0f;
                float M = mi;
#pragma unroll
                for (int s = 16; s > 0; s >>= 1) M = fmaxf(M, __shfl_xor_sync(0xffffffffu, M, s));
                float wi = (tid < cn) ? __expf(mi - M) : 0.0f;
                float S = si * wi;
#pragma unroll
                for (int s = 16; s > 0; s >>= 1) S += __shfl_xor_sync(0xffffffffu, S, s);
                if (tid < 16) wgt[tid] = wi;
                if (tid == 0) dinv = 1.0f / S;
            }
            if (tid < 128) h2s[tid] = __ldcg(&g_x2[nxt][(512 + tid) * 64 + n]);
            __syncthreads();
            if (tid < 128) {
                float acc = 0.0f;
                int i = 0;
                for (; i + 4 <= cn; i += 4) {
                    float p0 = __ldcg(&g_cctx[(size_t)(off + i    ) * 128 + tid]);
                    float p1 = __ldcg(&g_cctx[(size_t)(off + i + 1) * 128 + tid]);
                    float p2 = __ldcg(&g_cctx[(size_t)(off + i + 2) * 128 + tid]);
                    float p3 = __ldcg(&g_cctx[(size_t)(off + i + 3) * 128 + tid]);
                    acc += p0 * wgt[i] + p1 * wgt[i + 1] + p2 * wgt[i + 2] + p3 * wgt[i + 3];
                }
                for (; i < cn; i++) acc += __ldcg(&g_cctx[(size_t)(off + i) * 128 + tid]) * wgt[i];
                const float cx = acc * dinv;
                ctxs[tid] = cx;
                __stcg(&g_x1[nxt][tid * 64 + n], cx);
            }
            __syncthreads();
            {   // logits
                const float4 h0 = *reinterpret_cast<const float4*>(&h2s[lane * 4]);
                const float4 c0 = *reinterpret_cast<const float4*>(&ctxs[lane * 4]);
                for (int v = wid; v < V_V; v += 16) {
                    const float4* er = reinterpret_cast<const float4*>(emb + (size_t)v * E_E);
                    const float4 e0 = er[lane], e1 = er[lane + 32];
                    float d = e0.x * h0.x + e0.y * h0.y + e0.z * h0.z + e0.w * h0.w
                            + e1.x * c0.x + e1.y * c0.y + e1.z * c0.z + e1.w * c0.w;
#pragma unroll
                    for (int s = 16; s > 0; s >>= 1) d += __shfl_xor_sync(0xffffffffu, d, s);
                    if (lane == 0) out[((size_t)n * L_L + step) * V_V + v] = d + bout[v];
                }
            }
        } else {
            // pre1b: k in [256,512)
            const int j0 = (b - 64) * 8;
            const int ks = tid >> 7, jl = (tid >> 4) & 7, nq = tid & 15;
            const int j = j0 + jl;
            const float4* __restrict__ h14 = reinterpret_cast<const float4*>(g_h1);
            unsigned long long acc[8];
#pragma unroll
            for (int i = 0; i < 8; i++) acc[i] = 0ull;
            for (int kc = 0; kc < 64; kc += 8) {
                float4 xv[8];
#pragma unroll
                for (int i = 0; i < 8; i++)
                    xv[i] = __ldcg(&h14[(256 + ks * 64 + kc + i) * 16 + nq]);
#pragma unroll
                for (int i = 0; i < 8; i++) {
                    const int k = 256 + ks * 64 + kc + i;
                    const float4 w4 = *reinterpret_cast<const float4*>(&g_W1h[((size_t)k * 512 + j) * 4]);
                    const unsigned long long xlo = packf2(xv[i].x, xv[i].y);
                    const unsigned long long xhi = packf2(xv[i].z, xv[i].w);
                    acc[0] = f2fma(packf2(w4.x, w4.x), xlo, acc[0]);
                    acc[1] = f2fma(packf2(w4.x, w4.x), xhi, acc[1]);
                    acc[2] = f2fma(packf2(w4.y, w4.y), xlo, acc[2]);
                    acc[3] = f2fma(packf2(w4.y, w4.y), xhi, acc[3]);
                    acc[4] = f2fma(packf2(w4.z, w4.z), xlo, acc[4]);
                    acc[5] = f2fma(packf2(w4.z, w4.z), xhi, acc[5]);
                    acc[6] = f2fma(packf2(w4.w, w4.w), xlo, acc[6]);
                    acc[7] = f2fma(packf2(w4.w, w4.w), xhi, acc[7]);
                }
            }
#pragma unroll
            for (int g = 0; g < 4; g++) {
                float2 lo = *reinterpret_cast<float2*>(&acc[g * 2]);
                float2 hi = *reinterpret_cast<float2*>(&acc[g * 2 + 1]);
                *reinterpret_cast<float4*>(&cb[((ks * 8 + jl) * 4 + g) * 64 + nq * 4]) =
                    make_float4(lo.x, lo.y, hi.x, hi.y);
            }
            __syncthreads();
            {
                const int jl2 = tid >> 6, n = tid & 63;
                const int j2 = j0 + jl2;
#pragma unroll
                for (int g = 0; g < 4; g++) {
                    float s = cb[((0 * 8 + jl2) * 4 + g) * 64 + n]
                            + cb[((1 * 8 + jl2) * 4 + g) * 64 + n]
                            + cb[((2 * 8 + jl2) * 4 + g) * 64 + n]
                            + cb[((3 * 8 + jl2) * 4 + g) * 64 + n];
                    __stcg(&g_pre1b[(j2 * 4 + g) * 64 + n], s);
                }
            }
        }
        gridbar(bs);
    }
}

extern "C" void kernel_launch(void* const* d_in, const int* in_sizes, int n_in,
                              void* d_out, int out_size) {
    mega<<<NBLK, NTHR>>>(
        (const float*)d_in[0], (const float*)d_in[1], (const int*)d_in[2],
        (const int*)d_in[3], (const float*)d_in[4], (const float*)d_in[5],
        (const float*)d_in[6], (const float*)d_in[7], (const float*)d_in[8],
        (const float*)d_in[9], (const float*)d_in[10], (const float*)d_in[11],
        (const float*)d_in[12], (const float*)d_in[13], (float*)d_out);
}

// round 11
// speedup vs baseline: 1.0355x; 1.0355x over previous
#include <cuda_runtime.h>
#include <cstdint>
#include <cstddef>

// Problem: V=35, E=256, H=512, K=128, VS=128, N=64, T=2000, L=300, START=33
#define NBLK 128
#define NTHR 512

#define N_B   64
#define T_T   2000
#define TS    2048
#define T4S   512
#define L_L   300
#define E_E   256
#define H_H   512
#define KD    128
#define V_V   35
#define K2    640
#define START_TOK 33
#define XSTR  68          // padded n-stride for xs smem

// ---------------- device scratch ----------------
__device__ __align__(16) float g_keyT[(size_t)N_B * KD * TS];    // [n][d][t] padded, read-only after prep
__device__ __align__(16) float g_valT[(size_t)N_B * KD * TS];
__device__ __align__(16) float g_W1c[128 * H_H * 4];
__device__ __align__(16) float g_W1h[512 * H_H * 4];
__device__ __align__(16) float g_W2q[K2 * KD * 4];
__device__ __align__(16) float g_embW1[V_V * H_H * 4];
__device__ __align__(16) float g_b2[KD * 4];
__device__ __align__(16) float g_pre1a[H_H * 4 * N_B];
__device__ __align__(16) float g_pre1b[H_H * 4 * N_B];
__device__ __align__(16) float g_h1[H_H * N_B];
__device__ __align__(16) float g_x2[2][K2 * N_B];
__device__ __align__(16) float g_c1[H_H * N_B];
__device__ __align__(16) float g_c2[KD * N_B];

// flash schedule + partials (128 items, one per block)
__device__ int   g_itemN[NBLK], g_itemQA[NBLK], g_itemQB[NBLK];
__device__ int   g_coff[N_B + 1];
__device__ int   g_pn[N_B];
__device__ float g_cm[NBLK], g_cs[NBLK];
__device__ __align__(16) float g_cctx[NBLK * 128];

__device__ unsigned g_arrive[NBLK * 32];
__device__ unsigned g_release;

__device__ __forceinline__ float sigf(float x) { return 1.0f / (1.0f + __expf(-x)); }

__device__ __forceinline__ unsigned long long packf2(float a, float b) {
    float2 f = make_float2(a, b);
    return *reinterpret_cast<unsigned long long*>(&f);
}
__device__ __forceinline__ unsigned long long f2fma(unsigned long long a,
                                                    unsigned long long b,
                                                    unsigned long long c) {
    unsigned long long d;
    asm("fma.rn.f32x2 %0, %1, %2, %3;" : "=l"(d) : "l"(a), "l"(b), "l"(c));
    return d;
}

// ---------------- replay-safe grid barrier ----------------
struct Bar { unsigned gen, s0, r0, sb0, sb1, sb2, sb3; };

__device__ __forceinline__ unsigned ld_rlx(const unsigned* p) {
    unsigned v; asm volatile("ld.relaxed.gpu.u32 %0, [%1];" : "=r"(v) : "l"(p)); return v;
}
__device__ __forceinline__ unsigned ld_acq(const unsigned* p) {
    unsigned v; asm volatile("ld.acquire.gpu.u32 %0, [%1];" : "=r"(v) : "l"(p) : "memory"); return v;
}
__device__ __forceinline__ void st_rel(unsigned* p, unsigned v) {
    asm volatile("st.release.gpu.u32 [%0], %1;" :: "l"(p), "r"(v) : "memory");
}

__device__ __forceinline__ void gridbar(Bar& bs) {
    bs.gen++;
    __syncthreads();
    if (threadIdx.x == 0) st_rel(&g_arrive[blockIdx.x * 32], bs.s0 + bs.gen);
    if (blockIdx.x == 0) {
        if (threadIdx.x < 32) {
            unsigned base[4] = {bs.sb0, bs.sb1, bs.sb2, bs.sb3};
#pragma unroll
            for (int i = 0; i < 4; i++) {
                const unsigned tgt = base[i] + bs.gen;
                while (ld_acq(&g_arrive[(threadIdx.x + 32 * i) * 32]) != tgt) {}
            }
            __syncwarp();
            if (threadIdx.x == 0) st_rel(&g_release, bs.r0 + bs.gen);
        }
    } else {
        if (threadIdx.x == 0) {
            const unsigned tgt = bs.r0 + bs.gen;
            while (ld_acq(&g_release) != tgt) {}
        }
    }
    __syncthreads();
}

__global__ __launch_bounds__(NTHR, 1) void mega(
    const float* __restrict__ key, const float* __restrict__ values,
    const int* __restrict__ lens, const int* __restrict__ text,
    const float* __restrict__ emb,
    const float* __restrict__ Wih1, const float* __restrict__ Whh1,
    const float* __restrict__ bih1, const float* __restrict__ bhh1,
    const float* __restrict__ Wih2, const float* __restrict__ Whh2,
    const float* __restrict__ bih2, const float* __restrict__ bhh2,
    const float* __restrict__ bout, float* __restrict__ out)
{
    __shared__ __align__(16) float cb[128 * XSTR];   // 34 KB: xs / combine / transpose
    __shared__ __align__(16) float es[2048];         // 8 KB softmax weights
    __shared__ __align__(16) float h2s[128];
    __shared__ __align__(16) float ctxs[128];
    __shared__ __align__(16) float wflat[128];
    __shared__ float red[32];
    __shared__ float sred;

    const int tid = threadIdx.x;
    const int b = blockIdx.x;
    const int wid = tid >> 5, lane = tid & 31;

    Bar bs; bs.gen = 0; bs.s0 = 0; bs.r0 = 0; bs.sb0 = bs.sb1 = bs.sb2 = bs.sb3 = 0;
    if (tid == 0) { bs.s0 = ld_rlx(&g_arrive[b * 32]); bs.r0 = ld_rlx(&g_release); }
    if (b == 0 && tid < 32) {
        bs.sb0 = ld_rlx(&g_arrive[(tid +  0) * 32]);
        bs.sb1 = ld_rlx(&g_arrive[(tid + 32) * 32]);
        bs.sb2 = ld_rlx(&g_arrive[(tid + 64) * 32]);
        bs.sb3 = ld_rlx(&g_arrive[(tid + 96) * 32]);
    }

    // ======================= PREP =======================
    for (int i = b * NTHR + tid; i < H_H * N_B; i += NBLK * NTHR) g_h1[i] = 0.0f;
    for (int i = b * NTHR + tid; i < 2 * K2 * N_B; i += NBLK * NTHR) ((float*)g_x2)[i] = 0.0f;
    for (int i = b * NTHR + tid; i < H_H * N_B; i += NBLK * NTHR) g_c1[i] = 0.0f;
    for (int i = b * NTHR + tid; i < KD * N_B; i += NBLK * NTHR) g_c2[i] = 0.0f;
    for (int i = b * NTHR + tid; i < H_H * 4 * N_B; i += NBLK * NTHR) {
        g_pre1a[i] = 0.0f; g_pre1b[i] = 0.0f;
    }

    if (b == 0 && tid == 0) {   // greedy proportional schedule: 128 items
        int nq[N_B]; int p[N_B];
        for (int n = 0; n < N_B; n++) { nq[n] = (lens[n] + 3) >> 2; p[n] = 1; }
        for (int e = 0; e < 64; e++) {
            int best = 0;
            for (int n = 1; n < N_B; n++)
                if ((long long)nq[n] * p[best] > (long long)nq[best] * p[n]) best = n;
            p[best]++;
        }
        int idx = 0;
        for (int n = 0; n < N_B; n++) {
            g_coff[n] = idx; g_pn[n] = p[n];
            for (int i = 0; i < p[n]; i++) {
                g_itemN[idx] = n;
                g_itemQA[idx] = (int)((long long)nq[n] * i / p[n]);
                g_itemQB[idx] = (int)((long long)nq[n] * (i + 1) / p[n]);
                idx++;
            }
        }
        g_coff[N_B] = idx;
    }

    for (int idx = b * NTHR + tid; idx < 128 * H_H; idx += NBLK * NTHR) {
        int k = idx / H_H, j = idx % H_H;
        float4 w; float* wp = reinterpret_cast<float*>(&w);
#pragma unroll
        for (int g = 0; g < 4; g++) wp[g] = Wih1[(size_t)(g * H_H + j) * 384 + 256 + k];
        *reinterpret_cast<float4*>(&g_W1c[(size_t)idx * 4]) = w;
    }
    for (int idx = b * NTHR + tid; idx < 512 * H_H; idx += NBLK * NTHR) {
        int k = idx / H_H, j = idx % H_H;
        float4 w; float* wp = reinterpret_cast<float*>(&w);
#pragma unroll
        for (int g = 0; g < 4; g++) wp[g] = Whh1[(size_t)(g * H_H + j) * 512 + k];
        *reinterpret_cast<float4*>(&g_W1h[(size_t)idx * 4]) = w;
    }
    for (int idx = b * NTHR + tid; idx < K2 * KD; idx += NBLK * NTHR) {
        int k = idx / KD, j = idx % KD;
        float4 w; float* wp = reinterpret_cast<float*>(&w);
#pragma unroll
        for (int g = 0; g < 4; g++) {
            int row = g * KD + j;
            wp[g] = (k < 512) ? Wih2[(size_t)row * 512 + k]
                              : Whh2[(size_t)row * 128 + (k - 512)];
        }
        *reinterpret_cast<float4*>(&g_W2q[(size_t)idx * 4]) = w;
    }
    for (int j = b * NTHR + tid; j < KD; j += NBLK * NTHR) {
        float4 w;
        w.x = bih2[j] + bhh2[j];
        w.y = bih2[j + 128] + bhh2[j + 128];
        w.z = bih2[j + 256] + bhh2[j + 256];
        w.w = bih2[j + 384] + bhh2[j + 384];
        *reinterpret_cast<float4*>(&g_b2[j * 4]) = w;
    }
    for (int it = b * 16 + wid; it < V_V * H_H; it += NBLK * 16) {
        int tok = it / H_H, j = it % H_H;
        const float4* e4 = reinterpret_cast<const float4*>(emb + (size_t)tok * E_E);
        float4 ea = e4[lane], eb = e4[lane + 32];
        float a[4];
#pragma unroll
        for (int g = 0; g < 4; g++) {
            const float4* w4 = reinterpret_cast<const float4*>(Wih1 + (size_t)(g * H_H + j) * 384);
            float4 wa = w4[lane], wb = w4[lane + 32];
            a[g] = ea.x * wa.x + ea.y * wa.y + ea.z * wa.z + ea.w * wa.w
                 + eb.x * wb.x + eb.y * wb.y + eb.z * wb.z + eb.w * wb.w;
        }
#pragma unroll
        for (int s = 16; s > 0; s >>= 1) {
#pragma unroll
            for (int g = 0; g < 4; g++) a[g] += __shfl_xor_sync(0xffffffffu, a[g], s);
        }
        if (lane == 0) {
            float4 r;
            r.x = a[0] + bih1[j] + bhh1[j];
            r.y = a[1] + bih1[j + 512] + bhh1[j + 512];
            r.z = a[2] + bih1[j + 1024] + bhh1[j + 1024];
            r.w = a[3] + bih1[j + 1536] + bhh1[j + 1536];
            *reinterpret_cast<float4*>(&g_embW1[(size_t)it * 4]) = r;
        }
    }
    {   // transpose key/values -> [n][d][t padded 2048]
        const int tx = tid & 31, ty = tid >> 5;
        for (int tileid = b; tileid < 2 * N_B * 64 * 4; tileid += NBLK) {
            int rem = tileid;
            const float* src = key;
            float* dst = g_keyT;
            if (rem >= N_B * 64 * 4) { rem -= N_B * 64 * 4; src = values; dst = g_valT; }
            int n = rem / (64 * 4);
            int r2 = rem % (64 * 4);
            int t0 = (r2 / 4) * 32, d0 = (r2 % 4) * 32;
            __syncthreads();
#pragma unroll
            for (int r = 0; r < 32; r += 16) {
                int t = t0 + r + ty;
                cb[(r + ty) * 33 + tx] =
                    (t < T_T) ? src[((size_t)n * T_T + t) * KD + d0 + tx] : 0.0f;
            }
            __syncthreads();
#pragma unroll
            for (int r = 0; r < 32; r += 16) {
                dst[((size_t)n * KD + d0 + r + ty) * TS + t0 + tx] = cb[tx * 33 + (r + ty)];
            }
        }
        __syncthreads();
    }

    gridbar(bs);

    // per-block flash item (constant all steps)
    const int in_  = g_itemN[b];
    const int iqa  = g_itemQA[b];
    const int iqb  = g_itemQB[b];
    const int ilen = lens[in_];

    // ======================= MAIN LOOP =======================
    for (int step = 0; step < L_L; step++) {
        const int cur = step & 1, nxt = cur ^ 1;

        // ---- Phase A: merge weights -> xs (=ctx) -> gates1 GEMM -> cell1 -> logits(step-1) ----
        {
            if (step > 0) {
                if (tid < 64) {
                    const int off = g_coff[tid], pn = g_pn[tid];
                    float M = -3e38f;
                    for (int i = 0; i < pn; i++) M = fmaxf(M, __ldcg(&g_cm[off + i]));
                    float S = 0.0f;
                    for (int i = 0; i < pn; i++) {
                        float w = __expf(__ldcg(&g_cm[off + i]) - M);
                        wflat[off + i] = w;
                        S += w * __ldcg(&g_cs[off + i]);
                    }
                    const float dinv = 1.0f / S;
                    for (int i = 0; i < pn; i++) wflat[off + i] *= dinv;
                }
                if (b < 64 && tid >= 128 && tid < 256)
                    h2s[tid - 128] = __ldcg(&g_x2[cur][(512 + tid - 128) * 64 + b]);
                __syncthreads();
                // xs[k][n] = merged ctx
                const int k = tid & 127, ng = tid >> 7;
                for (int nn = ng * 16; nn < ng * 16 + 16; nn++) {
                    const int off = g_coff[nn], pn = g_pn[nn];
                    float s = 0.0f;
                    for (int i = 0; i < pn; i++)
                        s += wflat[off + i] * __ldcg(&g_cctx[(size_t)(off + i) * 128 + k]);
                    cb[k * XSTR + nn] = s;
                }
            } else {
                for (int i = tid; i < 128 * XSTR; i += NTHR) cb[i] = 0.0f;
            }
            __syncthreads();

            // gates1 ctx-GEMM (K=128) from smem xs
            const int ks = tid >> 6, jl = (tid >> 4) & 3, nqt = tid & 15;
            const int j = b * 4 + jl;
            unsigned long long acc[8];
#pragma unroll
            for (int i = 0; i < 8; i++) acc[i] = 0ull;
#pragma unroll
            for (int i = 0; i < 16; i++) {
                const int k = ks * 16 + i;
                const float4 w4 = *reinterpret_cast<const float4*>(&g_W1c[((size_t)k * 512 + j) * 4]);
                const float4 xv = *reinterpret_cast<const float4*>(&cb[k * XSTR + nqt * 4]);
                const unsigned long long xlo = packf2(xv.x, xv.y);
                const unsigned long long xhi = packf2(xv.z, xv.w);
                acc[0] = f2fma(packf2(w4.x, w4.x), xlo, acc[0]);
                acc[1] = f2fma(packf2(w4.x, w4.x), xhi, acc[1]);
                acc[2] = f2fma(packf2(w4.y, w4.y), xlo, acc[2]);
                acc[3] = f2fma(packf2(w4.y, w4.y), xhi, acc[3]);
                acc[4] = f2fma(packf2(w4.z, w4.z), xlo, acc[4]);
                acc[5] = f2fma(packf2(w4.z, w4.z), xhi, acc[5]);
                acc[6] = f2fma(packf2(w4.w, w4.w), xlo, acc[6]);
                acc[7] = f2fma(packf2(w4.w, w4.w), xhi, acc[7]);
            }
            __syncthreads();
            if (b < 64 && tid < 128 && step > 0) ctxs[tid] = cb[tid * XSTR + b];
            __syncthreads();
#pragma unroll
            for (int g = 0; g < 4; g++) {
                float2 lo = *reinterpret_cast<float2*>(&acc[g * 2]);
                float2 hi = *reinterpret_cast<float2*>(&acc[g * 2 + 1]);
                *reinterpret_cast<float4*>(&cb[((ks * 4 + jl) * 4 + g) * 64 + nqt * 4]) =
                    make_float4(lo.x, lo.y, hi.x, hi.y);
            }
            __syncthreads();
            if (tid < 256) {
                const int jl2 = tid >> 6, n = tid & 63;
                const int j2 = b * 4 + jl2;
                const int tok = (step == 0) ? START_TOK : text[n * L_L + step - 1];
                const float4 g0 = *reinterpret_cast<const float4*>(&g_embW1[((size_t)tok * 512 + j2) * 4]);
                float gi = g0.x + __ldcg(&g_pre1a[(j2 * 4 + 0) * 64 + n]) + __ldcg(&g_pre1b[(j2 * 4 + 0) * 64 + n]);
                float gf = g0.y + __ldcg(&g_pre1a[(j2 * 4 + 1) * 64 + n]) + __ldcg(&g_pre1b[(j2 * 4 + 1) * 64 + n]);
                float gg = g0.z + __ldcg(&g_pre1a[(j2 * 4 + 2) * 64 + n]) + __ldcg(&g_pre1b[(j2 * 4 + 2) * 64 + n]);
                float go = g0.w + __ldcg(&g_pre1a[(j2 * 4 + 3) * 64 + n]) + __ldcg(&g_pre1b[(j2 * 4 + 3) * 64 + n]);
#pragma unroll
                for (int s = 0; s < 8; s++) {
                    gi += cb[((s * 4 + jl2) * 4 + 0) * 64 + n];
                    gf += cb[((s * 4 + jl2) * 4 + 1) * 64 + n];
                    gg += cb[((s * 4 + jl2) * 4 + 2) * 64 + n];
                    go += cb[((s * 4 + jl2) * 4 + 3) * 64 + n];
                }
                float c = g_c1[j2 * 64 + n];
                c = sigf(gf) * c + sigf(gi) * tanhf(gg);
                float h = sigf(go) * tanhf(c);
                g_c1[j2 * 64 + n] = c;
                __stcg(&g_h1[j2 * 64 + n], h);
                __stcg(&g_x2[cur][j2 * 64 + n], h);
            }
            // logits for step-1
            if (b < 64 && step > 0) {
                const float4 h0 = *reinterpret_cast<const float4*>(&h2s[lane * 4]);
                const float4 c0 = *reinterpret_cast<const float4*>(&ctxs[lane * 4]);
                for (int v = wid; v < V_V; v += 16) {
                    const float4* er = reinterpret_cast<const float4*>(emb + (size_t)v * E_E);
                    const float4 e0 = er[lane], e1 = er[lane + 32];
                    float d = e0.x * h0.x + e0.y * h0.y + e0.z * h0.z + e0.w * h0.w
                            + e1.x * c0.x + e1.y * c0.y + e1.z * c0.z + e1.w * c0.w;
#pragma unroll
                    for (int s = 16; s > 0; s >>= 1) d += __shfl_xor_sync(0xffffffffu, d, s);
                    if (lane == 0) out[((size_t)b * L_L + step - 1) * V_V + v] = d + bout[v];
                }
            }
        }
        gridbar(bs);

        // ---- Phase B: gates2+cell2 (blocks 0-31) | pre1 units (blocks 32-127) ----
        if (b < 32) {
            const int ks = tid >> 6, jl = (tid >> 4) & 3, nqt = tid & 15;
            const int j = b * 4 + jl;
            const float4* __restrict__ x4 = reinterpret_cast<const float4*>(g_x2[cur]);
            unsigned long long acc[8];
#pragma unroll
            for (int i = 0; i < 8; i++) acc[i] = 0ull;
            for (int kc = 0; kc < 80; kc += 8) {
                float4 xv[8];
#pragma unroll
                for (int i = 0; i < 8; i++)
                    xv[i] = __ldcg(&x4[(ks * 80 + kc + i) * 16 + nqt]);
#pragma unroll
                for (int i = 0; i < 8; i++) {
                    const int k = ks * 80 + kc + i;
                    const float4 w4 = *reinterpret_cast<const float4*>(&g_W2q[((size_t)k * 128 + j) * 4]);
                    const unsigned long long xlo = packf2(xv[i].x, xv[i].y);
                    const unsigned long long xhi = packf2(xv[i].z, xv[i].w);
                    acc[0] = f2fma(packf2(w4.x, w4.x), xlo, acc[0]);
                    acc[1] = f2fma(packf2(w4.x, w4.x), xhi, acc[1]);
                    acc[2] = f2fma(packf2(w4.y, w4.y), xlo, acc[2]);
                    acc[3] = f2fma(packf2(w4.y, w4.y), xhi, acc[3]);
                    acc[4] = f2fma(packf2(w4.z, w4.z), xlo, acc[4]);
                    acc[5] = f2fma(packf2(w4.z, w4.z), xhi, acc[5]);
                    acc[6] = f2fma(packf2(w4.w, w4.w), xlo, acc[6]);
                    acc[7] = f2fma(packf2(w4.w, w4.w), xhi, acc[7]);
                }
            }
#pragma unroll
            for (int g = 0; g < 4; g++) {
                float2 lo = *reinterpret_cast<float2*>(&acc[g * 2]);
                float2 hi = *reinterpret_cast<float2*>(&acc[g * 2 + 1]);
                *reinterpret_cast<float4*>(&cb[((ks * 4 + jl) * 4 + g) * 64 + nqt * 4]) =
                    make_float4(lo.x, lo.y, hi.x, hi.y);
            }
            __syncthreads();
            if (tid < 256) {
                const int jl2 = tid >> 6, n = tid & 63;
                const int j2 = b * 4 + jl2;
                const float4 bb = *reinterpret_cast<const float4*>(&g_b2[j2 * 4]);
                float gi = bb.x, gf = bb.y, gg = bb.z, go = bb.w;
#pragma unroll
                for (int s = 0; s < 8; s++) {
                    gi += cb[((s * 4 + jl2) * 4 + 0) * 64 + n];
                    gf += cb[((s * 4 + jl2) * 4 + 1) * 64 + n];
                    gg += cb[((s * 4 + jl2) * 4 + 2) * 64 + n];
                    go += cb[((s * 4 + jl2) * 4 + 3) * 64 + n];
                }
                float c = g_c2[j2 * 64 + n];
                c = sigf(gf) * c + sigf(gi) * tanhf(gg);
                float h = sigf(go) * tanhf(c);
                g_c2[j2 * 64 + n] = c;
                __stcg(&g_x2[nxt][(512 + j2) * 64 + n], h);
            }
        } else {
            const int ub = b - 32;
            int u0, ucnt;
            if (ub < 64) { u0 = ub * 3; ucnt = 3; }
            else         { u0 = 192 + (ub - 64) * 2; ucnt = 2; }
            const int ks = tid >> 6, jl = (tid >> 4) & 3, nqt = tid & 15;
            const float4* __restrict__ h14 = reinterpret_cast<const float4*>(g_h1);
            for (int uu = 0; uu < ucnt; uu++) {
                const int u = u0 + uu;
                const int j0 = (u >> 1) * 4;
                const int k0 = (u & 1) * 256;
                float* dst = (u & 1) ? g_pre1b : g_pre1a;
                const int j = j0 + jl;
                unsigned long long acc[8];
#pragma unroll
                for (int i = 0; i < 8; i++) acc[i] = 0ull;
                for (int kc = 0; kc < 32; kc += 8) {
                    float4 xv[8];
#pragma unroll
                    for (int i = 0; i < 8; i++)
                        xv[i] = __ldcg(&h14[(k0 + ks * 32 + kc + i) * 16 + nqt]);
#pragma unroll
                    for (int i = 0; i < 8; i++) {
                        const int k = k0 + ks * 32 + kc + i;
                        const float4 w4 = *reinterpret_cast<const float4*>(&g_W1h[((size_t)k * 512 + j) * 4]);
                        const unsigned long long xlo = packf2(xv[i].x, xv[i].y);
                        const unsigned long long xhi = packf2(xv[i].z, xv[i].w);
                        acc[0] = f2fma(packf2(w4.x, w4.x), xlo, acc[0]);
                        acc[1] = f2fma(packf2(w4.x, w4.x), xhi, acc[1]);
                        acc[2] = f2fma(packf2(w4.y, w4.y), xlo, acc[2]);
                        acc[3] = f2fma(packf2(w4.y, w4.y), xhi, acc[3]);
                        acc[4] = f2fma(packf2(w4.z, w4.z), xlo, acc[4]);
                        acc[5] = f2fma(packf2(w4.z, w4.z), xhi, acc[5]);
                        acc[6] = f2fma(packf2(w4.w, w4.w), xlo, acc[6]);
                        acc[7] = f2fma(packf2(w4.w, w4.w), xhi, acc[7]);
                    }
                }
#pragma unroll
                for (int g = 0; g < 4; g++) {
                    float2 lo = *reinterpret_cast<float2*>(&acc[g * 2]);
                    float2 hi = *reinterpret_cast<float2*>(&acc[g * 2 + 1]);
                    *reinterpret_cast<float4*>(&cb[((ks * 4 + jl) * 4 + g) * 64 + nqt * 4]) =
                        make_float4(lo.x, lo.y, hi.x, hi.y);
                }
                __syncthreads();
                if (tid < 256) {
                    const int jl2 = tid >> 6, n = tid & 63;
                    const int j2 = j0 + jl2;
#pragma unroll
                    for (int g = 0; g < 4; g++) {
                        float s = cb[((0 * 4 + jl2) * 4 + g) * 64 + n]
                                + cb[((1 * 4 + jl2) * 4 + g) * 64 + n]
                                + cb[((2 * 4 + jl2) * 4 + g) * 64 + n]
                                + cb[((3 * 4 + jl2) * 4 + g) * 64 + n]
                                + cb[((4 * 4 + jl2) * 4 + g) * 64 + n]
                                + cb[((5 * 4 + jl2) * 4 + g) * 64 + n]
                                + cb[((6 * 4 + jl2) * 4 + g) * 64 + n]
                                + cb[((7 * 4 + jl2) * 4 + g) * 64 + n];
                        __stcg(&dst[(j2 * 4 + g) * 64 + n], s);
                    }
                }
                __syncthreads();
            }
        }
        gridbar(bs);

        // ---- Phase C: balanced flash attention, 1 item per block ----
        {
            const int n = in_;
            const int qa4 = iqa * 4, qb4 = iqb * 4;
            const int len = ilen;

            if (tid < 128) h2s[tid] = __ldcg(&g_x2[nxt][(512 + tid) * 64 + n]);
            __syncthreads();

            const float* kTn = g_keyT + (size_t)n * KD * TS;
            float lmax = -3e38f;
            for (int t = qa4 + tid; t < qb4; t += NTHR) {
                if (t < len) {
                    float acc = 0.0f;
#pragma unroll
                    for (int dc = 0; dc < 128; dc += 16) {
                        float kv[16];
#pragma unroll
                        for (int i = 0; i < 16; i++) kv[i] = kTn[(size_t)(dc + i) * TS + t];
#pragma unroll
                        for (int i = 0; i < 16; i++) acc = fmaf(h2s[dc + i], kv[i], acc);
                    }
                    es[t - qa4] = acc;
                    lmax = fmaxf(lmax, acc);
                }
            }
#pragma unroll
            for (int s = 16; s > 0; s >>= 1) lmax = fmaxf(lmax, __shfl_xor_sync(0xffffffffu, lmax, s));
            if (lane == 0) red[wid] = lmax;
            __syncthreads();
            float mx = red[0];
#pragma unroll
            for (int i = 1; i < 16; i++) mx = fmaxf(mx, red[i]);

            float ps = 0.0f;
            for (int t = qa4 + tid; t < qb4; t += NTHR) {
                float w = 0.0f;
                if (t < len) w = __expf(es[t - qa4] - mx);
                es[t - qa4] = w;
                ps += w;
            }
#pragma unroll
            for (int s = 16; s > 0; s >>= 1) ps += __shfl_xor_sync(0xffffffffu, ps, s);
            __syncthreads();
            if (lane == 0) red[wid] = ps;
            __syncthreads();
            float tot = red[0];
#pragma unroll
            for (int i = 1; i < 16; i++) tot += red[i];
            if (tid == 0) { __stcg(&g_cm[b], mx); __stcg(&g_cs[b], tot); }

            // ctx partials: warp wid handles d = wid + 16r, r=0..7
            {
                const int nq = iqb - iqa;
                const float4* vTn = reinterpret_cast<const float4*>(g_valT + (size_t)n * KD * TS);
                const float4* es4 = reinterpret_cast<const float4*>(es);
                unsigned long long acc[8];
#pragma unroll
                for (int r = 0; r < 8; r++) acc[r] = 0ull;
                for (int q = lane; q < nq; q += 32) {
                    const float4 e = es4[q];
                    const unsigned long long elo = packf2(e.x, e.y);
                    const unsigned long long ehi = packf2(e.z, e.w);
#pragma unroll
                    for (int r = 0; r < 8; r++) {
                        const float4 v = vTn[(size_t)(wid + 16 * r) * T4S + iqa + q];
                        acc[r] = f2fma(packf2(v.x, v.y), elo, acc[r]);
                        acc[r] = f2fma(packf2(v.z, v.w), ehi, acc[r]);
                    }
                }
#pragma unroll
                for (int r = 0; r < 8; r++) {
                    float2 f = *reinterpret_cast<float2*>(&acc[r]);
                    float s = f.x + f.y;
#pragma unroll
                    for (int sh = 16; sh > 0; sh >>= 1) s += __shfl_xor_sync(0xffffffffu, s, sh);
                    if (lane == 0) __stcg(&g_cctx[(size_t)b * 128 + wid + 16 * r], s);
                }
            }
        }
        gridbar(bs);
    }

    // ======================= EPILOGUE: logits for step L-1 =======================
    if (b < 64) {
        const int n = b, off = g_coff[n], pn = g_pn[n];
        if (tid < 32) {
            float M = -3e38f;
            for (int i = tid; i < pn; i += 32) M = fmaxf(M, __ldcg(&g_cm[off + i]));
#pragma unroll
            for (int s = 16; s > 0; s >>= 1) M = fmaxf(M, __shfl_xor_sync(0xffffffffu, M, s));
            float S = 0.0f;
            for (int i = tid; i < pn; i += 32) {
                float w = __expf(__ldcg(&g_cm[off + i]) - M);
                wflat[off + i] = w;
                S += w * __ldcg(&g_cs[off + i]);
            }
#pragma unroll
            for (int s = 16; s > 0; s >>= 1) S += __shfl_xor_sync(0xffffffffu, S, s);
            if (tid == 0) sred = 1.0f / S;
        }
        __syncthreads();
        if (tid < 128) {
            float s = 0.0f;
            for (int i = 0; i < pn; i++)
                s += wflat[off + i] * __ldcg(&g_cctx[(size_t)(off + i) * 128 + tid]);
            ctxs[tid] = s * sred;
            h2s[tid] = __ldcg(&g_x2[0][(512 + tid) * 64 + n]);  // nxt(L-1) = 0
        }
        __syncthreads();
        const float4 h0 = *reinterpret_cast<const float4*>(&h2s[lane * 4]);
        const float4 c0 = *reinterpret_cast<const float4*>(&ctxs[lane * 4]);
        for (int v = wid; v < V_V; v += 16) {
            const float4* er = reinterpret_cast<const float4*>(emb + (size_t)v * E_E);
            const float4 e0 = er[lane], e1 = er[lane + 32];
            float d = e0.x * h0.x + e0.y * h0.y + e0.z * h0.z + e0.w * h0.w
                    + e1.x * c0.x + e1.y * c0.y + e1.z * c0.z + e1.w * c0.w;
#pragma unroll
            for (int s = 16; s > 0; s >>= 1) d += __shfl_xor_sync(0xffffffffu, d, s);
            if (lane == 0) out[((size_t)n * L_L + L_L - 1) * V_V + v] = d + bout[v];
        }
    }
}

extern "C" void kernel_launch(void* const* d_in, const int* in_sizes, int n_in,
                              void* d_out, int out_size) {
    mega<<<NBLK, NTHR>>>(
        (const float*)d_in[0], (const float*)d_in[1], (const int*)d_in[2],
        (const int*)d_in[3], (const float*)d_in[4], (const float*)d_in[5],
        (const float*)d_in[6], (const float*)d_in[7], (const float*)d_in[8],
        (const float*)d_in[9], (const float*)d_in[10], (const float*)d_in[11],
        (const float*)d_in[12], (const float*)d_in[13], (float*)d_out);
}

// round 13
// speedup vs baseline: 1.3302x; 1.2846x over previous
#include <cuda_runtime.h>
#include <cstdint>
#include <cstddef>

// Problem: V=35, E=256, H=512, K=128, VS=128, N=64, T=2000, L=300, START=33
#define NBLK 128
#define NTHR 512

#define N_B   64
#define T_T   2000
#define TS    2048
#define T4S   512
#define L_L   300
#define E_E   256
#define H_H   512
#define KD    128
#define V_V   35
#define K2    640
#define START_TOK 33

// ---------------- device scratch ----------------
__device__ __align__(16) float g_keyT[(size_t)N_B * KD * TS];    // [n][d][t], read-only after prep
__device__ __align__(16) float g_valT[(size_t)N_B * KD * TS];
__device__ __align__(16) float g_W1c[128 * H_H * 4];
__device__ __align__(16) float g_W1h[512 * H_H * 4];
__device__ __align__(16) float g_W2q[K2 * KD * 4];
__device__ __align__(16) float g_embW1[V_V * H_H * 4];
__device__ __align__(16) float g_b2[KD * 4];
__device__ __align__(16) float g_pre1a[H_H * 4 * N_B];
__device__ __align__(16) float g_pre1b[H_H * 4 * N_B];
__device__ __align__(16) float g_x1[2][128 * N_B];               // merged ctx [buf][k][n]
__device__ __align__(16) float g_h1[H_H * N_B];
__device__ __align__(16) float g_x2[2][K2 * N_B];                // k<512 h1, k>=512 h2
__device__ __align__(16) float g_c1[H_H * N_B];
__device__ __align__(16) float g_c2[KD * N_B];

// flash schedule + partials (128 items, one per block)
__device__ int   g_itemN[NBLK], g_itemQA[NBLK], g_itemQB[NBLK];
__device__ int   g_coff[N_B + 1];
__device__ float g_cm[NBLK], g_cs[NBLK];
__device__ __align__(16) float g_cctx[NBLK * 128];               // [item][k]
__device__ unsigned g_cflag[NBLK * 32];                          // per-item flag, padded

__device__ unsigned g_arrive[NBLK * 32];
__device__ unsigned g_release;

__device__ __forceinline__ float sigf(float x) { return 1.0f / (1.0f + __expf(-x)); }

__device__ __forceinline__ unsigned long long packf2(float a, float b) {
    float2 f = make_float2(a, b);
    return *reinterpret_cast<unsigned long long*>(&f);
}
__device__ __forceinline__ unsigned long long f2fma(unsigned long long a,
                                                    unsigned long long b,
                                                    unsigned long long c) {
    unsigned long long d;
    asm("fma.rn.f32x2 %0, %1, %2, %3;" : "=l"(d) : "l"(a), "l"(b), "l"(c));
    return d;
}

// ---------------- replay-safe grid barrier ----------------
struct Bar { unsigned gen, s0, r0, sb0, sb1, sb2, sb3; };

__device__ __forceinline__ unsigned ld_rlx(const unsigned* p) {
    unsigned v; asm volatile("ld.relaxed.gpu.u32 %0, [%1];" : "=r"(v) : "l"(p)); return v;
}
__device__ __forceinline__ unsigned ld_acq(const unsigned* p) {
    unsigned v; asm volatile("ld.acquire.gpu.u32 %0, [%1];" : "=r"(v) : "l"(p) : "memory"); return v;
}
__device__ __forceinline__ void st_rel(unsigned* p, unsigned v) {
    asm volatile("st.release.gpu.u32 [%0], %1;" :: "l"(p), "r"(v) : "memory");
}

__device__ __forceinline__ void gridbar(Bar& bs) {
    bs.gen++;
    __syncthreads();
    if (threadIdx.x == 0) st_rel(&g_arrive[blockIdx.x * 32], bs.s0 + bs.gen);
    if (blockIdx.x == 0) {
        if (threadIdx.x < 32) {
            const unsigned t0 = bs.sb0 + bs.gen, t1 = bs.sb1 + bs.gen;
            const unsigned t2 = bs.sb2 + bs.gen, t3 = bs.sb3 + bs.gen;
            for (;;) {
                unsigned v0 = ld_rlx(&g_arrive[(threadIdx.x +  0) * 32]);
                unsigned v1 = ld_rlx(&g_arrive[(threadIdx.x + 32) * 32]);
                unsigned v2 = ld_rlx(&g_arrive[(threadIdx.x + 64) * 32]);
                unsigned v3 = ld_rlx(&g_arrive[(threadIdx.x + 96) * 32]);
                if ((((int)(v0 - t0)) | ((int)(v1 - t1)) |
                     ((int)(v2 - t2)) | ((int)(v3 - t3))) >= 0) break;
            }
            asm volatile("fence.acq_rel.gpu;" ::: "memory");
            __syncwarp();
            if (threadIdx.x == 0) st_rel(&g_release, bs.r0 + bs.gen);
        }
    } else if (threadIdx.x == 0) {
        const unsigned tgt = bs.r0 + bs.gen;
        while ((int)(ld_acq(&g_release) - tgt) < 0) {}
    }
    __syncthreads();
}

__global__ __launch_bounds__(NTHR, 1) void mega(
    const float* __restrict__ key, const float* __restrict__ values,
    const int* __restrict__ lens, const int* __restrict__ text,
    const float* __restrict__ emb,
    const float* __restrict__ Wih1, const float* __restrict__ Whh1,
    const float* __restrict__ bih1, const float* __restrict__ bhh1,
    const float* __restrict__ Wih2, const float* __restrict__ Whh2,
    const float* __restrict__ bih2, const float* __restrict__ bhh2,
    const float* __restrict__ bout, float* __restrict__ out)
{
    __shared__ __align__(16) float cb[8192];        // 32 KB combine / transpose
    __shared__ __align__(16) float es[2048];        // softmax weights (max ~1000-t segment)
    __shared__ __align__(16) float h2s[128];        // h2 of this block's attention sample
    __shared__ __align__(16) float h2o[128];        // h2 of owner sample b (merge/logits)
    __shared__ __align__(16) float ctxs[128];
    __shared__ float red[32];
    __shared__ float sm_m[80], sm_s[80];
    __shared__ unsigned fbase_sm[80];
    __shared__ float sred;

    const int tid = threadIdx.x;
    const int b = blockIdx.x;
    const int wid = tid >> 5, lane = tid & 31;

    Bar bs; bs.gen = 0; bs.s0 = 0; bs.r0 = 0; bs.sb0 = bs.sb1 = bs.sb2 = bs.sb3 = 0;
    if (tid == 0) { bs.s0 = ld_rlx(&g_arrive[b * 32]); bs.r0 = ld_rlx(&g_release); }
    if (b == 0 && tid < 32) {
        bs.sb0 = ld_rlx(&g_arrive[(tid +  0) * 32]);
        bs.sb1 = ld_rlx(&g_arrive[(tid + 32) * 32]);
        bs.sb2 = ld_rlx(&g_arrive[(tid + 64) * 32]);
        bs.sb3 = ld_rlx(&g_arrive[(tid + 96) * 32]);
    }
    unsigned fb_self = 0;
    if (tid == 0) fb_self = ld_acq(&g_cflag[b * 32]);

    // ======================= PREP =======================
    for (int i = b * NTHR + tid; i < 2 * 128 * N_B; i += NBLK * NTHR) ((float*)g_x1)[i] = 0.0f;
    for (int i = b * NTHR + tid; i < H_H * N_B; i += NBLK * NTHR) g_h1[i] = 0.0f;
    for (int i = b * NTHR + tid; i < 2 * K2 * N_B; i += NBLK * NTHR) ((float*)g_x2)[i] = 0.0f;
    for (int i = b * NTHR + tid; i < H_H * N_B; i += NBLK * NTHR) g_c1[i] = 0.0f;
    for (int i = b * NTHR + tid; i < KD * N_B; i += NBLK * NTHR) g_c2[i] = 0.0f;
    for (int i = b * NTHR + tid; i < H_H * 4 * N_B; i += NBLK * NTHR) {
        g_pre1a[i] = 0.0f; g_pre1b[i] = 0.0f;
    }

    if (b == 0 && tid == 0) {   // greedy proportional schedule: 128 items
        int nq[N_B]; int p[N_B];
        for (int n = 0; n < N_B; n++) { nq[n] = (lens[n] + 3) >> 2; p[n] = 1; }
        for (int e = 0; e < 64; e++) {
            int best = 0;
            for (int n = 1; n < N_B; n++)
                if ((long long)nq[n] * p[best] > (long long)nq[best] * p[n]) best = n;
            p[best]++;
        }
        int idx = 0;
        for (int n = 0; n < N_B; n++) {
            g_coff[n] = idx;
            for (int i = 0; i < p[n]; i++) {
                g_itemN[idx] = n;
                g_itemQA[idx] = (int)((long long)nq[n] * i / p[n]);
                g_itemQB[idx] = (int)((long long)nq[n] * (i + 1) / p[n]);
                idx++;
            }
        }
        g_coff[N_B] = idx;
    }

    for (int idx = b * NTHR + tid; idx < 128 * H_H; idx += NBLK * NTHR) {
        int k = idx / H_H, j = idx % H_H;
        float4 w; float* wp = reinterpret_cast<float*>(&w);
#pragma unroll
        for (int g = 0; g < 4; g++) wp[g] = Wih1[(size_t)(g * H_H + j) * 384 + 256 + k];
        *reinterpret_cast<float4*>(&g_W1c[(size_t)idx * 4]) = w;
    }
    for (int idx = b * NTHR + tid; idx < 512 * H_H; idx += NBLK * NTHR) {
        int k = idx / H_H, j = idx % H_H;
        float4 w; float* wp = reinterpret_cast<float*>(&w);
#pragma unroll
        for (int g = 0; g < 4; g++) wp[g] = Whh1[(size_t)(g * H_H + j) * 512 + k];
        *reinterpret_cast<float4*>(&g_W1h[(size_t)idx * 4]) = w;
    }
    for (int idx = b * NTHR + tid; idx < K2 * KD; idx += NBLK * NTHR) {
        int k = idx / KD, j = idx % KD;
        float4 w; float* wp = reinterpret_cast<float*>(&w);
#pragma unroll
        for (int g = 0; g < 4; g++) {
            int row = g * KD + j;
            wp[g] = (k < 512) ? Wih2[(size_t)row * 512 + k]
                              : Whh2[(size_t)row * 128 + (k - 512)];
        }
        *reinterpret_cast<float4*>(&g_W2q[(size_t)idx * 4]) = w;
    }
    for (int j = b * NTHR + tid; j < KD; j += NBLK * NTHR) {
        float4 w;
        w.x = bih2[j] + bhh2[j];
        w.y = bih2[j + 128] + bhh2[j + 128];
        w.z = bih2[j + 256] + bhh2[j + 256];
        w.w = bih2[j + 384] + bhh2[j + 384];
        *reinterpret_cast<float4*>(&g_b2[j * 4]) = w;
    }
    for (int it = b * 16 + wid; it < V_V * H_H; it += NBLK * 16) {
        int tok = it / H_H, j = it % H_H;
        const float4* e4 = reinterpret_cast<const float4*>(emb + (size_t)tok * E_E);
        float4 ea = e4[lane], eb = e4[lane + 32];
        float a[4];
#pragma unroll
        for (int g = 0; g < 4; g++) {
            const float4* w4 = reinterpret_cast<const float4*>(Wih1 + (size_t)(g * H_H + j) * 384);
            float4 wa = w4[lane], wb = w4[lane + 32];
            a[g] = ea.x * wa.x + ea.y * wa.y + ea.z * wa.z + ea.w * wa.w
                 + eb.x * wb.x + eb.y * wb.y + eb.z * wb.z + eb.w * wb.w;
        }
#pragma unroll
        for (int s = 16; s > 0; s >>= 1) {
#pragma unroll
            for (int g = 0; g < 4; g++) a[g] += __shfl_xor_sync(0xffffffffu, a[g], s);
        }
        if (lane == 0) {
            float4 r;
            r.x = a[0] + bih1[j] + bhh1[j];
            r.y = a[1] + bih1[j + 512] + bhh1[j + 512];
            r.z = a[2] + bih1[j + 1024] + bhh1[j + 1024];
            r.w = a[3] + bih1[j + 1536] + bhh1[j + 1536];
            *reinterpret_cast<float4*>(&g_embW1[(size_t)it * 4]) = r;
        }
    }
    {   // transpose key/values -> [n][d][t padded 2048]
        const int tx = tid & 31, ty = tid >> 5;
        for (int tileid = b; tileid < 2 * N_B * 64 * 4; tileid += NBLK) {
            int rem = tileid;
            const float* src = key;
            float* dst = g_keyT;
            if (rem >= N_B * 64 * 4) { rem -= N_B * 64 * 4; src = values; dst = g_valT; }
            int n = rem / (64 * 4);
            int r2 = rem % (64 * 4);
            int t0 = (r2 / 4) * 32, d0 = (r2 % 4) * 32;
            __syncthreads();
#pragma unroll
            for (int r = 0; r < 32; r += 16) {
                int t = t0 + r + ty;
                cb[(r + ty) * 33 + tx] =
                    (t < T_T) ? src[((size_t)n * T_T + t) * KD + d0 + tx] : 0.0f;
            }
            __syncthreads();
#pragma unroll
            for (int r = 0; r < 32; r += 16) {
                dst[((size_t)n * KD + d0 + r + ty) * TS + t0 + tx] = cb[tx * 33 + (r + ty)];
            }
        }
        __syncthreads();
    }

    gridbar(bs);

    // per-block flash item (constant all steps)
    const int in_  = g_itemN[b];
    const int iqa  = g_itemQA[b];
    const int iqb  = g_itemQB[b];
    const int ilen = lens[in_];
    // owner setup: flag bases for sample b's items (first flag write is >=2 gridbars away)
    int off = 0, pn = 0;
    if (b < 64) {
        off = g_coff[b]; pn = g_coff[b + 1] - off;
        if (tid < pn) fbase_sm[tid] = ld_acq(&g_cflag[(off + tid) * 32]);
    }
    __syncthreads();

    // ======================= MAIN LOOP =======================
    for (int step = 0; step < L_L; step++) {
        const int cur = step & 1, nxt = cur ^ 1;

        // ---- Phase A: gates1 = embW1 + W1c@ctx (K=128) + pre1a + pre1b; cell1 ----
        {
            const int ks = tid >> 6, jl = (tid >> 4) & 3, nqt = tid & 15;
            const int j = b * 4 + jl;
            const float4* __restrict__ x4 = reinterpret_cast<const float4*>(g_x1[cur]);
            unsigned long long acc[8];
#pragma unroll
            for (int i = 0; i < 8; i++) acc[i] = 0ull;
#pragma unroll
            for (int kc = 0; kc < 16; kc += 8) {
                float4 xv[8];
#pragma unroll
                for (int i = 0; i < 8; i++)
                    xv[i] = __ldcg(&x4[(ks * 16 + kc + i) * 16 + nqt]);
#pragma unroll
                for (int i = 0; i < 8; i++) {
                    const int k = ks * 16 + kc + i;
                    const float4 w4 = *reinterpret_cast<const float4*>(&g_W1c[((size_t)k * 512 + j) * 4]);
                    const unsigned long long xlo = packf2(xv[i].x, xv[i].y);
                    const unsigned long long xhi = packf2(xv[i].z, xv[i].w);
                    acc[0] = f2fma(packf2(w4.x, w4.x), xlo, acc[0]);
                    acc[1] = f2fma(packf2(w4.x, w4.x), xhi, acc[1]);
                    acc[2] = f2fma(packf2(w4.y, w4.y), xlo, acc[2]);
                    acc[3] = f2fma(packf2(w4.y, w4.y), xhi, acc[3]);
                    acc[4] = f2fma(packf2(w4.z, w4.z), xlo, acc[4]);
                    acc[5] = f2fma(packf2(w4.z, w4.z), xhi, acc[5]);
                    acc[6] = f2fma(packf2(w4.w, w4.w), xlo, acc[6]);
                    acc[7] = f2fma(packf2(w4.w, w4.w), xhi, acc[7]);
                }
            }
#pragma unroll
            for (int g = 0; g < 4; g++) {
                float2 lo = *reinterpret_cast<float2*>(&acc[g * 2]);
                float2 hi = *reinterpret_cast<float2*>(&acc[g * 2 + 1]);
                *reinterpret_cast<float4*>(&cb[((ks * 4 + jl) * 4 + g) * 64 + nqt * 4]) =
                    make_float4(lo.x, lo.y, hi.x, hi.y);
            }
            __syncthreads();
            if (tid < 256) {
                const int jl2 = tid >> 6, n = tid & 63;
                const int j2 = b * 4 + jl2;
                const int tok = (step == 0) ? START_TOK : text[n * L_L + step - 1];
                const float4 g0 = *reinterpret_cast<const float4*>(&g_embW1[((size_t)tok * 512 + j2) * 4]);
                float gi = g0.x + __ldcg(&g_pre1a[(j2 * 4 + 0) * 64 + n]) + __ldcg(&g_pre1b[(j2 * 4 + 0) * 64 + n]);
                float gf = g0.y + __ldcg(&g_pre1a[(j2 * 4 + 1) * 64 + n]) + __ldcg(&g_pre1b[(j2 * 4 + 1) * 64 + n]);
                float gg = g0.z + __ldcg(&g_pre1a[(j2 * 4 + 2) * 64 + n]) + __ldcg(&g_pre1b[(j2 * 4 + 2) * 64 + n]);
                float go = g0.w + __ldcg(&g_pre1a[(j2 * 4 + 3) * 64 + n]) + __ldcg(&g_pre1b[(j2 * 4 + 3) * 64 + n]);
#pragma unroll
                for (int s = 0; s < 8; s++) {
                    gi += cb[((s * 4 + jl2) * 4 + 0) * 64 + n];
                    gf += cb[((s * 4 + jl2) * 4 + 1) * 64 + n];
                    gg += cb[((s * 4 + jl2) * 4 + 2) * 64 + n];
                    go += cb[((s * 4 + jl2) * 4 + 3) * 64 + n];
                }
                float c = g_c1[j2 * 64 + n];
                c = sigf(gf) * c + sigf(gi) * tanhf(gg);
                float h = sigf(go) * tanhf(c);
                g_c1[j2 * 64 + n] = c;
                __stcg(&g_h1[j2 * 64 + n], h);
                __stcg(&g_x2[cur][j2 * 64 + n], h);
            }
        }
        gridbar(bs);

        // ---- Phase B: gates2+cell2 (blocks 0-31) | pre1 units (blocks 32-127) ----
        if (b < 32) {
            const int ks = tid >> 6, jl = (tid >> 4) & 3, nqt = tid & 15;
            const int j = b * 4 + jl;
            const float4* __restrict__ x4 = reinterpret_cast<const float4*>(g_x2[cur]);
            unsigned long long acc[8];
#pragma unroll
            for (int i = 0; i < 8; i++) acc[i] = 0ull;
            for (int kc = 0; kc < 80; kc += 8) {
                float4 xv[8];
#pragma unroll
                for (int i = 0; i < 8; i++)
                    xv[i] = __ldcg(&x4[(ks * 80 + kc + i) * 16 + nqt]);
#pragma unroll
                for (int i = 0; i < 8; i++) {
                    const int k = ks * 80 + kc + i;
                    const float4 w4 = *reinterpret_cast<const float4*>(&g_W2q[((size_t)k * 128 + j) * 4]);
                    const unsigned long long xlo = packf2(xv[i].x, xv[i].y);
                    const unsigned long long xhi = packf2(xv[i].z, xv[i].w);
                    acc[0] = f2fma(packf2(w4.x, w4.x), xlo, acc[0]);
                    acc[1] = f2fma(packf2(w4.x, w4.x), xhi, acc[1]);
                    acc[2] = f2fma(packf2(w4.y, w4.y), xlo, acc[2]);
                    acc[3] = f2fma(packf2(w4.y, w4.y), xhi, acc[3]);
                    acc[4] = f2fma(packf2(w4.z, w4.z), xlo, acc[4]);
                    acc[5] = f2fma(packf2(w4.z, w4.z), xhi, acc[5]);
                    acc[6] = f2fma(packf2(w4.w, w4.w), xlo, acc[6]);
                    acc[7] = f2fma(packf2(w4.w, w4.w), xhi, acc[7]);
                }
            }
#pragma unroll
            for (int g = 0; g < 4; g++) {
                float2 lo = *reinterpret_cast<float2*>(&acc[g * 2]);
                float2 hi = *reinterpret_cast<float2*>(&acc[g * 2 + 1]);
                *reinterpret_cast<float4*>(&cb[((ks * 4 + jl) * 4 + g) * 64 + nqt * 4]) =
                    make_float4(lo.x, lo.y, hi.x, hi.y);
            }
            __syncthreads();
            if (tid < 256) {
                const int jl2 = tid >> 6, n = tid & 63;
                const int j2 = b * 4 + jl2;
                const float4 bb = *reinterpret_cast<const float4*>(&g_b2[j2 * 4]);
                float gi = bb.x, gf = bb.y, gg = bb.z, go = bb.w;
#pragma unroll
                for (int s = 0; s < 8; s++) {
                    gi += cb[((s * 4 + jl2) * 4 + 0) * 64 + n];
                    gf += cb[((s * 4 + jl2) * 4 + 1) * 64 + n];
                    gg += cb[((s * 4 + jl2) * 4 + 2) * 64 + n];
                    go += cb[((s * 4 + jl2) * 4 + 3) * 64 + n];
                }
                float c = g_c2[j2 * 64 + n];
                c = sigf(gf) * c + sigf(gi) * tanhf(gg);
                float h = sigf(go) * tanhf(c);
                g_c2[j2 * 64 + n] = c;
                __stcg(&g_x2[nxt][(512 + j2) * 64 + n], h);
            }
        } else {
            const int ub = b - 32;
            int u0, ucnt;
            if (ub < 64) { u0 = ub * 3; ucnt = 3; }
            else         { u0 = 192 + (ub - 64) * 2; ucnt = 2; }
            const int ks = tid >> 6, jl = (tid >> 4) & 3, nqt = tid & 15;
            const float4* __restrict__ h14 = reinterpret_cast<const float4*>(g_h1);
            for (int uu = 0; uu < ucnt; uu++) {
                const int u = u0 + uu;
                const int j0 = (u >> 1) * 4;
                const int k0 = (u & 1) * 256;
                float* dst = (u & 1) ? g_pre1b : g_pre1a;
                const int j = j0 + jl;
                unsigned long long acc[8];
#pragma unroll
                for (int i = 0; i < 8; i++) acc[i] = 0ull;
                for (int kc = 0; kc < 32; kc += 8) {
                    float4 xv[8];
#pragma unroll
                    for (int i = 0; i < 8; i++)
                        xv[i] = __ldcg(&h14[(k0 + ks * 32 + kc + i) * 16 + nqt]);
#pragma unroll
                    for (int i = 0; i < 8; i++) {
                        const int k = k0 + ks * 32 + kc + i;
                        const float4 w4 = *reinterpret_cast<const float4*>(&g_W1h[((size_t)k * 512 + j) * 4]);
                        const unsigned long long xlo = packf2(xv[i].x, xv[i].y);
                        const unsigned long long xhi = packf2(xv[i].z, xv[i].w);
                        acc[0] = f2fma(packf2(w4.x, w4.x), xlo, acc[0]);
                        acc[1] = f2fma(packf2(w4.x, w4.x), xhi, acc[1]);
                        acc[2] = f2fma(packf2(w4.y, w4.y), xlo, acc[2]);
                        acc[3] = f2fma(packf2(w4.y, w4.y), xhi, acc[3]);
                        acc[4] = f2fma(packf2(w4.z, w4.z), xlo, acc[4]);
                        acc[5] = f2fma(packf2(w4.z, w4.z), xhi, acc[5]);
                        acc[6] = f2fma(packf2(w4.w, w4.w), xlo, acc[6]);
                        acc[7] = f2fma(packf2(w4.w, w4.w), xhi, acc[7]);
                    }
                }
#pragma unroll
                for (int g = 0; g < 4; g++) {
                    float2 lo = *reinterpret_cast<float2*>(&acc[g * 2]);
                    float2 hi = *reinterpret_cast<float2*>(&acc[g * 2 + 1]);
                    *reinterpret_cast<float4*>(&cb[((ks * 4 + jl) * 4 + g) * 64 + nqt * 4]) =
                        make_float4(lo.x, lo.y, hi.x, hi.y);
                }
                __syncthreads();
                if (tid < 256) {
                    const int jl2 = tid >> 6, n = tid & 63;
                    const int j2 = j0 + jl2;
#pragma unroll
                    for (int g = 0; g < 4; g++) {
                        float s = cb[((0 * 4 + jl2) * 4 + g) * 64 + n]
                                + cb[((1 * 4 + jl2) * 4 + g) * 64 + n]
                                + cb[((2 * 4 + jl2) * 4 + g) * 64 + n]
                                + cb[((3 * 4 + jl2) * 4 + g) * 64 + n]
                                + cb[((4 * 4 + jl2) * 4 + g) * 64 + n]
                                + cb[((5 * 4 + jl2) * 4 + g) * 64 + n]
                                + cb[((6 * 4 + jl2) * 4 + g) * 64 + n]
                                + cb[((7 * 4 + jl2) * 4 + g) * 64 + n];
                        __stcg(&dst[(j2 * 4 + g) * 64 + n], s);
                    }
                }
                __syncthreads();
            }
        }
        gridbar(bs);

        // ---- Phase C: balanced flash attention + owner merge + logits ----
        {
            const int n = in_;
            const int qa4 = iqa * 4, qb4 = iqb * 4;
            const int len = ilen;

            if (tid < 128) h2s[tid] = __ldcg(&g_x2[nxt][(512 + tid) * 64 + n]);
            __syncthreads();

            const float* kTn = g_keyT + (size_t)n * KD * TS;
            float lmax = -3e38f;
            for (int t = qa4 + tid; t < qb4; t += NTHR) {
                if (t < len) {
                    float acc = 0.0f;
#pragma unroll
                    for (int dc = 0; dc < 128; dc += 16) {
                        float kv[16];
#pragma unroll
                        for (int i = 0; i < 16; i++) kv[i] = kTn[(size_t)(dc + i) * TS + t];
#pragma unroll
                        for (int i = 0; i < 16; i++) acc = fmaf(h2s[dc + i], kv[i], acc);
                    }
                    es[t - qa4] = acc;
                    lmax = fmaxf(lmax, acc);
                }
            }
#pragma unroll
            for (int s = 16; s > 0; s >>= 1) lmax = fmaxf(lmax, __shfl_xor_sync(0xffffffffu, lmax, s));
            if (lane == 0) red[wid] = lmax;
            __syncthreads();
            float mx = red[0];
#pragma unroll
            for (int i = 1; i < 16; i++) mx = fmaxf(mx, red[i]);

            float ps = 0.0f;
            for (int t = qa4 + tid; t < qb4; t += NTHR) {
                float w = 0.0f;
                if (t < len) w = __expf(es[t - qa4] - mx);
                es[t - qa4] = w;
                ps += w;
            }
#pragma unroll
            for (int s = 16; s > 0; s >>= 1) ps += __shfl_xor_sync(0xffffffffu, ps, s);
            __syncthreads();
            if (lane == 0) red[wid] = ps;
            __syncthreads();
            float tot = red[0];
#pragma unroll
            for (int i = 1; i < 16; i++) tot += red[i];
            if (tid == 0) { __stcg(&g_cm[b], mx); __stcg(&g_cs[b], tot); }

            // ctx partials: warp wid handles d = wid + 16r
            {
                const int nq = iqb - iqa;
                const float4* vTn = reinterpret_cast<const float4*>(g_valT + (size_t)n * KD * TS);
                const float4* es4 = reinterpret_cast<const float4*>(es);
                unsigned long long acc[8];
#pragma unroll
                for (int r = 0; r < 8; r++) acc[r] = 0ull;
                for (int q = lane; q < nq; q += 32) {
                    const float4 e = es4[q];
                    const unsigned long long elo = packf2(e.x, e.y);
                    const unsigned long long ehi = packf2(e.z, e.w);
#pragma unroll
                    for (int r = 0; r < 8; r++) {
                        const float4 v = vTn[(size_t)(wid + 16 * r) * T4S + iqa + q];
                        acc[r] = f2fma(packf2(v.x, v.y), elo, acc[r]);
                        acc[r] = f2fma(packf2(v.z, v.w), ehi, acc[r]);
                    }
                }
#pragma unroll
                for (int r = 0; r < 8; r++) {
                    float2 f = *reinterpret_cast<float2*>(&acc[r]);
                    float s = f.x + f.y;
#pragma unroll
                    for (int sh = 16; sh > 0; sh >>= 1) s += __shfl_xor_sync(0xffffffffu, s, sh);
                    if (lane == 0) __stcg(&g_cctx[(size_t)b * 128 + wid + 16 * r], s);
                }
            }
            __syncthreads();
            if (tid == 0) st_rel(&g_cflag[b * 32], fb_self + (unsigned)(step + 1));

            // owner merge + logits (blocks 0..63, sample b)
            if (b < 64) {
                // h2 of sample b (NOT of in_!) — the R11 bug fix
                if (tid >= 128 && tid < 256)
                    h2o[tid - 128] = __ldcg(&g_x2[nxt][(512 + tid - 128) * 64 + b]);
                if (tid < pn) {
                    const unsigned tgt = fbase_sm[tid] + (unsigned)(step + 1);
                    while ((int)(ld_acq(&g_cflag[(off + tid) * 32]) - tgt) < 0) {}
                }
                __syncthreads();
                if (tid < pn) {
                    sm_m[tid] = __ldcg(&g_cm[off + tid]);
                    sm_s[tid] = __ldcg(&g_cs[off + tid]);
                }
                __syncthreads();
                if (tid < 32) {
                    float M = -3e38f;
                    for (int i = tid; i < pn; i += 32) M = fmaxf(M, sm_m[i]);
#pragma unroll
                    for (int s = 16; s > 0; s >>= 1) M = fmaxf(M, __shfl_xor_sync(0xffffffffu, M, s));
                    float S = 0.0f;
                    for (int i = tid; i < pn; i += 32) {
                        float w = __expf(sm_m[i] - M);
                        sm_m[i] = w;
                        S += w * sm_s[i];
                    }
#pragma unroll
                    for (int s = 16; s > 0; s >>= 1) S += __shfl_xor_sync(0xffffffffu, S, s);
                    if (tid == 0) sred = 1.0f / S;
                }
                __syncthreads();
                if (tid < 128) {
                    float acc = 0.0f;
                    int i = 0;
                    for (; i + 8 <= pn; i += 8) {
                        float p[8];
#pragma unroll
                        for (int r = 0; r < 8; r++)
                            p[r] = __ldcg(&g_cctx[(size_t)(off + i + r) * 128 + tid]);
#pragma unroll
                        for (int r = 0; r < 8; r++) acc += sm_m[i + r] * p[r];
                    }
                    for (; i < pn; i++)
                        acc += sm_m[i] * __ldcg(&g_cctx[(size_t)(off + i) * 128 + tid]);
                    const float cx = acc * sred;
                    ctxs[tid] = cx;
                    __stcg(&g_x1[nxt][tid * 64 + b], cx);
                }
                __syncthreads();
                {   // logits for this step, sample b: uses h2o (sample b) + merged ctx
                    const float4 h0 = *reinterpret_cast<const float4*>(&h2o[lane * 4]);
                    const float4 c0 = *reinterpret_cast<const float4*>(&ctxs[lane * 4]);
                    for (int v = wid; v < V_V; v += 16) {
                        const float4* er = reinterpret_cast<const float4*>(emb + (size_t)v * E_E);
                        const float4 e0 = er[lane], e1 = er[lane + 32];
                        float d = e0.x * h0.x + e0.y * h0.y + e0.z * h0.z + e0.w * h0.w
                                + e1.x * c0.x + e1.y * c0.y + e1.z * c0.z + e1.w * c0.w;
#pragma unroll
                        for (int s = 16; s > 0; s >>= 1) d += __shfl_xor_sync(0xffffffffu, d, s);
                        if (lane == 0) out[((size_t)b * L_L + step) * V_V + v] = d + bout[v];
                    }
                }
            }
        }
        gridbar(bs);
    }
}

extern "C" void kernel_launch(void* const* d_in, const int* in_sizes, int n_in,
                              void* d_out, int out_size) {
    mega<<<NBLK, NTHR>>>(
        (const float*)d_in[0], (const float*)d_in[1], (const int*)d_in[2],
        (const int*)d_in[3], (const float*)d_in[4], (const float*)d_in[5],
        (const float*)d_in[6], (const float*)d_in[7], (const float*)d_in[8],
        (const float*)d_in[9], (const float*)d_in[10], (const float*)d_in[11],
        (const float*)d_in[12], (const float*)d_in[13], (float*)d_out);
}

// round 14
// speedup vs baseline: 1.5335x; 1.1528x over previous
#include <cuda_runtime.h>
#include <cuda_fp16.h>
#include <cstdint>
#include <cstddef>

// Problem: V=35, E=256, H=512, K=128, VS=128, N=64, T=2000, L=300, START=33
#define NBLK 128
#define NTHR 512

#define N_B   64
#define T_T   2000
#define TS    2048
#define T4S   512
#define L_L   300
#define E_E   256
#define H_H   512
#define KD    128
#define V_V   35
#define K2    640
#define START_TOK 33

// ---------------- device scratch ----------------
__device__ __align__(16) float  g_keyT[(size_t)N_B * KD * TS];   // [n][d][t] fp32
__device__ __align__(16) __half g_valTh[(size_t)N_B * KD * TS];  // [n][d][t] fp16
__device__ __align__(16) float g_W1c[128 * H_H * 4];
__device__ __align__(16) float g_W1h[512 * H_H * 4];
__device__ __align__(16) float g_W2q[K2 * KD * 4];
__device__ __align__(16) float g_embW1[V_V * H_H * 4];
__device__ __align__(16) float g_b2[KD * 4];
__device__ __align__(16) float g_pre1a[H_H * N_B * 4];           // [(j*64+n)*4+g]
__device__ __align__(16) float g_pre1b[H_H * N_B * 4];
__device__ __align__(16) float g_x1[2][128 * N_B];               // merged ctx [buf][k][n]
__device__ __align__(16) float g_h1[H_H * N_B];
__device__ __align__(16) float g_x2[2][K2 * N_B];                // k<512 h1, k>=512 h2
__device__ __align__(16) float g_c1[H_H * N_B];
__device__ __align__(16) float g_c2[KD * N_B];

// flash schedule + partials
__device__ int   g_itemN[NBLK], g_itemQA[NBLK], g_itemQB[NBLK];
__device__ int   g_coff[N_B + 1];
__device__ float g_cm[NBLK], g_cs[NBLK];
__device__ __align__(16) float g_cctx[NBLK * 128];
__device__ unsigned g_cflag[NBLK * 32];      // per-item done flag
__device__ unsigned g_h2flag[32 * 32];       // per-gates2-block h2-ready flag

__device__ unsigned g_arrive[NBLK * 32];
__device__ unsigned g_release;

__device__ __forceinline__ float sigf(float x) { return 1.0f / (1.0f + __expf(-x)); }

__device__ __forceinline__ unsigned long long packf2(float a, float b) {
    float2 f = make_float2(a, b);
    return *reinterpret_cast<unsigned long long*>(&f);
}
__device__ __forceinline__ unsigned long long f2fma(unsigned long long a,
                                                    unsigned long long b,
                                                    unsigned long long c) {
    unsigned long long d;
    asm("fma.rn.f32x2 %0, %1, %2, %3;" : "=l"(d) : "l"(a), "l"(b), "l"(c));
    return d;
}

// ---------------- replay-safe grid barrier ----------------
struct Bar { unsigned gen, s0, r0, sb0, sb1, sb2, sb3; };

__device__ __forceinline__ unsigned ld_rlx(const unsigned* p) {
    unsigned v; asm volatile("ld.relaxed.gpu.u32 %0, [%1];" : "=r"(v) : "l"(p)); return v;
}
__device__ __forceinline__ unsigned ld_acq(const unsigned* p) {
    unsigned v; asm volatile("ld.acquire.gpu.u32 %0, [%1];" : "=r"(v) : "l"(p) : "memory"); return v;
}
__device__ __forceinline__ void st_rel(unsigned* p, unsigned v) {
    asm volatile("st.release.gpu.u32 [%0], %1;" :: "l"(p), "r"(v) : "memory");
}

__device__ __forceinline__ void gridbar(Bar& bs) {
    bs.gen++;
    __syncthreads();
    if (threadIdx.x == 0) st_rel(&g_arrive[blockIdx.x * 32], bs.s0 + bs.gen);
    if (blockIdx.x == 0) {
        if (threadIdx.x < 32) {
            const unsigned t0 = bs.sb0 + bs.gen, t1 = bs.sb1 + bs.gen;
            const unsigned t2 = bs.sb2 + bs.gen, t3 = bs.sb3 + bs.gen;
            for (;;) {
                unsigned v0 = ld_rlx(&g_arrive[(threadIdx.x +  0) * 32]);
                unsigned v1 = ld_rlx(&g_arrive[(threadIdx.x + 32) * 32]);
                unsigned v2 = ld_rlx(&g_arrive[(threadIdx.x + 64) * 32]);
                unsigned v3 = ld_rlx(&g_arrive[(threadIdx.x + 96) * 32]);
                if ((((int)(v0 - t0)) | ((int)(v1 - t1)) |
                     ((int)(v2 - t2)) | ((int)(v3 - t3))) >= 0) break;
            }
            asm volatile("fence.acq_rel.gpu;" ::: "memory");
            __syncwarp();
            if (threadIdx.x == 0) st_rel(&g_release, bs.r0 + bs.gen);
        }
    } else if (threadIdx.x == 0) {
        const unsigned tgt = bs.r0 + bs.gen;
        while ((int)(ld_acq(&g_release) - tgt) < 0) {}
    }
    __syncthreads();
}

__global__ __launch_bounds__(NTHR, 1) void mega(
    const float* __restrict__ key, const float* __restrict__ values,
    const int* __restrict__ lens, const int* __restrict__ text,
    const float* __restrict__ emb,
    const float* __restrict__ Wih1, const float* __restrict__ Whh1,
    const float* __restrict__ bih1, const float* __restrict__ bhh1,
    const float* __restrict__ Wih2, const float* __restrict__ Whh2,
    const float* __restrict__ bih2, const float* __restrict__ bhh2,
    const float* __restrict__ bout, float* __restrict__ out)
{
    __shared__ __align__(16) float cb[8192];        // 32 KB combine / transpose
    __shared__ __align__(16) float es[2048];        // softmax weights
    __shared__ __align__(16) float h2s[128];
    __shared__ __align__(16) float h2o[128];
    __shared__ __align__(16) float ctxs[128];
    __shared__ float red[32];
    __shared__ float sm_m[80], sm_s[80];
    __shared__ unsigned fbase_sm[80];
    __shared__ unsigned h2fb_sm[32];
    __shared__ float sred;

    const int tid = threadIdx.x;
    const int b = blockIdx.x;
    const int wid = tid >> 5, lane = tid & 31;

    Bar bs; bs.gen = 0; bs.s0 = 0; bs.r0 = 0; bs.sb0 = bs.sb1 = bs.sb2 = bs.sb3 = 0;
    if (tid == 0) { bs.s0 = ld_rlx(&g_arrive[b * 32]); bs.r0 = ld_rlx(&g_release); }
    if (b == 0 && tid < 32) {
        bs.sb0 = ld_rlx(&g_arrive[(tid +  0) * 32]);
        bs.sb1 = ld_rlx(&g_arrive[(tid + 32) * 32]);
        bs.sb2 = ld_rlx(&g_arrive[(tid + 64) * 32]);
        bs.sb3 = ld_rlx(&g_arrive[(tid + 96) * 32]);
    }
    unsigned fb_self = 0;
    if (tid == 0) fb_self = ld_acq(&g_cflag[b * 32]);
    if (tid < 32) h2fb_sm[tid] = ld_acq(&g_h2flag[tid * 32]);

    // ======================= PREP =======================
    for (int i = b * NTHR + tid; i < 2 * 128 * N_B; i += NBLK * NTHR) ((float*)g_x1)[i] = 0.0f;
    for (int i = b * NTHR + tid; i < H_H * N_B; i += NBLK * NTHR) g_h1[i] = 0.0f;
    for (int i = b * NTHR + tid; i < 2 * K2 * N_B; i += NBLK * NTHR) ((float*)g_x2)[i] = 0.0f;
    for (int i = b * NTHR + tid; i < H_H * N_B; i += NBLK * NTHR) g_c1[i] = 0.0f;
    for (int i = b * NTHR + tid; i < KD * N_B; i += NBLK * NTHR) g_c2[i] = 0.0f;
    for (int i = b * NTHR + tid; i < H_H * N_B * 4; i += NBLK * NTHR) {
        g_pre1a[i] = 0.0f; g_pre1b[i] = 0.0f;
    }

    if (b == 0 && tid == 0) {   // weighted greedy schedule: 128 items
        int nq[N_B]; int p[N_B];
        for (int n = 0; n < N_B; n++) { nq[n] = (lens[n] + 3) >> 2; p[n] = 1; }
        for (int e = 0; e < 64; e++) {
            int best = 0;
            for (int n = 1; n < N_B; n++)
                if ((long long)nq[n] * p[best] > (long long)nq[best] * p[n]) best = n;
            p[best]++;
        }
        int idx = 0;
        for (int n = 0; n < N_B; n++) {
            g_coff[n] = idx;
            // block-role weights: gates2 blocks get bigger slices (they start attn first)
            int wpre[66]; int wsum = 0;
            for (int i = 0; i < p[n]; i++) {
                wpre[i] = wsum;
                const int blk = idx + i;
                wsum += (blk < 32) ? 115 : (blk < 96) ? 82 : 103;
            }
            wpre[p[n]] = wsum;
            for (int i = 0; i < p[n]; i++) {
                g_itemN[idx] = n;
                g_itemQA[idx] = (int)((long long)nq[n] * wpre[i] / wsum);
                g_itemQB[idx] = (int)((long long)nq[n] * wpre[i + 1] / wsum);
                idx++;
            }
        }
        g_coff[N_B] = idx;
    }

    for (int idx = b * NTHR + tid; idx < 128 * H_H; idx += NBLK * NTHR) {
        int k = idx / H_H, j = idx % H_H;
        float4 w; float* wp = reinterpret_cast<float*>(&w);
#pragma unroll
        for (int g = 0; g < 4; g++) wp[g] = Wih1[(size_t)(g * H_H + j) * 384 + 256 + k];
        *reinterpret_cast<float4*>(&g_W1c[(size_t)idx * 4]) = w;
    }
    for (int idx = b * NTHR + tid; idx < 512 * H_H; idx += NBLK * NTHR) {
        int k = idx / H_H, j = idx % H_H;
        float4 w; float* wp = reinterpret_cast<float*>(&w);
#pragma unroll
        for (int g = 0; g < 4; g++) wp[g] = Whh1[(size_t)(g * H_H + j) * 512 + k];
        *reinterpret_cast<float4*>(&g_W1h[(size_t)idx * 4]) = w;
    }
    for (int idx = b * NTHR + tid; idx < K2 * KD; idx += NBLK * NTHR) {
        int k = idx / KD, j = idx % KD;
        float4 w; float* wp = reinterpret_cast<float*>(&w);
#pragma unroll
        for (int g = 0; g < 4; g++) {
            int row = g * KD + j;
            wp[g] = (k < 512) ? Wih2[(size_t)row * 512 + k]
                              : Whh2[(size_t)row * 128 + (k - 512)];
        }
        *reinterpret_cast<float4*>(&g_W2q[(size_t)idx * 4]) = w;
    }
    for (int j = b * NTHR + tid; j < KD; j += NBLK * NTHR) {
        float4 w;
        w.x = bih2[j] + bhh2[j];
        w.y = bih2[j + 128] + bhh2[j + 128];
        w.z = bih2[j + 256] + bhh2[j + 256];
        w.w = bih2[j + 384] + bhh2[j + 384];
        *reinterpret_cast<float4*>(&g_b2[j * 4]) = w;
    }
    for (int it = b * 16 + wid; it < V_V * H_H; it += NBLK * 16) {
        int tok = it / H_H, j = it % H_H;
        const float4* e4 = reinterpret_cast<const float4*>(emb + (size_t)tok * E_E);
        float4 ea = e4[lane], eb = e4[lane + 32];
        float a[4];
#pragma unroll
        for (int g = 0; g < 4; g++) {
            const float4* w4 = reinterpret_cast<const float4*>(Wih1 + (size_t)(g * H_H + j) * 384);
            float4 wa = w4[lane], wb = w4[lane + 32];
            a[g] = ea.x * wa.x + ea.y * wa.y + ea.z * wa.z + ea.w * wa.w
                 + eb.x * wb.x + eb.y * wb.y + eb.z * wb.z + eb.w * wb.w;
        }
#pragma unroll
        for (int s = 16; s > 0; s >>= 1) {
#pragma unroll
            for (int g = 0; g < 4; g++) a[g] += __shfl_xor_sync(0xffffffffu, a[g], s);
        }
        if (lane == 0) {
            float4 r;
            r.x = a[0] + bih1[j] + bhh1[j];
            r.y = a[1] + bih1[j + 512] + bhh1[j + 512];
            r.z = a[2] + bih1[j + 1024] + bhh1[j + 1024];
            r.w = a[3] + bih1[j + 1536] + bhh1[j + 1536];
            *reinterpret_cast<float4*>(&g_embW1[(size_t)it * 4]) = r;
        }
    }
    {   // transpose key (fp32) / values (fp16) -> [n][d][t padded 2048]
        const int tx = tid & 31, ty = tid >> 5;
        for (int tileid = b; tileid < 2 * N_B * 64 * 4; tileid += NBLK) {
            int rem = tileid;
            const bool isval = (rem >= N_B * 64 * 4);
            if (isval) rem -= N_B * 64 * 4;
            const float* src = isval ? values : key;
            int n = rem / (64 * 4);
            int r2 = rem % (64 * 4);
            int t0 = (r2 / 4) * 32, d0 = (r2 % 4) * 32;
            __syncthreads();
#pragma unroll
            for (int r = 0; r < 32; r += 16) {
                int t = t0 + r + ty;
                cb[(r + ty) * 33 + tx] =
                    (t < T_T) ? src[((size_t)n * T_T + t) * KD + d0 + tx] : 0.0f;
            }
            __syncthreads();
            if (isval) {
#pragma unroll
                for (int r = 0; r < 32; r += 16)
                    g_valTh[((size_t)n * KD + d0 + r + ty) * TS + t0 + tx] =
                        __float2half(cb[tx * 33 + (r + ty)]);
            } else {
#pragma unroll
                for (int r = 0; r < 32; r += 16)
                    g_keyT[((size_t)n * KD + d0 + r + ty) * TS + t0 + tx] = cb[tx * 33 + (r + ty)];
            }
        }
        __syncthreads();
    }

    gridbar(bs);

    const int in_  = g_itemN[b];
    const int iqa  = g_itemQA[b];
    const int iqb  = g_itemQB[b];
    const int ilen = lens[in_];
    int off = 0, pn = 0;
    if (b < 64) {
        off = g_coff[b]; pn = g_coff[b + 1] - off;
        if (tid < pn) fbase_sm[tid] = ld_acq(&g_cflag[(off + tid) * 32]);
    }
    __syncthreads();

    // ======================= MAIN LOOP (2 gridbars/step) =======================
    for (int step = 0; step < L_L; step++) {
        const int cur = step & 1, nxt = cur ^ 1;

        // ---- Phase A: gates1 = embW1 + W1c@ctx (K=128) + pre1a + pre1b; cell1 ----
        {
            const int ks = tid >> 6, jl = (tid >> 4) & 3, nqt = tid & 15;
            const int j = b * 4 + jl;
            const float4* __restrict__ x4 = reinterpret_cast<const float4*>(g_x1[cur]);
            unsigned long long acc[8];
#pragma unroll
            for (int i = 0; i < 8; i++) acc[i] = 0ull;
#pragma unroll
            for (int kc = 0; kc < 16; kc += 8) {
                float4 xv[8];
#pragma unroll
                for (int i = 0; i < 8; i++)
                    xv[i] = __ldcg(&x4[(ks * 16 + kc + i) * 16 + nqt]);
#pragma unroll
                for (int i = 0; i < 8; i++) {
                    const int k = ks * 16 + kc + i;
                    const float4 w4 = *reinterpret_cast<const float4*>(&g_W1c[((size_t)k * 512 + j) * 4]);
                    const unsigned long long xlo = packf2(xv[i].x, xv[i].y);
                    const unsigned long long xhi = packf2(xv[i].z, xv[i].w);
                    acc[0] = f2fma(packf2(w4.x, w4.x), xlo, acc[0]);
                    acc[1] = f2fma(packf2(w4.x, w4.x), xhi, acc[1]);
                    acc[2] = f2fma(packf2(w4.y, w4.y), xlo, acc[2]);
                    acc[3] = f2fma(packf2(w4.y, w4.y), xhi, acc[3]);
                    acc[4] = f2fma(packf2(w4.z, w4.z), xlo, acc[4]);
                    acc[5] = f2fma(packf2(w4.z, w4.z), xhi, acc[5]);
                    acc[6] = f2fma(packf2(w4.w, w4.w), xlo, acc[6]);
                    acc[7] = f2fma(packf2(w4.w, w4.w), xhi, acc[7]);
                }
            }
#pragma unroll
            for (int g = 0; g < 4; g++) {
                float2 lo = *reinterpret_cast<float2*>(&acc[g * 2]);
                float2 hi = *reinterpret_cast<float2*>(&acc[g * 2 + 1]);
                *reinterpret_cast<float4*>(&cb[((ks * 4 + jl) * 4 + g) * 64 + nqt * 4]) =
                    make_float4(lo.x, lo.y, hi.x, hi.y);
            }
            __syncthreads();
            if (tid < 256) {
                const int jl2 = tid >> 6, n = tid & 63;
                const int j2 = b * 4 + jl2;
                const int tok = (step == 0) ? START_TOK : text[n * L_L + step - 1];
                const float4 g0 = *reinterpret_cast<const float4*>(&g_embW1[((size_t)tok * 512 + j2) * 4]);
                const float4 pa = __ldcg(reinterpret_cast<const float4*>(&g_pre1a[((size_t)j2 * 64 + n) * 4]));
                const float4 pb = __ldcg(reinterpret_cast<const float4*>(&g_pre1b[((size_t)j2 * 64 + n) * 4]));
                float gi = g0.x + pa.x + pb.x;
                float gf = g0.y + pa.y + pb.y;
                float gg = g0.z + pa.z + pb.z;
                float go = g0.w + pa.w + pb.w;
#pragma unroll
                for (int s = 0; s < 8; s++) {
                    gi += cb[((s * 4 + jl2) * 4 + 0) * 64 + n];
                    gf += cb[((s * 4 + jl2) * 4 + 1) * 64 + n];
                    gg += cb[((s * 4 + jl2) * 4 + 2) * 64 + n];
                    go += cb[((s * 4 + jl2) * 4 + 3) * 64 + n];
                }
                float c = g_c1[j2 * 64 + n];
                c = sigf(gf) * c + sigf(gi) * tanhf(gg);
                float h = sigf(go) * tanhf(c);
                g_c1[j2 * 64 + n] = c;
                __stcg(&g_h1[j2 * 64 + n], h);
                __stcg(&g_x2[cur][j2 * 64 + n], h);
            }
        }
        gridbar(bs);

        // ---- Phase BC: gates2/pre1, then h2-flag-synced attention + merge + logits ----
        if (b < 32) {
            const int ks = tid >> 6, jl = (tid >> 4) & 3, nqt = tid & 15;
            const int j = b * 4 + jl;
            const float4* __restrict__ x4 = reinterpret_cast<const float4*>(g_x2[cur]);
            unsigned long long acc[8];
#pragma unroll
            for (int i = 0; i < 8; i++) acc[i] = 0ull;
            for (int kc = 0; kc < 80; kc += 8) {
                float4 xv[8];
#pragma unroll
                for (int i = 0; i < 8; i++)
                    xv[i] = __ldcg(&x4[(ks * 80 + kc + i) * 16 + nqt]);
#pragma unroll
                for (int i = 0; i < 8; i++) {
                    const int k = ks * 80 + kc + i;
                    const float4 w4 = *reinterpret_cast<const float4*>(&g_W2q[((size_t)k * 128 + j) * 4]);
                    const unsigned long long xlo = packf2(xv[i].x, xv[i].y);
                    const unsigned long long xhi = packf2(xv[i].z, xv[i].w);
                    acc[0] = f2fma(packf2(w4.x, w4.x), xlo, acc[0]);
                    acc[1] = f2fma(packf2(w4.x, w4.x), xhi, acc[1]);
                    acc[2] = f2fma(packf2(w4.y, w4.y), xlo, acc[2]);
                    acc[3] = f2fma(packf2(w4.y, w4.y), xhi, acc[3]);
                    acc[4] = f2fma(packf2(w4.z, w4.z), xlo, acc[4]);
                    acc[5] = f2fma(packf2(w4.z, w4.z), xhi, acc[5]);
                    acc[6] = f2fma(packf2(w4.w, w4.w), xlo, acc[6]);
                    acc[7] = f2fma(packf2(w4.w, w4.w), xhi, acc[7]);
                }
            }
#pragma unroll
            for (int g = 0; g < 4; g++) {
                float2 lo = *reinterpret_cast<float2*>(&acc[g * 2]);
                float2 hi = *reinterpret_cast<float2*>(&acc[g * 2 + 1]);
                *reinterpret_cast<float4*>(&cb[((ks * 4 + jl) * 4 + g) * 64 + nqt * 4]) =
                    make_float4(lo.x, lo.y, hi.x, hi.y);
            }
            __syncthreads();
            if (tid < 256) {
                const int jl2 = tid >> 6, n = tid & 63;
                const int j2 = b * 4 + jl2;
                const float4 bb = *reinterpret_cast<const float4*>(&g_b2[j2 * 4]);
                float gi = bb.x, gf = bb.y, gg = bb.z, go = bb.w;
#pragma unroll
                for (int s = 0; s < 8; s++) {
                    gi += cb[((s * 4 + jl2) * 4 + 0) * 64 + n];
                    gf += cb[((s * 4 + jl2) * 4 + 1) * 64 + n];
                    gg += cb[((s * 4 + jl2) * 4 + 2) * 64 + n];
                    go += cb[((s * 4 + jl2) * 4 + 3) * 64 + n];
                }
                float c = g_c2[j2 * 64 + n];
                c = sigf(gf) * c + sigf(gi) * tanhf(gg);
                float h = sigf(go) * tanhf(c);
                g_c2[j2 * 64 + n] = c;
                __stcg(&g_x2[nxt][(512 + j2) * 64 + n], h);
            }
            __syncthreads();
            if (tid == 0) st_rel(&g_h2flag[b * 32], h2fb_sm[b] + (unsigned)(step + 1));
        } else {
            const int ub = b - 32;
            int u0, ucnt;
            if (ub < 64) { u0 = ub * 3; ucnt = 3; }
            else         { u0 = 192 + (ub - 64) * 2; ucnt = 2; }
            const int ks = tid >> 6, jl = (tid >> 4) & 3, nqt = tid & 15;
            const float4* __restrict__ h14 = reinterpret_cast<const float4*>(g_h1);
            for (int uu = 0; uu < ucnt; uu++) {
                const int u = u0 + uu;
                const int j0 = (u >> 1) * 4;
                const int k0 = (u & 1) * 256;
                float* dst = (u & 1) ? g_pre1b : g_pre1a;
                const int j = j0 + jl;
                unsigned long long acc[8];
#pragma unroll
                for (int i = 0; i < 8; i++) acc[i] = 0ull;
                for (int kc = 0; kc < 32; kc += 8) {
                    float4 xv[8];
#pragma unroll
                    for (int i = 0; i < 8; i++)
                        xv[i] = __ldcg(&h14[(k0 + ks * 32 + kc + i) * 16 + nqt]);
#pragma unroll
                    for (int i = 0; i < 8; i++) {
                        const int k = k0 + ks * 32 + kc + i;
                        const float4 w4 = *reinterpret_cast<const float4*>(&g_W1h[((size_t)k * 512 + j) * 4]);
                        const unsigned long long xlo = packf2(xv[i].x, xv[i].y);
                        const unsigned long long xhi = packf2(xv[i].z, xv[i].w);
                        acc[0] = f2fma(packf2(w4.x, w4.x), xlo, acc[0]);
                        acc[1] = f2fma(packf2(w4.x, w4.x), xhi, acc[1]);
                        acc[2] = f2fma(packf2(w4.y, w4.y), xlo, acc[2]);
                        acc[3] = f2fma(packf2(w4.y, w4.y), xhi, acc[3]);
                        acc[4] = f2fma(packf2(w4.z, w4.z), xlo, acc[4]);
                        acc[5] = f2fma(packf2(w4.z, w4.z), xhi, acc[5]);
                        acc[6] = f2fma(packf2(w4.w, w4.w), xlo, acc[6]);
                        acc[7] = f2fma(packf2(w4.w, w4.w), xhi, acc[7]);
                    }
                }
#pragma unroll
                for (int g = 0; g < 4; g++) {
                    float2 lo = *reinterpret_cast<float2*>(&acc[g * 2]);
                    float2 hi = *reinterpret_cast<float2*>(&acc[g * 2 + 1]);
                    *reinterpret_cast<float4*>(&cb[((ks * 4 + jl) * 4 + g) * 64 + nqt * 4]) =
                        make_float4(lo.x, lo.y, hi.x, hi.y);
                }
                __syncthreads();
                if (tid < 256) {
                    const int jl2 = tid >> 6, n = tid & 63;
                    const int j2 = j0 + jl2;
                    float sv[4];
#pragma unroll
                    for (int g = 0; g < 4; g++) {
                        sv[g] = cb[((0 * 4 + jl2) * 4 + g) * 64 + n]
                              + cb[((1 * 4 + jl2) * 4 + g) * 64 + n]
                              + cb[((2 * 4 + jl2) * 4 + g) * 64 + n]
                              + cb[((3 * 4 + jl2) * 4 + g) * 64 + n]
                              + cb[((4 * 4 + jl2) * 4 + g) * 64 + n]
                              + cb[((5 * 4 + jl2) * 4 + g) * 64 + n]
                              + cb[((6 * 4 + jl2) * 4 + g) * 64 + n]
                              + cb[((7 * 4 + jl2) * 4 + g) * 64 + n];
                    }
                    __stcg(reinterpret_cast<float4*>(&dst[((size_t)j2 * 64 + n) * 4]),
                           make_float4(sv[0], sv[1], sv[2], sv[3]));
                }
                __syncthreads();
            }
        }

        // wait for all 32 h2 slices
        if (tid < 32) {
            const unsigned tgt = h2fb_sm[tid] + (unsigned)(step + 1);
            while ((int)(ld_acq(&g_h2flag[tid * 32]) - tgt) < 0) {}
        }
        __syncthreads();

        // ---- attention (balanced item) ----
        {
            const int n = in_;
            const int qa4 = iqa * 4, qb4 = iqb * 4;
            const int len = ilen;

            if (tid < 128) h2s[tid] = __ldcg(&g_x2[nxt][(512 + tid) * 64 + n]);
            __syncthreads();

            const float* kTn = g_keyT + (size_t)n * KD * TS;
            float lmax = -3e38f;
            for (int t = qa4 + tid; t < qb4; t += NTHR) {
                if (t < len) {
                    float a0 = 0.f, a1 = 0.f, a2 = 0.f, a3 = 0.f;
#pragma unroll
                    for (int dc = 0; dc < 128; dc += 16) {
                        float kv[16];
#pragma unroll
                        for (int i = 0; i < 16; i++) kv[i] = kTn[(size_t)(dc + i) * TS + t];
#pragma unroll
                        for (int i = 0; i < 16; i += 4) {
                            a0 = fmaf(h2s[dc + i],     kv[i],     a0);
                            a1 = fmaf(h2s[dc + i + 1], kv[i + 1], a1);
                            a2 = fmaf(h2s[dc + i + 2], kv[i + 2], a2);
                            a3 = fmaf(h2s[dc + i + 3], kv[i + 3], a3);
                        }
                    }
                    const float acc = (a0 + a1) + (a2 + a3);
                    es[t - qa4] = acc;
                    lmax = fmaxf(lmax, acc);
                }
            }
#pragma unroll
            for (int s = 16; s > 0; s >>= 1) lmax = fmaxf(lmax, __shfl_xor_sync(0xffffffffu, lmax, s));
            if (lane == 0) red[wid] = lmax;
            __syncthreads();
            float mx = red[0];
#pragma unroll
            for (int i = 1; i < 16; i++) mx = fmaxf(mx, red[i]);

            float ps = 0.0f;
            for (int t = qa4 + tid; t < qb4; t += NTHR) {
                float w = 0.0f;
                if (t < len) w = __expf(es[t - qa4] - mx);
                es[t - qa4] = w;
                ps += w;
            }
#pragma unroll
            for (int s = 16; s > 0; s >>= 1) ps += __shfl_xor_sync(0xffffffffu, ps, s);
            __syncthreads();
            if (lane == 0) red[wid] = ps;
            __syncthreads();
            float tot = red[0];
#pragma unroll
            for (int i = 1; i < 16; i++) tot += red[i];
            if (tid == 0) { __stcg(&g_cm[b], mx); __stcg(&g_cs[b], tot); }

            // ctx partials from fp16 values: warp wid handles d = wid + 16r
            {
                const int nq = iqb - iqa;
                const __half* vTh = g_valTh + (size_t)n * KD * TS;
                const float4* es4 = reinterpret_cast<const float4*>(es);
                unsigned long long acc[8];
#pragma unroll
                for (int r = 0; r < 8; r++) acc[r] = 0ull;
                for (int q = lane; q < nq; q += 32) {
                    const float4 e = es4[q];
                    const unsigned long long elo = packf2(e.x, e.y);
                    const unsigned long long ehi = packf2(e.z, e.w);
#pragma unroll
                    for (int r = 0; r < 8; r++) {
                        const __half2* vp = reinterpret_cast<const __half2*>(
                            vTh + (size_t)(wid + 16 * r) * TS + (size_t)(iqa + q) * 4);
                        const float2 v01 = __half22float2(vp[0]);
                        const float2 v23 = __half22float2(vp[1]);
                        acc[r] = f2fma(packf2(v01.x, v01.y), elo, acc[r]);
                        acc[r] = f2fma(packf2(v23.x, v23.y), ehi, acc[r]);
                    }
                }
#pragma unroll
                for (int r = 0; r < 8; r++) {
                    float2 f = *reinterpret_cast<float2*>(&acc[r]);
                    float s = f.x + f.y;
#pragma unroll
                    for (int sh = 16; sh > 0; sh >>= 1) s += __shfl_xor_sync(0xffffffffu, s, sh);
                    if (lane == 0) __stcg(&g_cctx[(size_t)b * 128 + wid + 16 * r], s);
                }
            }
            __syncthreads();
            if (tid == 0) st_rel(&g_cflag[b * 32], fb_self + (unsigned)(step + 1));

            // owner merge + logits (blocks 0..63, sample b)
            if (b < 64) {
                if (tid >= 128 && tid < 256)
                    h2o[tid - 128] = __ldcg(&g_x2[nxt][(512 + tid - 128) * 64 + b]);
                if (tid < pn) {
                    const unsigned tgt = fbase_sm[tid] + (unsigned)(step + 1);
                    while ((int)(ld_acq(&g_cflag[(off + tid) * 32]) - tgt) < 0) {}
                }
                __syncthreads();
                if (tid < pn) {
                    sm_m[tid] = __ldcg(&g_cm[off + tid]);
                    sm_s[tid] = __ldcg(&g_cs[off + tid]);
                }
                __syncthreads();
                if (tid < 32) {
                    float M = -3e38f;
                    for (int i = tid; i < pn; i += 32) M = fmaxf(M, sm_m[i]);
#pragma unroll
                    for (int s = 16; s > 0; s >>= 1) M = fmaxf(M, __shfl_xor_sync(0xffffffffu, M, s));
                    float S = 0.0f;
                    for (int i = tid; i < pn; i += 32) {
                        float w = __expf(sm_m[i] - M);
                        sm_m[i] = w;
                        S += w * sm_s[i];
                    }
#pragma unroll
                    for (int s = 16; s > 0; s >>= 1) S += __shfl_xor_sync(0xffffffffu, S, s);
                    if (tid == 0) sred = 1.0f / S;
                }
                __syncthreads();
                if (tid < 128) {
                    float acc = 0.0f;
                    int i = 0;
                    for (; i + 8 <= pn; i += 8) {
                        float p[8];
#pragma unroll
                        for (int r = 0; r < 8; r++)
                            p[r] = __ldcg(&g_cctx[(size_t)(off + i + r) * 128 + tid]);
#pragma unroll
                        for (int r = 0; r < 8; r++) acc += sm_m[i + r] * p[r];
                    }
                    for (; i < pn; i++)
                        acc += sm_m[i] * __ldcg(&g_cctx[(size_t)(off + i) * 128 + tid]);
                    const float cx = acc * sred;
                    ctxs[tid] = cx;
                    __stcg(&g_x1[nxt][tid * 64 + b], cx);
                }
                __syncthreads();
                {
                    const float4 h0 = *reinterpret_cast<const float4*>(&h2o[lane * 4]);
                    const float4 c0 = *reinterpret_cast<const float4*>(&ctxs[lane * 4]);
                    for (int v = wid; v < V_V; v += 16) {
                        const float4* er = reinterpret_cast<const float4*>(emb + (size_t)v * E_E);
                        const float4 e0 = er[lane], e1 = er[lane + 32];
                        float d = e0.x * h0.x + e0.y * h0.y + e0.z * h0.z + e0.w * h0.w
                                + e1.x * c0.x + e1.y * c0.y + e1.z * c0.z + e1.w * c0.w;
#pragma unroll
                        for (int s = 16; s > 0; s >>= 1) d += __shfl_xor_sync(0xffffffffu, d, s);
                        if (lane == 0) out[((size_t)b * L_L + step) * V_V + v] = d + bout[v];
                    }
                }
            }
        }
        gridbar(bs);
    }
}

extern "C" void kernel_launch(void* const* d_in, const int* in_sizes, int n_in,
                              void* d_out, int out_size) {
    mega<<<NBLK, NTHR>>>(
        (const float*)d_in[0], (const float*)d_in[1], (const int*)d_in[2],
        (const int*)d_in[3], (const float*)d_in[4], (const float*)d_in[5],
        (const float*)d_in[6], (const float*)d_in[7], (const float*)d_in[8],
        (const float*)d_in[9], (const float*)d_in[10], (const float*)d_in[11],
        (const float*)d_in[12], (const float*)d_in[13], (float*)d_out);
}

// round 15
// speedup vs baseline: 1.6576x; 1.0810x over previous
#include <cuda_runtime.h>
#include <cuda_fp16.h>
#include <cstdint>
#include <cstddef>

// Problem: V=35, E=256, H=512, K=128, VS=128, N=64, T=2000, L=300, START=33
#define NBLK 128
#define NTHR 512

#define N_B   64
#define T_T   2000
#define TS    2048
#define T4S   512
#define L_L   300
#define E_E   256
#define H_H   512
#define KD    128
#define V_V   35
#define K2    640
#define START_TOK 33

// ---------------- device scratch ----------------
// keys: interleaved [n][dq=d/4][t][4] fp32  (one float4 = 4 d's at fixed t)
__device__ __align__(16) float  g_keyT[(size_t)N_B * KD * TS];
__device__ __align__(16) __half g_valTh[(size_t)N_B * KD * TS]; // [n][d][t] fp16
__device__ __align__(16) float g_W1c[128 * H_H * 4];
__device__ __align__(16) float g_W1h[512 * H_H * 4];
__device__ __align__(16) float g_W2q[K2 * KD * 4];
__device__ __align__(16) float g_embW1[V_V * H_H * 4];
__device__ __align__(16) float g_b2[KD * 4];
__device__ __align__(16) float g_pre1a[H_H * N_B * 4];          // [(j*64+n)*4+g]
__device__ __align__(16) float g_pre1b[H_H * N_B * 4];
__device__ __align__(16) float g_x1[2][128 * N_B];              // merged ctx [buf][k][n]
__device__ __align__(16) float g_h1[H_H * N_B];
__device__ __align__(16) float g_x2[2][K2 * N_B];               // k<512 h1, k>=512 h2
__device__ __align__(16) float g_c1[H_H * N_B];
__device__ __align__(16) float g_c2[KD * N_B];

// flash schedule + partials
__device__ int   g_itemN[NBLK], g_itemQA[NBLK], g_itemQB[NBLK];
__device__ int   g_coff[N_B + 1];
__device__ float g_cm[NBLK], g_cs[NBLK];
__device__ __align__(16) float g_cctx[NBLK * 128];
__device__ unsigned g_cflag[NBLK * 32];      // per-item attention-done flag
__device__ unsigned g_h2flag[32 * 32];       // per-gates2-block h2-ready flag
__device__ unsigned g_h1flag[NBLK * 32];     // per-block h1-ready flag (phase A)

__device__ unsigned g_arrive[NBLK * 32];
__device__ unsigned g_release;

__device__ __forceinline__ float sigf(float x) { return 1.0f / (1.0f + __expf(-x)); }

__device__ __forceinline__ unsigned long long packf2(float a, float b) {
    float2 f = make_float2(a, b);
    return *reinterpret_cast<unsigned long long*>(&f);
}
__device__ __forceinline__ unsigned long long f2fma(unsigned long long a,
                                                    unsigned long long b,
                                                    unsigned long long c) {
    unsigned long long d;
    asm("fma.rn.f32x2 %0, %1, %2, %3;" : "=l"(d) : "l"(a), "l"(b), "l"(c));
    return d;
}

// ---------------- replay-safe grid barrier ----------------
struct Bar { unsigned gen, s0, r0, sb0, sb1, sb2, sb3; };

__device__ __forceinline__ unsigned ld_rlx(const unsigned* p) {
    unsigned v; asm volatile("ld.relaxed.gpu.u32 %0, [%1];" : "=r"(v) : "l"(p)); return v;
}
__device__ __forceinline__ unsigned ld_acq(const unsigned* p) {
    unsigned v; asm volatile("ld.acquire.gpu.u32 %0, [%1];" : "=r"(v) : "l"(p) : "memory"); return v;
}
__device__ __forceinline__ void st_rel(unsigned* p, unsigned v) {
    asm volatile("st.release.gpu.u32 [%0], %1;" :: "l"(p), "r"(v) : "memory");
}

__device__ __forceinline__ void gridbar(Bar& bs) {
    bs.gen++;
    __syncthreads();
    if (threadIdx.x == 0) st_rel(&g_arrive[blockIdx.x * 32], bs.s0 + bs.gen);
    if (blockIdx.x == 0) {
        if (threadIdx.x < 32) {
            const unsigned t0 = bs.sb0 + bs.gen, t1 = bs.sb1 + bs.gen;
            const unsigned t2 = bs.sb2 + bs.gen, t3 = bs.sb3 + bs.gen;
            for (;;) {
                unsigned v0 = ld_rlx(&g_arrive[(threadIdx.x +  0) * 32]);
                unsigned v1 = ld_rlx(&g_arrive[(threadIdx.x + 32) * 32]);
                unsigned v2 = ld_rlx(&g_arrive[(threadIdx.x + 64) * 32]);
                unsigned v3 = ld_rlx(&g_arrive[(threadIdx.x + 96) * 32]);
                if ((((int)(v0 - t0)) | ((int)(v1 - t1)) |
                     ((int)(v2 - t2)) | ((int)(v3 - t3))) >= 0) break;
            }
            asm volatile("fence.acq_rel.gpu;" ::: "memory");
            __syncwarp();
            if (threadIdx.x == 0) st_rel(&g_release, bs.r0 + bs.gen);
        }
    } else if (threadIdx.x == 0) {
        const unsigned tgt = bs.r0 + bs.gen;
        while ((int)(ld_acq(&g_release) - tgt) < 0) {}
    }
    __syncthreads();
}

__global__ __launch_bounds__(NTHR, 1) void mega(
    const float* __restrict__ key, const float* __restrict__ values,
    const int* __restrict__ lens, const int* __restrict__ text,
    const float* __restrict__ emb,
    const float* __restrict__ Wih1, const float* __restrict__ Whh1,
    const float* __restrict__ bih1, const float* __restrict__ bhh1,
    const float* __restrict__ Wih2, const float* __restrict__ Whh2,
    const float* __restrict__ bih2, const float* __restrict__ bhh2,
    const float* __restrict__ bout, float* __restrict__ out)
{
    __shared__ __align__(16) float cb[8192];        // 32 KB combine / transpose
    __shared__ __align__(16) float es[2048];        // softmax weights
    __shared__ __align__(16) float h2s[128];
    __shared__ __align__(16) float h2o[128];
    __shared__ __align__(16) float ctxs[128];
    __shared__ float red[32];
    __shared__ float sm_m[80], sm_s[80];
    __shared__ unsigned fbase_sm[80];
    __shared__ unsigned h2fb_sm[32];
    __shared__ unsigned h1fb_sm[128];
    __shared__ float sred;

    const int tid = threadIdx.x;
    const int b = blockIdx.x;
    const int wid = tid >> 5, lane = tid & 31;

    Bar bs; bs.gen = 0; bs.s0 = 0; bs.r0 = 0; bs.sb0 = bs.sb1 = bs.sb2 = bs.sb3 = 0;
    if (tid == 0) { bs.s0 = ld_rlx(&g_arrive[b * 32]); bs.r0 = ld_rlx(&g_release); }
    if (b == 0 && tid < 32) {
        bs.sb0 = ld_rlx(&g_arrive[(tid +  0) * 32]);
        bs.sb1 = ld_rlx(&g_arrive[(tid + 32) * 32]);
        bs.sb2 = ld_rlx(&g_arrive[(tid + 64) * 32]);
        bs.sb3 = ld_rlx(&g_arrive[(tid + 96) * 32]);
    }
    unsigned fb_self = 0;
    if (tid == 0) fb_self = ld_acq(&g_cflag[b * 32]);
    if (tid < 32) h2fb_sm[tid] = ld_acq(&g_h2flag[tid * 32]);
    if (tid < 128) h1fb_sm[tid] = ld_acq(&g_h1flag[tid * 32]);

    // ======================= PREP =======================
    for (int i = b * NTHR + tid; i < 2 * 128 * N_B; i += NBLK * NTHR) ((float*)g_x1)[i] = 0.0f;
    for (int i = b * NTHR + tid; i < H_H * N_B; i += NBLK * NTHR) g_h1[i] = 0.0f;
    for (int i = b * NTHR + tid; i < 2 * K2 * N_B; i += NBLK * NTHR) ((float*)g_x2)[i] = 0.0f;
    for (int i = b * NTHR + tid; i < H_H * N_B; i += NBLK * NTHR) g_c1[i] = 0.0f;
    for (int i = b * NTHR + tid; i < KD * N_B; i += NBLK * NTHR) g_c2[i] = 0.0f;
    for (int i = b * NTHR + tid; i < H_H * N_B * 4; i += NBLK * NTHR) {
        g_pre1a[i] = 0.0f; g_pre1b[i] = 0.0f;
    }

    if (b == 0 && tid == 0) {   // weighted greedy schedule: 128 items
        int nq[N_B]; int p[N_B];
        for (int n = 0; n < N_B; n++) { nq[n] = (lens[n] + 3) >> 2; p[n] = 1; }
        for (int e = 0; e < 64; e++) {
            int best = 0;
            for (int n = 1; n < N_B; n++)
                if ((long long)nq[n] * p[best] > (long long)nq[best] * p[n]) best = n;
            p[best]++;
        }
        int idx = 0;
        for (int n = 0; n < N_B; n++) {
            g_coff[n] = idx;
            int wpre[66]; int wsum = 0;
            for (int i = 0; i < p[n]; i++) {
                wpre[i] = wsum;
                const int blk = idx + i;
                wsum += (blk < 32) ? 115 : (blk < 96) ? 82 : 103;
            }
            wpre[p[n]] = wsum;
            for (int i = 0; i < p[n]; i++) {
                g_itemN[idx] = n;
                g_itemQA[idx] = (int)((long long)nq[n] * wpre[i] / wsum);
                g_itemQB[idx] = (int)((long long)nq[n] * wpre[i + 1] / wsum);
                idx++;
            }
        }
        g_coff[N_B] = idx;
    }

    for (int idx = b * NTHR + tid; idx < 128 * H_H; idx += NBLK * NTHR) {
        int k = idx / H_H, j = idx % H_H;
        float4 w; float* wp = reinterpret_cast<float*>(&w);
#pragma unroll
        for (int g = 0; g < 4; g++) wp[g] = Wih1[(size_t)(g * H_H + j) * 384 + 256 + k];
        *reinterpret_cast<float4*>(&g_W1c[(size_t)idx * 4]) = w;
    }
    for (int idx = b * NTHR + tid; idx < 512 * H_H; idx += NBLK * NTHR) {
        int k = idx / H_H, j = idx % H_H;
        float4 w; float* wp = reinterpret_cast<float*>(&w);
#pragma unroll
        for (int g = 0; g < 4; g++) wp[g] = Whh1[(size_t)(g * H_H + j) * 512 + k];
        *reinterpret_cast<float4*>(&g_W1h[(size_t)idx * 4]) = w;
    }
    for (int idx = b * NTHR + tid; idx < K2 * KD; idx += NBLK * NTHR) {
        int k = idx / KD, j = idx % KD;
        float4 w; float* wp = reinterpret_cast<float*>(&w);
#pragma unroll
        for (int g = 0; g < 4; g++) {
            int row = g * KD + j;
            wp[g] = (k < 512) ? Wih2[(size_t)row * 512 + k]
                              : Whh2[(size_t)row * 128 + (k - 512)];
        }
        *reinterpret_cast<float4*>(&g_W2q[(size_t)idx * 4]) = w;
    }
    for (int j = b * NTHR + tid; j < KD; j += NBLK * NTHR) {
        float4 w;
        w.x = bih2[j] + bhh2[j];
        w.y = bih2[j + 128] + bhh2[j + 128];
        w.z = bih2[j + 256] + bhh2[j + 256];
        w.w = bih2[j + 384] + bhh2[j + 384];
        *reinterpret_cast<float4*>(&g_b2[j * 4]) = w;
    }
    for (int it = b * 16 + wid; it < V_V * H_H; it += NBLK * 16) {
        int tok = it / H_H, j = it % H_H;
        const float4* e4 = reinterpret_cast<const float4*>(emb + (size_t)tok * E_E);
        float4 ea = e4[lane], eb = e4[lane + 32];
        float a[4];
#pragma unroll
        for (int g = 0; g < 4; g++) {
            const float4* w4 = reinterpret_cast<const float4*>(Wih1 + (size_t)(g * H_H + j) * 384);
            float4 wa = w4[lane], wb = w4[lane + 32];
            a[g] = ea.x * wa.x + ea.y * wa.y + ea.z * wa.z + ea.w * wa.w
                 + eb.x * wb.x + eb.y * wb.y + eb.z * wb.z + eb.w * wb.w;
        }
#pragma unroll
        for (int s = 16; s > 0; s >>= 1) {
#pragma unroll
            for (int g = 0; g < 4; g++) a[g] += __shfl_xor_sync(0xffffffffu, a[g], s);
        }
        if (lane == 0) {
            float4 r;
            r.x = a[0] + bih1[j] + bhh1[j];
            r.y = a[1] + bih1[j + 512] + bhh1[j + 512];
            r.z = a[2] + bih1[j + 1024] + bhh1[j + 1024];
            r.w = a[3] + bih1[j + 1536] + bhh1[j + 1536];
            *reinterpret_cast<float4*>(&g_embW1[(size_t)it * 4]) = r;
        }
    }
    {   // transpose: key fp32 -> interleaved [n][dq][t][4]; values fp16 -> [n][d][t]
        const int tx = tid & 31, ty = tid >> 5;
        for (int tileid = b; tileid < 2 * N_B * 64 * 4; tileid += NBLK) {
            int rem = tileid;
            const bool isval = (rem >= N_B * 64 * 4);
            if (isval) rem -= N_B * 64 * 4;
            const float* src = isval ? values : key;
            int n = rem / (64 * 4);
            int r2 = rem % (64 * 4);
            int t0 = (r2 / 4) * 32, d0 = (r2 % 4) * 32;
            __syncthreads();
#pragma unroll
            for (int r = 0; r < 32; r += 16) {
                int t = t0 + r + ty;
                cb[(r + ty) * 33 + tx] =
                    (t < T_T) ? src[((size_t)n * T_T + t) * KD + d0 + tx] : 0.0f;
            }
            __syncthreads();
            if (isval) {
#pragma unroll
                for (int r = 0; r < 32; r += 16)
                    g_valTh[((size_t)n * KD + d0 + r + ty) * TS + t0 + tx] =
                        __float2half(cb[tx * 33 + (r + ty)]);
            } else {
#pragma unroll
                for (int r = 0; r < 32; r += 16) {
                    const int d = d0 + r + ty;
                    g_keyT[(size_t)n * KD * TS + (size_t)(d >> 2) * (TS * 4)
                           + (size_t)(t0 + tx) * 4 + (d & 3)] = cb[tx * 33 + (r + ty)];
                }
            }
        }
        __syncthreads();
    }

    gridbar(bs);

    const int in_  = g_itemN[b];
    const int iqa  = g_itemQA[b];
    const int iqb  = g_itemQB[b];
    const int ilen = lens[in_];
    int off = 0, pn = 0;
    if (b < 64) {
        off = g_coff[b]; pn = g_coff[b + 1] - off;
        if (tid < pn) fbase_sm[tid] = ld_acq(&g_cflag[(off + tid) * 32]);
    }
    __syncthreads();

    // ======================= MAIN LOOP (1 gridbar/step) =======================
    for (int step = 0; step < L_L; step++) {
        const int cur = step & 1, nxt = cur ^ 1;

        // ---- Phase A: gates1 = embW1 + W1c@ctx (K=128) + pre1a + pre1b; cell1 ----
        {
            const int ks = tid >> 6, jl = (tid >> 4) & 3, nqt = tid & 15;
            const int j = b * 4 + jl;
            const float4* __restrict__ x4 = reinterpret_cast<const float4*>(g_x1[cur]);
            unsigned long long acc[8];
#pragma unroll
            for (int i = 0; i < 8; i++) acc[i] = 0ull;
#pragma unroll
            for (int kc = 0; kc < 16; kc += 8) {
                float4 xv[8];
#pragma unroll
                for (int i = 0; i < 8; i++)
                    xv[i] = __ldcg(&x4[(ks * 16 + kc + i) * 16 + nqt]);
#pragma unroll
                for (int i = 0; i < 8; i++) {
                    const int k = ks * 16 + kc + i;
                    const float4 w4 = *reinterpret_cast<const float4*>(&g_W1c[((size_t)k * 512 + j) * 4]);
                    const unsigned long long xlo = packf2(xv[i].x, xv[i].y);
                    const unsigned long long xhi = packf2(xv[i].z, xv[i].w);
                    acc[0] = f2fma(packf2(w4.x, w4.x), xlo, acc[0]);
                    acc[1] = f2fma(packf2(w4.x, w4.x), xhi, acc[1]);
                    acc[2] = f2fma(packf2(w4.y, w4.y), xlo, acc[2]);
                    acc[3] = f2fma(packf2(w4.y, w4.y), xhi, acc[3]);
                    acc[4] = f2fma(packf2(w4.z, w4.z), xlo, acc[4]);
                    acc[5] = f2fma(packf2(w4.z, w4.z), xhi, acc[5]);
                    acc[6] = f2fma(packf2(w4.w, w4.w), xlo, acc[6]);
                    acc[7] = f2fma(packf2(w4.w, w4.w), xhi, acc[7]);
                }
            }
#pragma unroll
            for (int g = 0; g < 4; g++) {
                float2 lo = *reinterpret_cast<float2*>(&acc[g * 2]);
                float2 hi = *reinterpret_cast<float2*>(&acc[g * 2 + 1]);
                *reinterpret_cast<float4*>(&cb[((ks * 4 + jl) * 4 + g) * 64 + nqt * 4]) =
                    make_float4(lo.x, lo.y, hi.x, hi.y);
            }
            __syncthreads();
            if (tid < 256) {
                const int jl2 = tid >> 6, n = tid & 63;
                const int j2 = b * 4 + jl2;
                const int tok = (step == 0) ? START_TOK : text[n * L_L + step - 1];
                const float4 g0 = *reinterpret_cast<const float4*>(&g_embW1[((size_t)tok * 512 + j2) * 4]);
                const float4 pa = __ldcg(reinterpret_cast<const float4*>(&g_pre1a[((size_t)j2 * 64 + n) * 4]));
                const float4 pb = __ldcg(reinterpret_cast<const float4*>(&g_pre1b[((size_t)j2 * 64 + n) * 4]));
                float gi = g0.x + pa.x + pb.x;
                float gf = g0.y + pa.y + pb.y;
                float gg = g0.z + pa.z + pb.z;
                float go = g0.w + pa.w + pb.w;
#pragma unroll
                for (int s = 0; s < 8; s++) {
                    gi += cb[((s * 4 + jl2) * 4 + 0) * 64 + n];
                    gf += cb[((s * 4 + jl2) * 4 + 1) * 64 + n];
                    gg += cb[((s * 4 + jl2) * 4 + 2) * 64 + n];
                    go += cb[((s * 4 + jl2) * 4 + 3) * 64 + n];
                }
                float c = g_c1[j2 * 64 + n];
                c = sigf(gf) * c + sigf(gi) * tanhf(gg);
                float h = sigf(go) * tanhf(c);
                g_c1[j2 * 64 + n] = c;
                __stcg(&g_h1[j2 * 64 + n], h);
                __stcg(&g_x2[cur][j2 * 64 + n], h);
            }
        }
        // publish h1 flag; decentralized wait replaces the post-A gridbar
        __syncthreads();
        if (tid == 0) st_rel(&g_h1flag[b * 32], h1fb_sm[b] + (unsigned)(step + 1));
        if (tid < 128) {
            const unsigned tgt = h1fb_sm[tid] + (unsigned)(step + 1);
            while ((int)(ld_acq(&g_h1flag[tid * 32]) - tgt) < 0) {}
        }
        __syncthreads();

        // ---- Phase BC: gates2/pre1, then h2-flag-synced attention + merge + logits ----
        if (b < 32) {
            const int ks = tid >> 6, jl = (tid >> 4) & 3, nqt = tid & 15;
            const int j = b * 4 + jl;
            const float4* __restrict__ x4 = reinterpret_cast<const float4*>(g_x2[cur]);
            unsigned long long acc[8];
#pragma unroll
            for (int i = 0; i < 8; i++) acc[i] = 0ull;
            for (int kc = 0; kc < 80; kc += 8) {
                float4 xv[8];
#pragma unroll
                for (int i = 0; i < 8; i++)
                    xv[i] = __ldcg(&x4[(ks * 80 + kc + i) * 16 + nqt]);
#pragma unroll
                for (int i = 0; i < 8; i++) {
                    const int k = ks * 80 + kc + i;
                    const float4 w4 = *reinterpret_cast<const float4*>(&g_W2q[((size_t)k * 128 + j) * 4]);
                    const unsigned long long xlo = packf2(xv[i].x, xv[i].y);
                    const unsigned long long xhi = packf2(xv[i].z, xv[i].w);
                    acc[0] = f2fma(packf2(w4.x, w4.x), xlo, acc[0]);
                    acc[1] = f2fma(packf2(w4.x, w4.x), xhi, acc[1]);
                    acc[2] = f2fma(packf2(w4.y, w4.y), xlo, acc[2]);
                    acc[3] = f2fma(packf2(w4.y, w4.y), xhi, acc[3]);
                    acc[4] = f2fma(packf2(w4.z, w4.z), xlo, acc[4]);
                    acc[5] = f2fma(packf2(w4.z, w4.z), xhi, acc[5]);
                    acc[6] = f2fma(packf2(w4.w, w4.w), xlo, acc[6]);
                    acc[7] = f2fma(packf2(w4.w, w4.w), xhi, acc[7]);
                }
            }
#pragma unroll
            for (int g = 0; g < 4; g++) {
                float2 lo = *reinterpret_cast<float2*>(&acc[g * 2]);
                float2 hi = *reinterpret_cast<float2*>(&acc[g * 2 + 1]);
                *reinterpret_cast<float4*>(&cb[((ks * 4 + jl) * 4 + g) * 64 + nqt * 4]) =
                    make_float4(lo.x, lo.y, hi.x, hi.y);
            }
            __syncthreads();
            if (tid < 256) {
                const int jl2 = tid >> 6, n = tid & 63;
                const int j2 = b * 4 + jl2;
                const float4 bb = *reinterpret_cast<const float4*>(&g_b2[j2 * 4]);
                float gi = bb.x, gf = bb.y, gg = bb.z, go = bb.w;
#pragma unroll
                for (int s = 0; s < 8; s++) {
                    gi += cb[((s * 4 + jl2) * 4 + 0) * 64 + n];
                    gf += cb[((s * 4 + jl2) * 4 + 1) * 64 + n];
                    gg += cb[((s * 4 + jl2) * 4 + 2) * 64 + n];
                    go += cb[((s * 4 + jl2) * 4 + 3) * 64 + n];
                }
                float c = g_c2[j2 * 64 + n];
                c = sigf(gf) * c + sigf(gi) * tanhf(gg);
                float h = sigf(go) * tanhf(c);
                g_c2[j2 * 64 + n] = c;
                __stcg(&g_x2[nxt][(512 + j2) * 64 + n], h);
            }
            __syncthreads();
            if (tid == 0) st_rel(&g_h2flag[b * 32], h2fb_sm[b] + (unsigned)(step + 1));
        } else {
            const int ub = b - 32;
            int u0, ucnt;
            if (ub < 64) { u0 = ub * 3; ucnt = 3; }
            else         { u0 = 192 + (ub - 64) * 2; ucnt = 2; }
            const int ks = tid >> 6, jl = (tid >> 4) & 3, nqt = tid & 15;
            const float4* __restrict__ h14 = reinterpret_cast<const float4*>(g_h1);
            for (int uu = 0; uu < ucnt; uu++) {
                const int u = u0 + uu;
                const int j0 = (u >> 1) * 4;
                const int k0 = (u & 1) * 256;
                float* dst = (u & 1) ? g_pre1b : g_pre1a;
                const int j = j0 + jl;
                unsigned long long acc[8];
#pragma unroll
                for (int i = 0; i < 8; i++) acc[i] = 0ull;
                for (int kc = 0; kc < 32; kc += 8) {
                    float4 xv[8];
#pragma unroll
                    for (int i = 0; i < 8; i++)
                        xv[i] = __ldcg(&h14[(k0 + ks * 32 + kc + i) * 16 + nqt]);
#pragma unroll
                    for (int i = 0; i < 8; i++) {
                        const int k = k0 + ks * 32 + kc + i;
                        const float4 w4 = *reinterpret_cast<const float4*>(&g_W1h[((size_t)k * 512 + j) * 4]);
                        const unsigned long long xlo = packf2(xv[i].x, xv[i].y);
                        const unsigned long long xhi = packf2(xv[i].z, xv[i].w);
                        acc[0] = f2fma(packf2(w4.x, w4.x), xlo, acc[0]);
                        acc[1] = f2fma(packf2(w4.x, w4.x), xhi, acc[1]);
                        acc[2] = f2fma(packf2(w4.y, w4.y), xlo, acc[2]);
                        acc[3] = f2fma(packf2(w4.y, w4.y), xhi, acc[3]);
                        acc[4] = f2fma(packf2(w4.z, w4.z), xlo, acc[4]);
                        acc[5] = f2fma(packf2(w4.z, w4.z), xhi, acc[5]);
                        acc[6] = f2fma(packf2(w4.w, w4.w), xlo, acc[6]);
                        acc[7] = f2fma(packf2(w4.w, w4.w), xhi, acc[7]);
                    }
                }
#pragma unroll
                for (int g = 0; g < 4; g++) {
                    float2 lo = *reinterpret_cast<float2*>(&acc[g * 2]);
                    float2 hi = *reinterpret_cast<float2*>(&acc[g * 2 + 1]);
                    *reinterpret_cast<float4*>(&cb[((ks * 4 + jl) * 4 + g) * 64 + nqt * 4]) =
                        make_float4(lo.x, lo.y, hi.x, hi.y);
                }
                __syncthreads();
                if (tid < 256) {
                    const int jl2 = tid >> 6, n = tid & 63;
                    const int j2 = j0 + jl2;
                    float sv[4];
#pragma unroll
                    for (int g = 0; g < 4; g++) {
                        sv[g] = cb[((0 * 4 + jl2) * 4 + g) * 64 + n]
                              + cb[((1 * 4 + jl2) * 4 + g) * 64 + n]
                              + cb[((2 * 4 + jl2) * 4 + g) * 64 + n]
                              + cb[((3 * 4 + jl2) * 4 + g) * 64 + n]
                              + cb[((4 * 4 + jl2) * 4 + g) * 64 + n]
                              + cb[((5 * 4 + jl2) * 4 + g) * 64 + n]
                              + cb[((6 * 4 + jl2) * 4 + g) * 64 + n]
                              + cb[((7 * 4 + jl2) * 4 + g) * 64 + n];
                    }
                    __stcg(reinterpret_cast<float4*>(&dst[((size_t)j2 * 64 + n) * 4]),
                           make_float4(sv[0], sv[1], sv[2], sv[3]));
                }
                __syncthreads();
            }
        }

        // wait for all 32 h2 slices
        if (tid < 32) {
            const unsigned tgt = h2fb_sm[tid] + (unsigned)(step + 1);
            while ((int)(ld_acq(&g_h2flag[tid * 32]) - tgt) < 0) {}
        }
        __syncthreads();

        // ---- attention (balanced item) ----
        {
            const int n = in_;
            const int qa4 = iqa * 4, qb4 = iqb * 4;
            const int len = ilen;

            if (tid < 128) h2s[tid] = __ldcg(&g_x2[nxt][(512 + tid) * 64 + n]);
            __syncthreads();

            const float4* kTn4 = reinterpret_cast<const float4*>(g_keyT + (size_t)n * KD * TS);
            float lmax = -3e38f;
            for (int t = qa4 + tid; t < qb4; t += NTHR) {
                if (t < len) {
                    float a0 = 0.f, a1 = 0.f, a2 = 0.f, a3 = 0.f;
#pragma unroll
                    for (int dq = 0; dq < 32; dq += 8) {
                        float4 kv[8];
#pragma unroll
                        for (int i = 0; i < 8; i++) kv[i] = kTn4[(size_t)(dq + i) * TS + t];
#pragma unroll
                        for (int i = 0; i < 8; i++) {
                            a0 = fmaf(h2s[(dq + i) * 4 + 0], kv[i].x, a0);
                            a1 = fmaf(h2s[(dq + i) * 4 + 1], kv[i].y, a1);
                            a2 = fmaf(h2s[(dq + i) * 4 + 2], kv[i].z, a2);
                            a3 = fmaf(h2s[(dq + i) * 4 + 3], kv[i].w, a3);
                        }
                    }
                    const float acc = (a0 + a1) + (a2 + a3);
                    es[t - qa4] = acc;
                    lmax = fmaxf(lmax, acc);
                }
            }
#pragma unroll
            for (int s = 16; s > 0; s >>= 1) lmax = fmaxf(lmax, __shfl_xor_sync(0xffffffffu, lmax, s));
            if (lane == 0) red[wid] = lmax;
            __syncthreads();
            float mx = red[0];
#pragma unroll
            for (int i = 1; i < 16; i++) mx = fmaxf(mx, red[i]);

            float ps = 0.0f;
            for (int t = qa4 + tid; t < qb4; t += NTHR) {
                float w = 0.0f;
                if (t < len) w = __expf(es[t - qa4] - mx);
                es[t - qa4] = w;
                ps += w;
            }
#pragma unroll
            for (int s = 16; s > 0; s >>= 1) ps += __shfl_xor_sync(0xffffffffu, ps, s);
            __syncthreads();
            if (lane == 0) red[wid] = ps;
            __syncthreads();
            float tot = red[0];
#pragma unroll
            for (int i = 1; i < 16; i++) tot += red[i];
            if (tid == 0) { __stcg(&g_cm[b], mx); __stcg(&g_cs[b], tot); }

            // ctx partials from fp16 values: warp wid handles d = wid + 16r
            {
                const int nq = iqb - iqa;
                const __half* vTh = g_valTh + (size_t)n * KD * TS;
                const float4* es4 = reinterpret_cast<const float4*>(es);
                unsigned long long acc[8];
#pragma unroll
                for (int r = 0; r < 8; r++) acc[r] = 0ull;
                for (int q = lane; q < nq; q += 32) {
                    const float4 e = es4[q];
                    const unsigned long long elo = packf2(e.x, e.y);
                    const unsigned long long ehi = packf2(e.z, e.w);
#pragma unroll
                    for (int r = 0; r < 8; r++) {
                        const __half2* vp = reinterpret_cast<const __half2*>(
                            vTh + (size_t)(wid + 16 * r) * TS + (size_t)(iqa + q) * 4);
                        const float2 v01 = __half22float2(vp[0]);
                        const float2 v23 = __half22float2(vp[1]);
                        acc[r] = f2fma(packf2(v01.x, v01.y), elo, acc[r]);
                        acc[r] = f2fma(packf2(v23.x, v23.y), ehi, acc[r]);
                    }
                }
#pragma unroll
                for (int r = 0; r < 8; r++) {
                    float2 f = *reinterpret_cast<float2*>(&acc[r]);
                    float s = f.x + f.y;
#pragma unroll
                    for (int sh = 16; sh > 0; sh >>= 1) s += __shfl_xor_sync(0xffffffffu, s, sh);
                    if (lane == 0) __stcg(&g_cctx[(size_t)b * 128 + wid + 16 * r], s);
                }
            }
            __syncthreads();
            if (tid == 0) st_rel(&g_cflag[b * 32], fb_self + (unsigned)(step + 1));

            // owner merge + logits (blocks 0..63, sample b)
            if (b < 64) {
                if (tid >= 128 && tid < 256)
                    h2o[tid - 128] = __ldcg(&g_x2[nxt][(512 + tid - 128) * 64 + b]);
                if (tid < pn) {
                    const unsigned tgt = fbase_sm[tid] + (unsigned)(step + 1);
                    while ((int)(ld_acq(&g_cflag[(off + tid) * 32]) - tgt) < 0) {}
                }
                __syncthreads();
                if (tid < pn) {
                    sm_m[tid] = __ldcg(&g_cm[off + tid]);
                    sm_s[tid] = __ldcg(&g_cs[off + tid]);
                }
                __syncthreads();
                if (tid < 32) {
                    float M = -3e38f;
                    for (int i = tid; i < pn; i += 32) M = fmaxf(M, sm_m[i]);
#pragma unroll
                    for (int s = 16; s > 0; s >>= 1) M = fmaxf(M, __shfl_xor_sync(0xffffffffu, M, s));
                    float S = 0.0f;
                    for (int i = tid; i < pn; i += 32) {
                        float w = __expf(sm_m[i] - M);
                        sm_m[i] = w;
                        S += w * sm_s[i];
                    }
#pragma unroll
                    for (int s = 16; s > 0; s >>= 1) S += __shfl_xor_sync(0xffffffffu, S, s);
                    if (tid == 0) sred = 1.0f / S;
                }
                __syncthreads();
                if (tid < 128) {
                    float acc = 0.0f;
                    int i = 0;
                    for (; i + 8 <= pn; i += 8) {
                        float p[8];
#pragma unroll
                        for (int r = 0; r < 8; r++)
                            p[r] = __ldcg(&g_cctx[(size_t)(off + i + r) * 128 + tid]);
#pragma unroll
                        for (int r = 0; r < 8; r++) acc += sm_m[i + r] * p[r];
                    }
                    for (; i < pn; i++)
                        acc += sm_m[i] * __ldcg(&g_cctx[(size_t)(off + i) * 128 + tid]);
                    const float cx = acc * sred;
                    ctxs[tid] = cx;
                    __stcg(&g_x1[nxt][tid * 64 + b], cx);
                }
                __syncthreads();
                {
                    const float4 h0 = *reinterpret_cast<const float4*>(&h2o[lane * 4]);
                    const float4 c0 = *reinterpret_cast<const float4*>(&ctxs[lane * 4]);
                    for (int v = wid; v < V_V; v += 16) {
                        const float4* er = reinterpret_cast<const float4*>(emb + (size_t)v * E_E);
                        const float4 e0 = er[lane], e1 = er[lane + 32];
                        float d = e0.x * h0.x + e0.y * h0.y + e0.z * h0.z + e0.w * h0.w
                                + e1.x * c0.x + e1.y * c0.y + e1.z * c0.z + e1.w * c0.w;
#pragma unroll
                        for (int s = 16; s > 0; s >>= 1) d += __shfl_xor_sync(0xffffffffu, d, s);
                        if (lane == 0) out[((size_t)b * L_L + step) * V_V + v] = d + bout[v];
                    }
                }
            }
        }
        gridbar(bs);
    }
}

extern "C" void kernel_launch(void* const* d_in, const int* in_sizes, int n_in,
                              void* d_out, int out_size) {
    mega<<<NBLK, NTHR>>>(
        (const float*)d_in[0], (const float*)d_in[1], (const int*)d_in[2],
        (const int*)d_in[3], (const float*)d_in[4], (const float*)d_in[5],
        (const float*)d_in[6], (const float*)d_in[7], (const float*)d_in[8],
        (const float*)d_in[9], (const float*)d_in[10], (const float*)d_in[11],
        (const float*)d_in[12], (const float*)d_in[13], (float*)d_out);
}

// round 16
// speedup vs baseline: 1.8796x; 1.1339x over previous
#include <cuda_runtime.h>
#include <cuda_fp16.h>
#include <cstdint>
#include <cstddef>

// Problem: V=35, E=256, H=512, K=128, VS=128, N=64, T=2000, L=300, START=33
#define NBLK 128
#define NTHR 512

#define N_B   64
#define T_T   2000
#define TS    2048
#define T4S   512
#define L_L   300
#define E_E   256
#define H_H   512
#define KD    128
#define V_V   35
#define K2    640
#define START_TOK 33

// ---------------- device scratch ----------------
// keys: interleaved [n][dq=d/4][t][4] fp32  (one float4 = 4 d's at fixed t)
__device__ __align__(16) float  g_keyT[(size_t)N_B * KD * TS];
__device__ __align__(16) __half g_valTh[(size_t)N_B * KD * TS]; // [n][d][t] fp16
__device__ __align__(16) float g_W1c[128 * H_H * 4];
__device__ __align__(16) float g_W1h[512 * H_H * 4];
__device__ __align__(16) float g_W2q[K2 * KD * 4];
__device__ __align__(16) float g_embW1[V_V * H_H * 4];
__device__ __align__(16) float g_b2[KD * 4];
__device__ __align__(16) float g_pre1a[H_H * N_B * 4];          // [(j*64+n)*4+g]
__device__ __align__(16) float g_pre1b[H_H * N_B * 4];
__device__ __align__(16) float g_x1[2][128 * N_B];              // merged ctx [buf][k][n]
__device__ __align__(16) float g_h1[H_H * N_B];
__device__ __align__(16) float g_x2[2][K2 * N_B];               // k<512 h1, k>=512 h2
__device__ __align__(16) float g_c1[H_H * N_B];
__device__ __align__(16) float g_c2[KD * N_B];

// flash schedule + partials
__device__ int   g_itemN[NBLK], g_itemQA[NBLK], g_itemQB[NBLK];
__device__ int   g_coff[N_B + 1];
__device__ float g_cm[NBLK], g_cs[NBLK];
__device__ __align__(16) float g_cctx[NBLK * 128];
__device__ unsigned g_cflag[NBLK * 32];      // per-item attention-done flag
__device__ unsigned g_h2flag[32 * 32];       // per-gates2-block h2-ready flag
__device__ unsigned g_h1flag[NBLK * 32];     // per-block h1-ready flag (phase A)
__device__ unsigned g_ctxflag[64 * 32];      // per-owner ctx-ready flag (replaces end gridbar)

__device__ unsigned g_arrive[NBLK * 32];
__device__ unsigned g_release;

__device__ __forceinline__ float sigf(float x) { return 1.0f / (1.0f + __expf(-x)); }

__device__ __forceinline__ unsigned long long packf2(float a, float b) {
    float2 f = make_float2(a, b);
    return *reinterpret_cast<unsigned long long*>(&f);
}
__device__ __forceinline__ unsigned long long f2fma(unsigned long long a,
                                                    unsigned long long b,
                                                    unsigned long long c) {
    unsigned long long d;
    asm("fma.rn.f32x2 %0, %1, %2, %3;" : "=l"(d) : "l"(a), "l"(b), "l"(c));
    return d;
}

// ---------------- replay-safe grid barrier (prep only) ----------------
struct Bar { unsigned gen, s0, r0, sb0, sb1, sb2, sb3; };

__device__ __forceinline__ unsigned ld_rlx(const unsigned* p) {
    unsigned v; asm volatile("ld.relaxed.gpu.u32 %0, [%1];" : "=r"(v) : "l"(p)); return v;
}
__device__ __forceinline__ unsigned ld_acq(const unsigned* p) {
    unsigned v; asm volatile("ld.acquire.gpu.u32 %0, [%1];" : "=r"(v) : "l"(p) : "memory"); return v;
}
__device__ __forceinline__ void st_rel(unsigned* p, unsigned v) {
    asm volatile("st.release.gpu.u32 [%0], %1;" :: "l"(p), "r"(v) : "memory");
}

__device__ __forceinline__ void gridbar(Bar& bs) {
    bs.gen++;
    __syncthreads();
    if (threadIdx.x == 0) st_rel(&g_arrive[blockIdx.x * 32], bs.s0 + bs.gen);
    if (blockIdx.x == 0) {
        if (threadIdx.x < 32) {
            const unsigned t0 = bs.sb0 + bs.gen, t1 = bs.sb1 + bs.gen;
            const unsigned t2 = bs.sb2 + bs.gen, t3 = bs.sb3 + bs.gen;
            for (;;) {
                unsigned v0 = ld_rlx(&g_arrive[(threadIdx.x +  0) * 32]);
                unsigned v1 = ld_rlx(&g_arrive[(threadIdx.x + 32) * 32]);
                unsigned v2 = ld_rlx(&g_arrive[(threadIdx.x + 64) * 32]);
                unsigned v3 = ld_rlx(&g_arrive[(threadIdx.x + 96) * 32]);
                if ((((int)(v0 - t0)) | ((int)(v1 - t1)) |
                     ((int)(v2 - t2)) | ((int)(v3 - t3))) >= 0) break;
            }
            asm volatile("fence.acq_rel.gpu;" ::: "memory");
            __syncwarp();
            if (threadIdx.x == 0) st_rel(&g_release, bs.r0 + bs.gen);
        }
    } else if (threadIdx.x == 0) {
        const unsigned tgt = bs.r0 + bs.gen;
        while ((int)(ld_acq(&g_release) - tgt) < 0) {}
    }
    __syncthreads();
}

__global__ __launch_bounds__(NTHR, 1) void mega(
    const float* __restrict__ key, const float* __restrict__ values,
    const int* __restrict__ lens, const int* __restrict__ text,
    const float* __restrict__ emb,
    const float* __restrict__ Wih1, const float* __restrict__ Whh1,
    const float* __restrict__ bih1, const float* __restrict__ bhh1,
    const float* __restrict__ Wih2, const float* __restrict__ Whh2,
    const float* __restrict__ bih2, const float* __restrict__ bhh2,
    const float* __restrict__ bout, float* __restrict__ out)
{
    __shared__ __align__(16) float cb[8192];        // 32 KB combine / transpose
    __shared__ __align__(16) float es[2048];        // softmax weights
    __shared__ __align__(16) float h2s[128];
    __shared__ __align__(16) float h2o[128];
    __shared__ __align__(16) float ctxs[128];
    __shared__ float red[32];
    __shared__ float sm_m[80], sm_s[80];
    __shared__ unsigned fbase_sm[80];
    __shared__ unsigned h2fb_sm[32];
    __shared__ unsigned h1fb_sm[128];
    __shared__ unsigned ctxfb_sm[64];
    __shared__ float sred;

    const int tid = threadIdx.x;
    const int b = blockIdx.x;
    const int wid = tid >> 5, lane = tid & 31;

    Bar bs; bs.gen = 0; bs.s0 = 0; bs.r0 = 0; bs.sb0 = bs.sb1 = bs.sb2 = bs.sb3 = 0;
    if (tid == 0) { bs.s0 = ld_rlx(&g_arrive[b * 32]); bs.r0 = ld_rlx(&g_release); }
    if (b == 0 && tid < 32) {
        bs.sb0 = ld_rlx(&g_arrive[(tid +  0) * 32]);
        bs.sb1 = ld_rlx(&g_arrive[(tid + 32) * 32]);
        bs.sb2 = ld_rlx(&g_arrive[(tid + 64) * 32]);
        bs.sb3 = ld_rlx(&g_arrive[(tid + 96) * 32]);
    }
    unsigned fb_self = 0;
    if (tid == 0) fb_self = ld_acq(&g_cflag[b * 32]);
    if (tid < 32) h2fb_sm[tid] = ld_acq(&g_h2flag[tid * 32]);
    if (tid < 128) h1fb_sm[tid] = ld_acq(&g_h1flag[tid * 32]);
    if (tid < 64)  ctxfb_sm[tid] = ld_acq(&g_ctxflag[tid * 32]);

    // ======================= PREP =======================
    for (int i = b * NTHR + tid; i < 2 * 128 * N_B; i += NBLK * NTHR) ((float*)g_x1)[i] = 0.0f;
    for (int i = b * NTHR + tid; i < H_H * N_B; i += NBLK * NTHR) g_h1[i] = 0.0f;
    for (int i = b * NTHR + tid; i < 2 * K2 * N_B; i += NBLK * NTHR) ((float*)g_x2)[i] = 0.0f;
    for (int i = b * NTHR + tid; i < H_H * N_B; i += NBLK * NTHR) g_c1[i] = 0.0f;
    for (int i = b * NTHR + tid; i < KD * N_B; i += NBLK * NTHR) g_c2[i] = 0.0f;
    for (int i = b * NTHR + tid; i < H_H * N_B * 4; i += NBLK * NTHR) {
        g_pre1a[i] = 0.0f; g_pre1b[i] = 0.0f;
    }

    if (b == 0 && tid == 0) {   // weighted greedy schedule: 128 items
        int nq[N_B]; int p[N_B];
        for (int n = 0; n < N_B; n++) { nq[n] = (lens[n] + 3) >> 2; p[n] = 1; }
        for (int e = 0; e < 64; e++) {
            int best = 0;
            for (int n = 1; n < N_B; n++)
                if ((long long)nq[n] * p[best] > (long long)nq[best] * p[n]) best = n;
            p[best]++;
        }
        int idx = 0;
        for (int n = 0; n < N_B; n++) {
            g_coff[n] = idx;
            int wpre[66]; int wsum = 0;
            for (int i = 0; i < p[n]; i++) {
                wpre[i] = wsum;
                const int blk = idx + i;
                wsum += (blk < 32) ? 115 : (blk < 96) ? 82 : 103;
            }
            wpre[p[n]] = wsum;
            for (int i = 0; i < p[n]; i++) {
                g_itemN[idx] = n;
                g_itemQA[idx] = (int)((long long)nq[n] * wpre[i] / wsum);
                g_itemQB[idx] = (int)((long long)nq[n] * wpre[i + 1] / wsum);
                idx++;
            }
        }
        g_coff[N_B] = idx;
    }

    for (int idx = b * NTHR + tid; idx < 128 * H_H; idx += NBLK * NTHR) {
        int k = idx / H_H, j = idx % H_H;
        float4 w; float* wp = reinterpret_cast<float*>(&w);
#pragma unroll
        for (int g = 0; g < 4; g++) wp[g] = Wih1[(size_t)(g * H_H + j) * 384 + 256 + k];
        *reinterpret_cast<float4*>(&g_W1c[(size_t)idx * 4]) = w;
    }
    for (int idx = b * NTHR + tid; idx < 512 * H_H; idx += NBLK * NTHR) {
        int k = idx / H_H, j = idx % H_H;
        float4 w; float* wp = reinterpret_cast<float*>(&w);
#pragma unroll
        for (int g = 0; g < 4; g++) wp[g] = Whh1[(size_t)(g * H_H + j) * 512 + k];
        *reinterpret_cast<float4*>(&g_W1h[(size_t)idx * 4]) = w;
    }
    for (int idx = b * NTHR + tid; idx < K2 * KD; idx += NBLK * NTHR) {
        int k = idx / KD, j = idx % KD;
        float4 w; float* wp = reinterpret_cast<float*>(&w);
#pragma unroll
        for (int g = 0; g < 4; g++) {
            int row = g * KD + j;
            wp[g] = (k < 512) ? Wih2[(size_t)row * 512 + k]
                              : Whh2[(size_t)row * 128 + (k - 512)];
        }
        *reinterpret_cast<float4*>(&g_W2q[(size_t)idx * 4]) = w;
    }
    for (int j = b * NTHR + tid; j < KD; j += NBLK * NTHR) {
        float4 w;
        w.x = bih2[j] + bhh2[j];
        w.y = bih2[j + 128] + bhh2[j + 128];
        w.z = bih2[j + 256] + bhh2[j + 256];
        w.w = bih2[j + 384] + bhh2[j + 384];
        *reinterpret_cast<float4*>(&g_b2[j * 4]) = w;
    }
    for (int it = b * 16 + wid; it < V_V * H_H; it += NBLK * 16) {
        int tok = it / H_H, j = it % H_H;
        const float4* e4 = reinterpret_cast<const float4*>(emb + (size_t)tok * E_E);
        float4 ea = e4[lane], eb = e4[lane + 32];
        float a[4];
#pragma unroll
        for (int g = 0; g < 4; g++) {
            const float4* w4 = reinterpret_cast<const float4*>(Wih1 + (size_t)(g * H_H + j) * 384);
            float4 wa = w4[lane], wb = w4[lane + 32];
            a[g] = ea.x * wa.x + ea.y * wa.y + ea.z * wa.z + ea.w * wa.w
                 + eb.x * wb.x + eb.y * wb.y + eb.z * wb.z + eb.w * wb.w;
        }
#pragma unroll
        for (int s = 16; s > 0; s >>= 1) {
#pragma unroll
            for (int g = 0; g < 4; g++) a[g] += __shfl_xor_sync(0xffffffffu, a[g], s);
        }
        if (lane == 0) {
            float4 r;
            r.x = a[0] + bih1[j] + bhh1[j];
            r.y = a[1] + bih1[j + 512] + bhh1[j + 512];
            r.z = a[2] + bih1[j + 1024] + bhh1[j + 1024];
            r.w = a[3] + bih1[j + 1536] + bhh1[j + 1536];
            *reinterpret_cast<float4*>(&g_embW1[(size_t)it * 4]) = r;
        }
    }
    {   // transpose: key fp32 -> interleaved [n][dq][t][4]; values fp16 -> [n][d][t]
        const int tx = tid & 31, ty = tid >> 5;
        for (int tileid = b; tileid < 2 * N_B * 64 * 4; tileid += NBLK) {
            int rem = tileid;
            const bool isval = (rem >= N_B * 64 * 4);
            if (isval) rem -= N_B * 64 * 4;
            const float* src = isval ? values : key;
            int n = rem / (64 * 4);
            int r2 = rem % (64 * 4);
            int t0 = (r2 / 4) * 32, d0 = (r2 % 4) * 32;
            __syncthreads();
#pragma unroll
            for (int r = 0; r < 32; r += 16) {
                int t = t0 + r + ty;
                cb[(r + ty) * 33 + tx] =
                    (t < T_T) ? src[((size_t)n * T_T + t) * KD + d0 + tx] : 0.0f;
            }
            __syncthreads();
            if (isval) {
#pragma unroll
                for (int r = 0; r < 32; r += 16)
                    g_valTh[((size_t)n * KD + d0 + r + ty) * TS + t0 + tx] =
                        __float2half(cb[tx * 33 + (r + ty)]);
            } else {
#pragma unroll
                for (int r = 0; r < 32; r += 16) {
                    const int d = d0 + r + ty;
                    g_keyT[(size_t)n * KD * TS + (size_t)(d >> 2) * (TS * 4)
                           + (size_t)(t0 + tx) * 4 + (d & 3)] = cb[tx * 33 + (r + ty)];
                }
            }
        }
        __syncthreads();
    }

    gridbar(bs);

    const int in_  = g_itemN[b];
    const int iqa  = g_itemQA[b];
    const int iqb  = g_itemQB[b];
    const int ilen = lens[in_];
    int off = 0, pn = 0;
    if (b < 64) {
        off = g_coff[b]; pn = g_coff[b + 1] - off;
        if (tid < pn) fbase_sm[tid] = ld_acq(&g_cflag[(off + tid) * 32]);
    }
    __syncthreads();

    // ======================= MAIN LOOP (flag-dataflow; no gridbar) =======================
    for (int step = 0; step < L_L; step++) {
        const int cur = step & 1, nxt = cur ^ 1;

        // wait for ctx(step-1) from the 64 owners
        if (step > 0) {
            if (tid < 64) {
                const unsigned tgt = ctxfb_sm[tid] + (unsigned)step;
                while ((int)(ld_acq(&g_ctxflag[tid * 32]) - tgt) < 0) {}
            }
            __syncthreads();
        }

        // ---- Phase A: gates1 = embW1 + W1c@ctx (K=128) + pre1a + pre1b; cell1 ----
        {
            const int ks = tid >> 6, jl = (tid >> 4) & 3, nqt = tid & 15;
            const int j = b * 4 + jl;
            const float4* __restrict__ x4 = reinterpret_cast<const float4*>(g_x1[cur]);
            unsigned long long acc[8];
#pragma unroll
            for (int i = 0; i < 8; i++) acc[i] = 0ull;
#pragma unroll
            for (int kc = 0; kc < 16; kc += 8) {
                float4 xv[8];
#pragma unroll
                for (int i = 0; i < 8; i++)
                    xv[i] = __ldcg(&x4[(ks * 16 + kc + i) * 16 + nqt]);
#pragma unroll
                for (int i = 0; i < 8; i++) {
                    const int k = ks * 16 + kc + i;
                    const float4 w4 = *reinterpret_cast<const float4*>(&g_W1c[((size_t)k * 512 + j) * 4]);
                    const unsigned long long xlo = packf2(xv[i].x, xv[i].y);
                    const unsigned long long xhi = packf2(xv[i].z, xv[i].w);
                    acc[0] = f2fma(packf2(w4.x, w4.x), xlo, acc[0]);
                    acc[1] = f2fma(packf2(w4.x, w4.x), xhi, acc[1]);
                    acc[2] = f2fma(packf2(w4.y, w4.y), xlo, acc[2]);
                    acc[3] = f2fma(packf2(w4.y, w4.y), xhi, acc[3]);
                    acc[4] = f2fma(packf2(w4.z, w4.z), xlo, acc[4]);
                    acc[5] = f2fma(packf2(w4.z, w4.z), xhi, acc[5]);
                    acc[6] = f2fma(packf2(w4.w, w4.w), xlo, acc[6]);
                    acc[7] = f2fma(packf2(w4.w, w4.w), xhi, acc[7]);
                }
            }
#pragma unroll
            for (int g = 0; g < 4; g++) {
                float2 lo = *reinterpret_cast<float2*>(&acc[g * 2]);
                float2 hi = *reinterpret_cast<float2*>(&acc[g * 2 + 1]);
                *reinterpret_cast<float4*>(&cb[((ks * 4 + jl) * 4 + g) * 64 + nqt * 4]) =
                    make_float4(lo.x, lo.y, hi.x, hi.y);
            }
            __syncthreads();
            if (tid < 256) {
                const int jl2 = tid >> 6, n = tid & 63;
                const int j2 = b * 4 + jl2;
                const int tok = (step == 0) ? START_TOK : text[n * L_L + step - 1];
                const float4 g0 = *reinterpret_cast<const float4*>(&g_embW1[((size_t)tok * 512 + j2) * 4]);
                const float4 pa = __ldcg(reinterpret_cast<const float4*>(&g_pre1a[((size_t)j2 * 64 + n) * 4]));
                const float4 pb = __ldcg(reinterpret_cast<const float4*>(&g_pre1b[((size_t)j2 * 64 + n) * 4]));
                float gi = g0.x + pa.x + pb.x;
                float gf = g0.y + pa.y + pb.y;
                float gg = g0.z + pa.z + pb.z;
                float go = g0.w + pa.w + pb.w;
#pragma unroll
                for (int s = 0; s < 8; s++) {
                    gi += cb[((s * 4 + jl2) * 4 + 0) * 64 + n];
                    gf += cb[((s * 4 + jl2) * 4 + 1) * 64 + n];
                    gg += cb[((s * 4 + jl2) * 4 + 2) * 64 + n];
                    go += cb[((s * 4 + jl2) * 4 + 3) * 64 + n];
                }
                float c = g_c1[j2 * 64 + n];
                c = sigf(gf) * c + sigf(gi) * tanhf(gg);
                float h = sigf(go) * tanhf(c);
                g_c1[j2 * 64 + n] = c;
                __stcg(&g_h1[j2 * 64 + n], h);
                __stcg(&g_x2[cur][j2 * 64 + n], h);
            }
        }
        // publish h1 flag; decentralized wait
        __syncthreads();
        if (tid == 0) st_rel(&g_h1flag[b * 32], h1fb_sm[b] + (unsigned)(step + 1));
        if (tid < 128) {
            const unsigned tgt = h1fb_sm[tid] + (unsigned)(step + 1);
            while ((int)(ld_acq(&g_h1flag[tid * 32]) - tgt) < 0) {}
        }
        __syncthreads();

        // ---- Phase BC: gates2/pre1, then h2-flag-synced attention + merge + logits ----
        if (b < 32) {
            const int ks = tid >> 6, jl = (tid >> 4) & 3, nqt = tid & 15;
            const int j = b * 4 + jl;
            const float4* __restrict__ x4 = reinterpret_cast<const float4*>(g_x2[cur]);
            unsigned long long acc[8];
#pragma unroll
            for (int i = 0; i < 8; i++) acc[i] = 0ull;
            for (int kc = 0; kc < 80; kc += 8) {
                float4 xv[8];
#pragma unroll
                for (int i = 0; i < 8; i++)
                    xv[i] = __ldcg(&x4[(ks * 80 + kc + i) * 16 + nqt]);
#pragma unroll
                for (int i = 0; i < 8; i++) {
                    const int k = ks * 80 + kc + i;
                    const float4 w4 = *reinterpret_cast<const float4*>(&g_W2q[((size_t)k * 128 + j) * 4]);
                    const unsigned long long xlo = packf2(xv[i].x, xv[i].y);
                    const unsigned long long xhi = packf2(xv[i].z, xv[i].w);
                    acc[0] = f2fma(packf2(w4.x, w4.x), xlo, acc[0]);
                    acc[1] = f2fma(packf2(w4.x, w4.x), xhi, acc[1]);
                    acc[2] = f2fma(packf2(w4.y, w4.y), xlo, acc[2]);
                    acc[3] = f2fma(packf2(w4.y, w4.y), xhi, acc[3]);
                    acc[4] = f2fma(packf2(w4.z, w4.z), xlo, acc[4]);
                    acc[5] = f2fma(packf2(w4.z, w4.z), xhi, acc[5]);
                    acc[6] = f2fma(packf2(w4.w, w4.w), xlo, acc[6]);
                    acc[7] = f2fma(packf2(w4.w, w4.w), xhi, acc[7]);
                }
            }
#pragma unroll
            for (int g = 0; g < 4; g++) {
                float2 lo = *reinterpret_cast<float2*>(&acc[g * 2]);
                float2 hi = *reinterpret_cast<float2*>(&acc[g * 2 + 1]);
                *reinterpret_cast<float4*>(&cb[((ks * 4 + jl) * 4 + g) * 64 + nqt * 4]) =
                    make_float4(lo.x, lo.y, hi.x, hi.y);
            }
            __syncthreads();
            if (tid < 256) {
                const int jl2 = tid >> 6, n = tid & 63;
                const int j2 = b * 4 + jl2;
                const float4 bb = *reinterpret_cast<const float4*>(&g_b2[j2 * 4]);
                float gi = bb.x, gf = bb.y, gg = bb.z, go = bb.w;
#pragma unroll
                for (int s = 0; s < 8; s++) {
                    gi += cb[((s * 4 + jl2) * 4 + 0) * 64 + n];
                    gf += cb[((s * 4 + jl2) * 4 + 1) * 64 + n];
                    gg += cb[((s * 4 + jl2) * 4 + 2) * 64 + n];
                    go += cb[((s * 4 + jl2) * 4 + 3) * 64 + n];
                }
                float c = g_c2[j2 * 64 + n];
                c = sigf(gf) * c + sigf(gi) * tanhf(gg);
                float h = sigf(go) * tanhf(c);
                g_c2[j2 * 64 + n] = c;
                __stcg(&g_x2[nxt][(512 + j2) * 64 + n], h);
            }
            __syncthreads();
            if (tid == 0) st_rel(&g_h2flag[b * 32], h2fb_sm[b] + (unsigned)(step + 1));
        } else {
            const int ub = b - 32;
            int u0, ucnt;
            if (ub < 64) { u0 = ub * 3; ucnt = 3; }
            else         { u0 = 192 + (ub - 64) * 2; ucnt = 2; }
            const int ks = tid >> 6, jl = (tid >> 4) & 3, nqt = tid & 15;
            const float4* __restrict__ h14 = reinterpret_cast<const float4*>(g_h1);
            for (int uu = 0; uu < ucnt; uu++) {
                const int u = u0 + uu;
                const int j0 = (u >> 1) * 4;
                const int k0 = (u & 1) * 256;
                float* dst = (u & 1) ? g_pre1b : g_pre1a;
                const int j = j0 + jl;
                unsigned long long acc[8];
#pragma unroll
                for (int i = 0; i < 8; i++) acc[i] = 0ull;
                for (int kc = 0; kc < 32; kc += 8) {
                    float4 xv[8];
#pragma unroll
                    for (int i = 0; i < 8; i++)
                        xv[i] = __ldcg(&h14[(k0 + ks * 32 + kc + i) * 16 + nqt]);
#pragma unroll
                    for (int i = 0; i < 8; i++) {
                        const int k = k0 + ks * 32 + kc + i;
                        const float4 w4 = *reinterpret_cast<const float4*>(&g_W1h[((size_t)k * 512 + j) * 4]);
                        const unsigned long long xlo = packf2(xv[i].x, xv[i].y);
                        const unsigned long long xhi = packf2(xv[i].z, xv[i].w);
                        acc[0] = f2fma(packf2(w4.x, w4.x), xlo, acc[0]);
                        acc[1] = f2fma(packf2(w4.x, w4.x), xhi, acc[1]);
                        acc[2] = f2fma(packf2(w4.y, w4.y), xlo, acc[2]);
                        acc[3] = f2fma(packf2(w4.y, w4.y), xhi, acc[3]);
                        acc[4] = f2fma(packf2(w4.z, w4.z), xlo, acc[4]);
                        acc[5] = f2fma(packf2(w4.z, w4.z), xhi, acc[5]);
                        acc[6] = f2fma(packf2(w4.w, w4.w), xlo, acc[6]);
                        acc[7] = f2fma(packf2(w4.w, w4.w), xhi, acc[7]);
                    }
                }
#pragma unroll
                for (int g = 0; g < 4; g++) {
                    float2 lo = *reinterpret_cast<float2*>(&acc[g * 2]);
                    float2 hi = *reinterpret_cast<float2*>(&acc[g * 2 + 1]);
                    *reinterpret_cast<float4*>(&cb[((ks * 4 + jl) * 4 + g) * 64 + nqt * 4]) =
                        make_float4(lo.x, lo.y, hi.x, hi.y);
                }
                __syncthreads();
                if (tid < 256) {
                    const int jl2 = tid >> 6, n = tid & 63;
                    const int j2 = j0 + jl2;
                    float sv[4];
#pragma unroll
                    for (int g = 0; g < 4; g++) {
                        sv[g] = cb[((0 * 4 + jl2) * 4 + g) * 64 + n]
                              + cb[((1 * 4 + jl2) * 4 + g) * 64 + n]
                              + cb[((2 * 4 + jl2) * 4 + g) * 64 + n]
                              + cb[((3 * 4 + jl2) * 4 + g) * 64 + n]
                              + cb[((4 * 4 + jl2) * 4 + g) * 64 + n]
                              + cb[((5 * 4 + jl2) * 4 + g) * 64 + n]
                              + cb[((6 * 4 + jl2) * 4 + g) * 64 + n]
                              + cb[((7 * 4 + jl2) * 4 + g) * 64 + n];
                    }
                    __stcg(reinterpret_cast<float4*>(&dst[((size_t)j2 * 64 + n) * 4]),
                           make_float4(sv[0], sv[1], sv[2], sv[3]));
                }
                __syncthreads();
            }
        }

        // wait for all 32 h2 slices
        if (tid < 32) {
            const unsigned tgt = h2fb_sm[tid] + (unsigned)(step + 1);
            while ((int)(ld_acq(&g_h2flag[tid * 32]) - tgt) < 0) {}
        }
        __syncthreads();

        // ---- attention (balanced item) ----
        {
            const int n = in_;
            const int qa4 = iqa * 4, qb4 = iqb * 4;
            const int len = ilen;

            if (tid < 128) h2s[tid] = __ldcg(&g_x2[nxt][(512 + tid) * 64 + n]);
            __syncthreads();

            const float4* kTn4 = reinterpret_cast<const float4*>(g_keyT + (size_t)n * KD * TS);
            float lmax = -3e38f;
            for (int t = qa4 + tid; t < qb4; t += NTHR) {
                if (t < len) {
                    float a0 = 0.f, a1 = 0.f, a2 = 0.f, a3 = 0.f;
#pragma unroll
                    for (int dq = 0; dq < 32; dq += 8) {
                        float4 kv[8];
#pragma unroll
                        for (int i = 0; i < 8; i++) kv[i] = kTn4[(size_t)(dq + i) * TS + t];
#pragma unroll
                        for (int i = 0; i < 8; i++) {
                            a0 = fmaf(h2s[(dq + i) * 4 + 0], kv[i].x, a0);
                            a1 = fmaf(h2s[(dq + i) * 4 + 1], kv[i].y, a1);
                            a2 = fmaf(h2s[(dq + i) * 4 + 2], kv[i].z, a2);
                            a3 = fmaf(h2s[(dq + i) * 4 + 3], kv[i].w, a3);
                        }
                    }
                    const float acc = (a0 + a1) + (a2 + a3);
                    es[t - qa4] = acc;
                    lmax = fmaxf(lmax, acc);
                }
            }
#pragma unroll
            for (int s = 16; s > 0; s >>= 1) lmax = fmaxf(lmax, __shfl_xor_sync(0xffffffffu, lmax, s));
            if (lane == 0) red[wid] = lmax;
            __syncthreads();
            float mx = red[0];
#pragma unroll
            for (int i = 1; i < 16; i++) mx = fmaxf(mx, red[i]);

            float ps = 0.0f;
            for (int t = qa4 + tid; t < qb4; t += NTHR) {
                float w = 0.0f;
                if (t < len) w = __expf(es[t - qa4] - mx);
                es[t - qa4] = w;
                ps += w;
            }
#pragma unroll
            for (int s = 16; s > 0; s >>= 1) ps += __shfl_xor_sync(0xffffffffu, ps, s);
            __syncthreads();
            if (lane == 0) red[wid] = ps;
            __syncthreads();
            float tot = red[0];
#pragma unroll
            for (int i = 1; i < 16; i++) tot += red[i];
            if (tid == 0) { __stcg(&g_cm[b], mx); __stcg(&g_cs[b], tot); }

            // ctx partials from fp16 values: warp wid handles d = wid + 16r
            {
                const int nq = iqb - iqa;
                const __half* vTh = g_valTh + (size_t)n * KD * TS;
                const float4* es4 = reinterpret_cast<const float4*>(es);
                unsigned long long acc[8];
#pragma unroll
                for (int r = 0; r < 8; r++) acc[r] = 0ull;
                for (int q = lane; q < nq; q += 32) {
                    const float4 e = es4[q];
                    const unsigned long long elo = packf2(e.x, e.y);
                    const unsigned long long ehi = packf2(e.z, e.w);
#pragma unroll
                    for (int r = 0; r < 8; r++) {
                        const __half2* vp = reinterpret_cast<const __half2*>(
                            vTh + (size_t)(wid + 16 * r) * TS + (size_t)(iqa + q) * 4);
                        const float2 v01 = __half22float2(vp[0]);
                        const float2 v23 = __half22float2(vp[1]);
                        acc[r] = f2fma(packf2(v01.x, v01.y), elo, acc[r]);
                        acc[r] = f2fma(packf2(v23.x, v23.y), ehi, acc[r]);
                    }
                }
#pragma unroll
                for (int r = 0; r < 8; r++) {
                    float2 f = *reinterpret_cast<float2*>(&acc[r]);
                    float s = f.x + f.y;
#pragma unroll
                    for (int sh = 16; sh > 0; sh >>= 1) s += __shfl_xor_sync(0xffffffffu, s, sh);
                    if (lane == 0) __stcg(&g_cctx[(size_t)b * 128 + wid + 16 * r], s);
                }
            }
            __syncthreads();
            if (tid == 0) st_rel(&g_cflag[b * 32], fb_self + (unsigned)(step + 1));

            // owner merge + ctx publish + logits (blocks 0..63, sample b)
            if (b < 64) {
                if (tid >= 128 && tid < 256)
                    h2o[tid - 128] = __ldcg(&g_x2[nxt][(512 + tid - 128) * 64 + b]);
                if (tid < pn) {
                    const unsigned tgt = fbase_sm[tid] + (unsigned)(step + 1);
                    while ((int)(ld_acq(&g_cflag[(off + tid) * 32]) - tgt) < 0) {}
                }
                __syncthreads();
                if (tid < pn) {
                    sm_m[tid] = __ldcg(&g_cm[off + tid]);
                    sm_s[tid] = __ldcg(&g_cs[off + tid]);
                }
                __syncthreads();
                if (tid < 32) {
                    float M = -3e38f;
                    for (int i = tid; i < pn; i += 32) M = fmaxf(M, sm_m[i]);
#pragma unroll
                    for (int s = 16; s > 0; s >>= 1) M = fmaxf(M, __shfl_xor_sync(0xffffffffu, M, s));
                    float S = 0.0f;
                    for (int i = tid; i < pn; i += 32) {
                        float w = __expf(sm_m[i] - M);
                        sm_m[i] = w;
                        S += w * sm_s[i];
                    }
#pragma unroll
                    for (int s = 16; s > 0; s >>= 1) S += __shfl_xor_sync(0xffffffffu, S, s);
                    if (tid == 0) sred = 1.0f / S;
                }
                __syncthreads();
                if (tid < 128) {
                    float acc = 0.0f;
                    int i = 0;
                    for (; i + 8 <= pn; i += 8) {
                        float p[8];
#pragma unroll
                        for (int r = 0; r < 8; r++)
                            p[r] = __ldcg(&g_cctx[(size_t)(off + i + r) * 128 + tid]);
#pragma unroll
                        for (int r = 0; r < 8; r++) acc += sm_m[i + r] * p[r];
                    }
                    for (; i < pn; i++)
                        acc += sm_m[i] * __ldcg(&g_cctx[(size_t)(off + i) * 128 + tid]);
                    const float cx = acc * sred;
                    ctxs[tid] = cx;
                    __stcg(&g_x1[nxt][tid * 64 + b], cx);
                }
                __syncthreads();
                // publish ctx-ready BEFORE logits so other blocks enter A(step+1)
                if (tid == 0) st_rel(&g_ctxflag[b * 32], ctxfb_sm[b] + (unsigned)(step + 1));
                {
                    const float4 h0 = *reinterpret_cast<const float4*>(&h2o[lane * 4]);
                    const float4 c0 = *reinterpret_cast<const float4*>(&ctxs[lane * 4]);
                    for (int v = wid; v < V_V; v += 16) {
                        const float4* er = reinterpret_cast<const float4*>(emb + (size_t)v * E_E);
                        const float4 e0 = er[lane], e1 = er[lane + 32];
                        float d = e0.x * h0.x + e0.y * h0.y + e0.z * h0.z + e0.w * h0.w
                                + e1.x * c0.x + e1.y * c0.y + e1.z * c0.z + e1.w * c0.w;
#pragma unroll
                        for (int s = 16; s > 0; s >>= 1) d += __shfl_xor_sync(0xffffffffu, d, s);
                        if (lane == 0) out[((size_t)b * L_L + step) * V_V + v] = d + bout[v];
                    }
                }
            }
        }
    }
}

extern "C" void kernel_launch(void* const* d_in, const int* in_sizes, int n_in,
                              void* d_out, int out_size) {
    mega<<<NBLK, NTHR>>>(
        (const float*)d_in[0], (const float*)d_in[1], (const int*)d_in[2],
        (const int*)d_in[3], (const float*)d_in[4], (const float*)d_in[5],
        (const float*)d_in[6], (const float*)d_in[7], (const float*)d_in[8],
        (const float*)d_in[9], (const float*)d_in[10], (const float*)d_in[11],
        (const float*)d_in[12], (const float*)d_in[13], (float*)d_out);
}

// round 17
// speedup vs baseline: 1.9833x; 1.0551x over previous
#include <cuda_runtime.h>
#include <cuda_fp16.h>
#include <cstdint>
#include <cstddef>

// Problem: V=35, E=256, H=512, K=128, VS=128, N=64, T=2000, L=300, START=33
#define NBLK 128
#define NTHR 512

#define N_B   64
#define T_T   2000
#define TS    2048
#define T4S   512
#define L_L   300
#define E_E   256
#define H_H   512
#define KD    128
#define V_V   35
#define K2    640
#define START_TOK 33

// ---------------- device scratch ----------------
// keys: interleaved [n][dq=d/4][t][4] fp32  (one float4 = 4 d's at fixed t)
__device__ __align__(16) float  g_keyT[(size_t)N_B * KD * TS];
__device__ __align__(16) __half g_valTh[(size_t)N_B * KD * TS]; // [n][d][t] fp16
__device__ __align__(16) float g_W1c[128 * H_H * 4];
__device__ __align__(16) float g_W1h[512 * H_H * 4];
__device__ __align__(16) float g_W2q[K2 * KD * 4];
__device__ __align__(16) float g_embW1[V_V * H_H * 4];
__device__ __align__(16) float g_b2[KD * 4];
__device__ __align__(16) float g_pre1a[H_H * N_B * 4];          // [(j*64+n)*4+g]
__device__ __align__(16) float g_pre1b[H_H * N_B * 4];
__device__ __align__(16) float g_x1[2][128 * N_B];              // merged ctx [buf][k][n]
__device__ __align__(16) float g_h1[H_H * N_B];
__device__ __align__(16) float g_x2[2][K2 * N_B];               // k<512 h1, k>=512 h2
__device__ __align__(16) float g_c1[H_H * N_B];
__device__ __align__(16) float g_c2[KD * N_B];

// flash schedule + partials
__device__ int   g_itemN[NBLK], g_itemQA[NBLK], g_itemQB[NBLK];
__device__ int   g_coff[N_B + 1];
__device__ float g_cm[NBLK], g_cs[NBLK];
__device__ __align__(16) float g_cctx[NBLK * 128];
__device__ unsigned g_cflag[NBLK * 32];      // per-item attention-done flag
__device__ unsigned g_h2flag[32 * 32];       // per-gates2-block h2-ready flag
__device__ unsigned g_h1flag[NBLK * 32];     // per-block h1-ready flag (phase A)
__device__ unsigned g_ctxflag[64 * 32];      // per-owner ctx-ready flag

__device__ unsigned g_arrive[NBLK * 32];
__device__ unsigned g_release;

__device__ __forceinline__ float sigf(float x) { return 1.0f / (1.0f + __expf(-x)); }

__device__ __forceinline__ unsigned long long packf2(float a, float b) {
    float2 f = make_float2(a, b);
    return *reinterpret_cast<unsigned long long*>(&f);
}
__device__ __forceinline__ unsigned long long f2fma(unsigned long long a,
                                                    unsigned long long b,
                                                    unsigned long long c) {
    unsigned long long d;
    asm("fma.rn.f32x2 %0, %1, %2, %3;" : "=l"(d) : "l"(a), "l"(b), "l"(c));
    return d;
}

// ---------------- replay-safe grid barrier (prep only) ----------------
struct Bar { unsigned gen, s0, r0, sb0, sb1, sb2, sb3; };

__device__ __forceinline__ unsigned ld_rlx(const unsigned* p) {
    unsigned v; asm volatile("ld.relaxed.gpu.u32 %0, [%1];" : "=r"(v) : "l"(p)); return v;
}
__device__ __forceinline__ unsigned ld_acq(const unsigned* p) {
    unsigned v; asm volatile("ld.acquire.gpu.u32 %0, [%1];" : "=r"(v) : "l"(p) : "memory"); return v;
}
__device__ __forceinline__ void st_rel(unsigned* p, unsigned v) {
    asm volatile("st.release.gpu.u32 [%0], %1;" :: "l"(p), "r"(v) : "memory");
}

__device__ __forceinline__ void gridbar(Bar& bs) {
    bs.gen++;
    __syncthreads();
    if (threadIdx.x == 0) st_rel(&g_arrive[blockIdx.x * 32], bs.s0 + bs.gen);
    if (blockIdx.x == 0) {
        if (threadIdx.x < 32) {
            const unsigned t0 = bs.sb0 + bs.gen, t1 = bs.sb1 + bs.gen;
            const unsigned t2 = bs.sb2 + bs.gen, t3 = bs.sb3 + bs.gen;
            for (;;) {
                unsigned v0 = ld_rlx(&g_arrive[(threadIdx.x +  0) * 32]);
                unsigned v1 = ld_rlx(&g_arrive[(threadIdx.x + 32) * 32]);
                unsigned v2 = ld_rlx(&g_arrive[(threadIdx.x + 64) * 32]);
                unsigned v3 = ld_rlx(&g_arrive[(threadIdx.x + 96) * 32]);
                if ((((int)(v0 - t0)) | ((int)(v1 - t1)) |
                     ((int)(v2 - t2)) | ((int)(v3 - t3))) >= 0) break;
            }
            asm volatile("fence.acq_rel.gpu;" ::: "memory");
            __syncwarp();
            if (threadIdx.x == 0) st_rel(&g_release, bs.r0 + bs.gen);
        }
    } else if (threadIdx.x == 0) {
        const unsigned tgt = bs.r0 + bs.gen;
        while ((int)(ld_acq(&g_release) - tgt) < 0) {}
    }
    __syncthreads();
}

__global__ __launch_bounds__(NTHR, 1) void mega(
    const float* __restrict__ key, const float* __restrict__ values,
    const int* __restrict__ lens, const int* __restrict__ text,
    const float* __restrict__ emb,
    const float* __restrict__ Wih1, const float* __restrict__ Whh1,
    const float* __restrict__ bih1, const float* __restrict__ bhh1,
    const float* __restrict__ Wih2, const float* __restrict__ Whh2,
    const float* __restrict__ bih2, const float* __restrict__ bhh2,
    const float* __restrict__ bout, float* __restrict__ out)
{
    __shared__ __align__(16) float cb[8192];        // 32 KB combine / transpose
    __shared__ __align__(16) float es[2048];        // softmax weights
    __shared__ __align__(16) float h2s[128];
    __shared__ __align__(16) float h2o[128];
    __shared__ __align__(16) float ctxs[128];
    __shared__ float red[32];
    __shared__ float sm_m[80], sm_s[80];
    __shared__ unsigned fbase_sm[80];
    __shared__ unsigned h2fb_sm[32];
    __shared__ unsigned h1fb_sm[128];
    __shared__ unsigned ctxfb_sm[64];
    __shared__ float sred;

    const int tid = threadIdx.x;
    const int b = blockIdx.x;
    const int wid = tid >> 5, lane = tid & 31;

    Bar bs; bs.gen = 0; bs.s0 = 0; bs.r0 = 0; bs.sb0 = bs.sb1 = bs.sb2 = bs.sb3 = 0;
    if (tid == 0) { bs.s0 = ld_rlx(&g_arrive[b * 32]); bs.r0 = ld_rlx(&g_release); }
    if (b == 0 && tid < 32) {
        bs.sb0 = ld_rlx(&g_arrive[(tid +  0) * 32]);
        bs.sb1 = ld_rlx(&g_arrive[(tid + 32) * 32]);
        bs.sb2 = ld_rlx(&g_arrive[(tid + 64) * 32]);
        bs.sb3 = ld_rlx(&g_arrive[(tid + 96) * 32]);
    }
    unsigned fb_self = 0;
    if (tid == 0) fb_self = ld_acq(&g_cflag[b * 32]);
    if (tid < 32) h2fb_sm[tid] = ld_acq(&g_h2flag[tid * 32]);
    if (tid < 128) h1fb_sm[tid] = ld_acq(&g_h1flag[tid * 32]);
    if (tid < 64)  ctxfb_sm[tid] = ld_acq(&g_ctxflag[tid * 32]);

    // ======================= PREP =======================
    for (int i = b * NTHR + tid; i < 2 * 128 * N_B; i += NBLK * NTHR) ((float*)g_x1)[i] = 0.0f;
    for (int i = b * NTHR + tid; i < H_H * N_B; i += NBLK * NTHR) g_h1[i] = 0.0f;
    for (int i = b * NTHR + tid; i < 2 * K2 * N_B; i += NBLK * NTHR) ((float*)g_x2)[i] = 0.0f;
    for (int i = b * NTHR + tid; i < H_H * N_B; i += NBLK * NTHR) g_c1[i] = 0.0f;
    for (int i = b * NTHR + tid; i < KD * N_B; i += NBLK * NTHR) g_c2[i] = 0.0f;
    for (int i = b * NTHR + tid; i < H_H * N_B * 4; i += NBLK * NTHR) {
        g_pre1a[i] = 0.0f; g_pre1b[i] = 0.0f;
    }

    if (b == 0 && tid == 0) {   // weighted greedy schedule: 128 items
        int nq[N_B]; int p[N_B];
        for (int n = 0; n < N_B; n++) { nq[n] = (lens[n] + 3) >> 2; p[n] = 1; }
        for (int e = 0; e < 64; e++) {
            int best = 0;
            for (int n = 1; n < N_B; n++)
                if ((long long)nq[n] * p[best] > (long long)nq[best] * p[n]) best = n;
            p[best]++;
        }
        int idx = 0;
        for (int n = 0; n < N_B; n++) {
            g_coff[n] = idx;
            int wpre[66]; int wsum = 0;
            for (int i = 0; i < p[n]; i++) {
                wpre[i] = wsum;
                const int blk = idx + i;
                wsum += (blk < 32) ? 115 : (blk < 96) ? 82 : 103;
            }
            wpre[p[n]] = wsum;
            for (int i = 0; i < p[n]; i++) {
                g_itemN[idx] = n;
                g_itemQA[idx] = (int)((long long)nq[n] * wpre[i] / wsum);
                g_itemQB[idx] = (int)((long long)nq[n] * wpre[i + 1] / wsum);
                idx++;
            }
        }
        g_coff[N_B] = idx;
    }

    for (int idx = b * NTHR + tid; idx < 128 * H_H; idx += NBLK * NTHR) {
        int k = idx / H_H, j = idx % H_H;
        float4 w; float* wp = reinterpret_cast<float*>(&w);
#pragma unroll
        for (int g = 0; g < 4; g++) wp[g] = Wih1[(size_t)(g * H_H + j) * 384 + 256 + k];
        *reinterpret_cast<float4*>(&g_W1c[(size_t)idx * 4]) = w;
    }
    for (int idx = b * NTHR + tid; idx < 512 * H_H; idx += NBLK * NTHR) {
        int k = idx / H_H, j = idx % H_H;
        float4 w; float* wp = reinterpret_cast<float*>(&w);
#pragma unroll
        for (int g = 0; g < 4; g++) wp[g] = Whh1[(size_t)(g * H_H + j) * 512 + k];
        *reinterpret_cast<float4*>(&g_W1h[(size_t)idx * 4]) = w;
    }
    for (int idx = b * NTHR + tid; idx < K2 * KD; idx += NBLK * NTHR) {
        int k = idx / KD, j = idx % KD;
        float4 w; float* wp = reinterpret_cast<float*>(&w);
#pragma unroll
        for (int g = 0; g < 4; g++) {
            int row = g * KD + j;
            wp[g] = (k < 512) ? Wih2[(size_t)row * 512 + k]
                              : Whh2[(size_t)row * 128 + (k - 512)];
        }
        *reinterpret_cast<float4*>(&g_W2q[(size_t)idx * 4]) = w;
    }
    for (int j = b * NTHR + tid; j < KD; j += NBLK * NTHR) {
        float4 w;
        w.x = bih2[j] + bhh2[j];
        w.y = bih2[j + 128] + bhh2[j + 128];
        w.z = bih2[j + 256] + bhh2[j + 256];
        w.w = bih2[j + 384] + bhh2[j + 384];
        *reinterpret_cast<float4*>(&g_b2[j * 4]) = w;
    }
    for (int it = b * 16 + wid; it < V_V * H_H; it += NBLK * 16) {
        int tok = it / H_H, j = it % H_H;
        const float4* e4 = reinterpret_cast<const float4*>(emb + (size_t)tok * E_E);
        float4 ea = e4[lane], eb = e4[lane + 32];
        float a[4];
#pragma unroll
        for (int g = 0; g < 4; g++) {
            const float4* w4 = reinterpret_cast<const float4*>(Wih1 + (size_t)(g * H_H + j) * 384);
            float4 wa = w4[lane], wb = w4[lane + 32];
            a[g] = ea.x * wa.x + ea.y * wa.y + ea.z * wa.z + ea.w * wa.w
                 + eb.x * wb.x + eb.y * wb.y + eb.z * wb.z + eb.w * wb.w;
        }
#pragma unroll
        for (int s = 16; s > 0; s >>= 1) {
#pragma unroll
            for (int g = 0; g < 4; g++) a[g] += __shfl_xor_sync(0xffffffffu, a[g], s);
        }
        if (lane == 0) {
            float4 r;
            r.x = a[0] + bih1[j] + bhh1[j];
            r.y = a[1] + bih1[j + 512] + bhh1[j + 512];
            r.z = a[2] + bih1[j + 1024] + bhh1[j + 1024];
            r.w = a[3] + bih1[j + 1536] + bhh1[j + 1536];
            *reinterpret_cast<float4*>(&g_embW1[(size_t)it * 4]) = r;
        }
    }
    {   // transpose: key fp32 -> interleaved [n][dq][t][4]; values fp16 -> [n][d][t]
        const int tx = tid & 31, ty = tid >> 5;
        for (int tileid = b; tileid < 2 * N_B * 64 * 4; tileid += NBLK) {
            int rem = tileid;
            const bool isval = (rem >= N_B * 64 * 4);
            if (isval) rem -= N_B * 64 * 4;
            const float* src = isval ? values : key;
            int n = rem / (64 * 4);
            int r2 = rem % (64 * 4);
            int t0 = (r2 / 4) * 32, d0 = (r2 % 4) * 32;
            __syncthreads();
#pragma unroll
            for (int r = 0; r < 32; r += 16) {
                int t = t0 + r + ty;
                cb[(r + ty) * 33 + tx] =
                    (t < T_T) ? src[((size_t)n * T_T + t) * KD + d0 + tx] : 0.0f;
            }
            __syncthreads();
            if (isval) {
#pragma unroll
                for (int r = 0; r < 32; r += 16)
                    g_valTh[((size_t)n * KD + d0 + r + ty) * TS + t0 + tx] =
                        __float2half(cb[tx * 33 + (r + ty)]);
            } else {
#pragma unroll
                for (int r = 0; r < 32; r += 16) {
                    const int d = d0 + r + ty;
                    g_keyT[(size_t)n * KD * TS + (size_t)(d >> 2) * (TS * 4)
                           + (size_t)(t0 + tx) * 4 + (d & 3)] = cb[tx * 33 + (r + ty)];
                }
            }
        }
        __syncthreads();
    }

    gridbar(bs);

    const int in_  = g_itemN[b];
    const int iqa  = g_itemQA[b];
    const int iqb  = g_itemQB[b];
    const int ilen = lens[in_];
    int off = 0, pn = 0;
    if (b < 64) {
        off = g_coff[b]; pn = g_coff[b + 1] - off;
        if (tid < pn) fbase_sm[tid] = ld_acq(&g_cflag[(off + tid) * 32]);
    }
    __syncthreads();

    // ======================= MAIN LOOP (flag-dataflow; no gridbar) =======================
    for (int step = 0; step < L_L; step++) {
        const int cur = step & 1, nxt = cur ^ 1;

        // wait for ctx(step-1) from the 64 owners
        if (step > 0) {
            if (tid < 64) {
                const unsigned tgt = ctxfb_sm[tid] + (unsigned)step;
                while ((int)(ld_acq(&g_ctxflag[tid * 32]) - tgt) < 0) {}
            }
            __syncthreads();
        }

        // ---- Phase A: gates1 = embW1 + W1c@ctx (K=128) + pre1a + pre1b; cell1 ----
        {
            const int ks = tid >> 6, jl = (tid >> 4) & 3, nqt = tid & 15;
            const int j = b * 4 + jl;
            const float4* __restrict__ x4 = reinterpret_cast<const float4*>(g_x1[cur]);

            // prefetch cell inputs so their L2 latency overlaps the GEMM
            float4 pa, pb, g0;
            int cj2 = 0, cn = 0;
            if (tid < 256) {
                const int jl2 = tid >> 6;
                cn = tid & 63;
                cj2 = b * 4 + jl2;
                const int tok = (step == 0) ? START_TOK : text[cn * L_L + step - 1];
                pa = __ldcg(reinterpret_cast<const float4*>(&g_pre1a[((size_t)cj2 * 64 + cn) * 4]));
                pb = __ldcg(reinterpret_cast<const float4*>(&g_pre1b[((size_t)cj2 * 64 + cn) * 4]));
                g0 = *reinterpret_cast<const float4*>(&g_embW1[((size_t)tok * 512 + cj2) * 4]);
            }

            unsigned long long acc[8];
#pragma unroll
            for (int i = 0; i < 8; i++) acc[i] = 0ull;
#pragma unroll
            for (int kc = 0; kc < 16; kc += 8) {
                float4 xv[8];
#pragma unroll
                for (int i = 0; i < 8; i++)
                    xv[i] = __ldcg(&x4[(ks * 16 + kc + i) * 16 + nqt]);
#pragma unroll
                for (int i = 0; i < 8; i++) {
                    const int k = ks * 16 + kc + i;
                    const float4 w4 = *reinterpret_cast<const float4*>(&g_W1c[((size_t)k * 512 + j) * 4]);
                    const unsigned long long xlo = packf2(xv[i].x, xv[i].y);
                    const unsigned long long xhi = packf2(xv[i].z, xv[i].w);
                    acc[0] = f2fma(packf2(w4.x, w4.x), xlo, acc[0]);
                    acc[1] = f2fma(packf2(w4.x, w4.x), xhi, acc[1]);
                    acc[2] = f2fma(packf2(w4.y, w4.y), xlo, acc[2]);
                    acc[3] = f2fma(packf2(w4.y, w4.y), xhi, acc[3]);
                    acc[4] = f2fma(packf2(w4.z, w4.z), xlo, acc[4]);
                    acc[5] = f2fma(packf2(w4.z, w4.z), xhi, acc[5]);
                    acc[6] = f2fma(packf2(w4.w, w4.w), xlo, acc[6]);
                    acc[7] = f2fma(packf2(w4.w, w4.w), xhi, acc[7]);
                }
            }
#pragma unroll
            for (int g = 0; g < 4; g++) {
                float2 lo = *reinterpret_cast<float2*>(&acc[g * 2]);
                float2 hi = *reinterpret_cast<float2*>(&acc[g * 2 + 1]);
                *reinterpret_cast<float4*>(&cb[((ks * 4 + jl) * 4 + g) * 64 + nqt * 4]) =
                    make_float4(lo.x, lo.y, hi.x, hi.y);
            }
            __syncthreads();
            if (tid < 256) {
                const int jl2 = tid >> 6;
                float gi = g0.x + pa.x + pb.x;
                float gf = g0.y + pa.y + pb.y;
                float gg = g0.z + pa.z + pb.z;
                float go = g0.w + pa.w + pb.w;
#pragma unroll
                for (int s = 0; s < 8; s++) {
                    gi += cb[((s * 4 + jl2) * 4 + 0) * 64 + cn];
                    gf += cb[((s * 4 + jl2) * 4 + 1) * 64 + cn];
                    gg += cb[((s * 4 + jl2) * 4 + 2) * 64 + cn];
                    go += cb[((s * 4 + jl2) * 4 + 3) * 64 + cn];
                }
                float c = g_c1[cj2 * 64 + cn];
                c = sigf(gf) * c + sigf(gi) * tanhf(gg);
                float h = sigf(go) * tanhf(c);
                g_c1[cj2 * 64 + cn] = c;
                __stcg(&g_h1[cj2 * 64 + cn], h);
                __stcg(&g_x2[cur][cj2 * 64 + cn], h);
            }
        }
        // publish h1 flag; decentralized wait
        __syncthreads();
        if (tid == 0) st_rel(&g_h1flag[b * 32], h1fb_sm[b] + (unsigned)(step + 1));
        if (tid < 128) {
            const unsigned tgt = h1fb_sm[tid] + (unsigned)(step + 1);
            while ((int)(ld_acq(&g_h1flag[tid * 32]) - tgt) < 0) {}
        }
        __syncthreads();

        // ---- Phase BC: gates2/pre1, then h2-flag-synced attention + merge + logits ----
        if (b < 32) {
            const int ks = tid >> 6, jl = (tid >> 4) & 3, nqt = tid & 15;
            const int j = b * 4 + jl;
            const float4* __restrict__ x4 = reinterpret_cast<const float4*>(g_x2[cur]);
            unsigned long long acc[8];
#pragma unroll
            for (int i = 0; i < 8; i++) acc[i] = 0ull;
            for (int kc = 0; kc < 80; kc += 8) {
                float4 xv[8];
#pragma unroll
                for (int i = 0; i < 8; i++)
                    xv[i] = __ldcg(&x4[(ks * 80 + kc + i) * 16 + nqt]);
#pragma unroll
                for (int i = 0; i < 8; i++) {
                    const int k = ks * 80 + kc + i;
                    const float4 w4 = *reinterpret_cast<const float4*>(&g_W2q[((size_t)k * 128 + j) * 4]);
                    const unsigned long long xlo = packf2(xv[i].x, xv[i].y);
                    const unsigned long long xhi = packf2(xv[i].z, xv[i].w);
                    acc[0] = f2fma(packf2(w4.x, w4.x), xlo, acc[0]);
                    acc[1] = f2fma(packf2(w4.x, w4.x), xhi, acc[1]);
                    acc[2] = f2fma(packf2(w4.y, w4.y), xlo, acc[2]);
                    acc[3] = f2fma(packf2(w4.y, w4.y), xhi, acc[3]);
                    acc[4] = f2fma(packf2(w4.z, w4.z), xlo, acc[4]);
                    acc[5] = f2fma(packf2(w4.z, w4.z), xhi, acc[5]);
                    acc[6] = f2fma(packf2(w4.w, w4.w), xlo, acc[6]);
                    acc[7] = f2fma(packf2(w4.w, w4.w), xhi, acc[7]);
                }
            }
#pragma unroll
            for (int g = 0; g < 4; g++) {
                float2 lo = *reinterpret_cast<float2*>(&acc[g * 2]);
                float2 hi = *reinterpret_cast<float2*>(&acc[g * 2 + 1]);
                *reinterpret_cast<float4*>(&cb[((ks * 4 + jl) * 4 + g) * 64 + nqt * 4]) =
                    make_float4(lo.x, lo.y, hi.x, hi.y);
            }
            __syncthreads();
            if (tid < 256) {
                const int jl2 = tid >> 6, n = tid & 63;
                const int j2 = b * 4 + jl2;
                const float4 bb = *reinterpret_cast<const float4*>(&g_b2[j2 * 4]);
                float gi = bb.x, gf = bb.y, gg = bb.z, go = bb.w;
#pragma unroll
                for (int s = 0; s < 8; s++) {
                    gi += cb[((s * 4 + jl2) * 4 + 0) * 64 + n];
                    gf += cb[((s * 4 + jl2) * 4 + 1) * 64 + n];
                    gg += cb[((s * 4 + jl2) * 4 + 2) * 64 + n];
                    go += cb[((s * 4 + jl2) * 4 + 3) * 64 + n];
                }
                float c = g_c2[j2 * 64 + n];
                c = sigf(gf) * c + sigf(gi) * tanhf(gg);
                float h = sigf(go) * tanhf(c);
                g_c2[j2 * 64 + n] = c;
                __stcg(&g_x2[nxt][(512 + j2) * 64 + n], h);
            }
            __syncthreads();
            if (tid == 0) st_rel(&g_h2flag[b * 32], h2fb_sm[b] + (unsigned)(step + 1));
        } else {
            const int ub = b - 32;
            int u0, ucnt;
            if (ub < 64) { u0 = ub * 3; ucnt = 3; }
            else         { u0 = 192 + (ub - 64) * 2; ucnt = 2; }
            const int ks = tid >> 6, jl = (tid >> 4) & 3, nqt = tid & 15;
            const float4* __restrict__ h14 = reinterpret_cast<const float4*>(g_h1);
            for (int uu = 0; uu < ucnt; uu++) {
                const int u = u0 + uu;
                const int j0 = (u >> 1) * 4;
                const int k0 = (u & 1) * 256;
                float* dst = (u & 1) ? g_pre1b : g_pre1a;
                const int j = j0 + jl;
                unsigned long long acc[8];
#pragma unroll
                for (int i = 0; i < 8; i++) acc[i] = 0ull;
                for (int kc = 0; kc < 32; kc += 8) {
                    float4 xv[8];
#pragma unroll
                    for (int i = 0; i < 8; i++)
                        xv[i] = __ldcg(&h14[(k0 + ks * 32 + kc + i) * 16 + nqt]);
#pragma unroll
                    for (int i = 0; i < 8; i++) {
                        const int k = k0 + ks * 32 + kc + i;
                        const float4 w4 = *reinterpret_cast<const float4*>(&g_W1h[((size_t)k * 512 + j) * 4]);
                        const unsigned long long xlo = packf2(xv[i].x, xv[i].y);
                        const unsigned long long xhi = packf2(xv[i].z, xv[i].w);
                        acc[0] = f2fma(packf2(w4.x, w4.x), xlo, acc[0]);
                        acc[1] = f2fma(packf2(w4.x, w4.x), xhi, acc[1]);
                        acc[2] = f2fma(packf2(w4.y, w4.y), xlo, acc[2]);
                        acc[3] = f2fma(packf2(w4.y, w4.y), xhi, acc[3]);
                        acc[4] = f2fma(packf2(w4.z, w4.z), xlo, acc[4]);
                        acc[5] = f2fma(packf2(w4.z, w4.z), xhi, acc[5]);
                        acc[6] = f2fma(packf2(w4.w, w4.w), xlo, acc[6]);
                        acc[7] = f2fma(packf2(w4.w, w4.w), xhi, acc[7]);
                    }
                }
#pragma unroll
                for (int g = 0; g < 4; g++) {
                    float2 lo = *reinterpret_cast<float2*>(&acc[g * 2]);
                    float2 hi = *reinterpret_cast<float2*>(&acc[g * 2 + 1]);
                    *reinterpret_cast<float4*>(&cb[((ks * 4 + jl) * 4 + g) * 64 + nqt * 4]) =
                        make_float4(lo.x, lo.y, hi.x, hi.y);
                }
                __syncthreads();
                if (tid < 256) {
                    const int jl2 = tid >> 6, n = tid & 63;
                    const int j2 = j0 + jl2;
                    float sv[4];
#pragma unroll
                    for (int g = 0; g < 4; g++) {
                        sv[g] = cb[((0 * 4 + jl2) * 4 + g) * 64 + n]
                              + cb[((1 * 4 + jl2) * 4 + g) * 64 + n]
                              + cb[((2 * 4 + jl2) * 4 + g) * 64 + n]
                              + cb[((3 * 4 + jl2) * 4 + g) * 64 + n]
                              + cb[((4 * 4 + jl2) * 4 + g) * 64 + n]
                              + cb[((5 * 4 + jl2) * 4 + g) * 64 + n]
                              + cb[((6 * 4 + jl2) * 4 + g) * 64 + n]
                              + cb[((7 * 4 + jl2) * 4 + g) * 64 + n];
                    }
                    __stcg(reinterpret_cast<float4*>(&dst[((size_t)j2 * 64 + n) * 4]),
                           make_float4(sv[0], sv[1], sv[2], sv[3]));
                }
                __syncthreads();
            }
        }

        // wait for all 32 h2 slices
        if (tid < 32) {
            const unsigned tgt = h2fb_sm[tid] + (unsigned)(step + 1);
            while ((int)(ld_acq(&g_h2flag[tid * 32]) - tgt) < 0) {}
        }
        __syncthreads();

        // ---- attention (balanced item) ----
        {
            const int n = in_;
            const int qa4 = iqa * 4, qb4 = iqb * 4;
            const int len = ilen;

            if (tid < 128) h2s[tid] = __ldcg(&g_x2[nxt][(512 + tid) * 64 + n]);
            __syncthreads();

            const float4* kTn4 = reinterpret_cast<const float4*>(g_keyT + (size_t)n * KD * TS);
            float lmax = -3e38f;
            for (int t = qa4 + tid; t < qb4; t += NTHR) {
                if (t < len) {
                    float a0 = 0.f, a1 = 0.f, a2 = 0.f, a3 = 0.f;
#pragma unroll
                    for (int dq = 0; dq < 32; dq += 16) {
                        float4 kv[16];
#pragma unroll
                        for (int i = 0; i < 16; i++) kv[i] = kTn4[(size_t)(dq + i) * TS + t];
#pragma unroll
                        for (int i = 0; i < 16; i++) {
                            a0 = fmaf(h2s[(dq + i) * 4 + 0], kv[i].x, a0);
                            a1 = fmaf(h2s[(dq + i) * 4 + 1], kv[i].y, a1);
                            a2 = fmaf(h2s[(dq + i) * 4 + 2], kv[i].z, a2);
                            a3 = fmaf(h2s[(dq + i) * 4 + 3], kv[i].w, a3);
                        }
                    }
                    const float acc = (a0 + a1) + (a2 + a3);
                    es[t - qa4] = acc;
                    lmax = fmaxf(lmax, acc);
                }
            }
#pragma unroll
            for (int s = 16; s > 0; s >>= 1) lmax = fmaxf(lmax, __shfl_xor_sync(0xffffffffu, lmax, s));
            if (lane == 0) red[wid] = lmax;
            __syncthreads();
            float mx = red[0];
#pragma unroll
            for (int i = 1; i < 16; i++) mx = fmaxf(mx, red[i]);

            float ps = 0.0f;
            for (int t = qa4 + tid; t < qb4; t += NTHR) {
                float w = 0.0f;
                if (t < len) w = __expf(es[t - qa4] - mx);
                es[t - qa4] = w;
                ps += w;
            }
#pragma unroll
            for (int s = 16; s > 0; s >>= 1) ps += __shfl_xor_sync(0xffffffffu, ps, s);
            __syncthreads();
            if (lane == 0) red[wid] = ps;
            __syncthreads();
            float tot = red[0];
#pragma unroll
            for (int i = 1; i < 16; i++) tot += red[i];
            if (tid == 0) { __stcg(&g_cm[b], mx); __stcg(&g_cs[b], tot); }

            // ctx partials from fp16 values: warp wid handles d = wid + 16r
            {
                const int nq = iqb - iqa;
                const __half* vTh = g_valTh + (size_t)n * KD * TS;
                const float4* es4 = reinterpret_cast<const float4*>(es);
                unsigned long long acc[8];
#pragma unroll
                for (int r = 0; r < 8; r++) acc[r] = 0ull;
#pragma unroll 2
                for (int q = lane; q < nq; q += 32) {
                    const float4 e = es4[q];
                    const unsigned long long elo = packf2(e.x, e.y);
                    const unsigned long long ehi = packf2(e.z, e.w);
#pragma unroll
                    for (int r = 0; r < 8; r++) {
                        const uint2 u = *reinterpret_cast<const uint2*>(
                            vTh + (size_t)(wid + 16 * r) * TS + (size_t)(iqa + q) * 4);
                        const float2 v01 = __half22float2(*reinterpret_cast<const __half2*>(&u.x));
                        const float2 v23 = __half22float2(*reinterpret_cast<const __half2*>(&u.y));
                        acc[r] = f2fma(packf2(v01.x, v01.y), elo, acc[r]);
                        acc[r] = f2fma(packf2(v23.x, v23.y), ehi, acc[r]);
                    }
                }
#pragma unroll
                for (int r = 0; r < 8; r++) {
                    float2 f = *reinterpret_cast<float2*>(&acc[r]);
                    float s = f.x + f.y;
#pragma unroll
                    for (int sh = 16; sh > 0; sh >>= 1) s += __shfl_xor_sync(0xffffffffu, s, sh);
                    if (lane == 0) __stcg(&g_cctx[(size_t)b * 128 + wid + 16 * r], s);
                }
            }
            __syncthreads();
            if (tid == 0) st_rel(&g_cflag[b * 32], fb_self + (unsigned)(step + 1));

            // owner merge + ctx publish + logits (blocks 0..63, sample b)
            if (b < 64) {
                if (tid >= 128 && tid < 256)
                    h2o[tid - 128] = __ldcg(&g_x2[nxt][(512 + tid - 128) * 64 + b]);
                if (tid < pn) {
                    const unsigned tgt = fbase_sm[tid] + (unsigned)(step + 1);
                    while ((int)(ld_acq(&g_cflag[(off + tid) * 32]) - tgt) < 0) {}
                }
                __syncthreads();
                if (tid < pn) {
                    sm_m[tid] = __ldcg(&g_cm[off + tid]);
                    sm_s[tid] = __ldcg(&g_cs[off + tid]);
                }
                __syncthreads();
                if (tid < 32) {
                    float M = -3e38f;
                    for (int i = tid; i < pn; i += 32) M = fmaxf(M, sm_m[i]);
#pragma unroll
                    for (int s = 16; s > 0; s >>= 1) M = fmaxf(M, __shfl_xor_sync(0xffffffffu, M, s));
                    float S = 0.0f;
                    for (int i = tid; i < pn; i += 32) {
                        float w = __expf(sm_m[i] - M);
                        sm_m[i] = w;
                        S += w * sm_s[i];
                    }
#pragma unroll
                    for (int s = 16; s > 0; s >>= 1) S += __shfl_xor_sync(0xffffffffu, S, s);
                    if (tid == 0) sred = 1.0f / S;
                }
                __syncthreads();
                if (tid < 128) {
                    float acc = 0.0f;
                    int i = 0;
                    for (; i + 8 <= pn; i += 8) {
                        float p[8];
#pragma unroll
                        for (int r = 0; r < 8; r++)
                            p[r] = __ldcg(&g_cctx[(size_t)(off + i + r) * 128 + tid]);
#pragma unroll
                        for (int r = 0; r < 8; r++) acc += sm_m[i + r] * p[r];
                    }
                    for (; i < pn; i++)
                        acc += sm_m[i] * __ldcg(&g_cctx[(size_t)(off + i) * 128 + tid]);
                    const float cx = acc * sred;
                    ctxs[tid] = cx;
                    __stcg(&g_x1[nxt][tid * 64 + b], cx);
                }
                __syncthreads();
                // publish ctx-ready BEFORE logits so other blocks enter A(step+1)
                if (tid == 0) st_rel(&g_ctxflag[b * 32], ctxfb_sm[b] + (unsigned)(step + 1));
                {
                    const float4 h0 = *reinterpret_cast<const float4*>(&h2o[lane * 4]);
                    const float4 c0 = *reinterpret_cast<const float4*>(&ctxs[lane * 4]);
                    for (int v = wid; v < V_V; v += 16) {
                        const float4* er = reinterpret_cast<const float4*>(emb + (size_t)v * E_E);
                        const float4 e0 = er[lane], e1 = er[lane + 32];
                        float d = e0.x * h0.x + e0.y * h0.y + e0.z * h0.z + e0.w * h0.w
                                + e1.x * c0.x + e1.y * c0.y + e1.z * c0.z + e1.w * c0.w;
#pragma unroll
                        for (int s = 16; s > 0; s >>= 1) d += __shfl_xor_sync(0xffffffffu, d, s);
                        if (lane == 0) out[((size_t)b * L_L + step) * V_V + v] = d + bout[v];
                    }
                }
            }
        }
    }
}

extern "C" void kernel_launch(void* const* d_in, const int* in_sizes, int n_in,
                              void* d_out, int out_size) {
    mega<<<NBLK, NTHR>>>(
        (const float*)d_in[0], (const float*)d_in[1], (const int*)d_in[2],
        (const int*)d_in[3], (const float*)d_in[4], (const float*)d_in[5],
        (const float*)d_in[6], (const float*)d_in[7], (const float*)d_in[8],
        (const float*)d_in[9], (const float*)d_in[10], (const float*)d_in[11],
        (const float*)d_in[12], (const float*)d_in[13], (float*)d_out);
}